// round 10
// baseline (speedup 1.0000x reference)
#include <cuda_runtime.h>
#include <cuda_bf16.h>
#include <cstdint>

#define NN   10000
#define EE   160000
#define RNAD 2000
#define PROTD 100
#define EMBD 128
#define HIDD 128
#define NH   4
#define DIN  256
#define DMID 512
#define BIGW 1536

#define KRNA  2016
#define KPROT 128
#define XPAD  (KRNA + KPROT)

// ---------------- scratch (static device globals) --------------------------
__device__ float          g_big[NN * BIGW];
__device__ float          g_gat[NN * DMID];
__device__ float          g_as [NN * NH];
__device__ float          g_ad [NN * NH];
__device__ int            g_src[EE];
__device__ int            g_dst[EE];
__device__ int            g_is64;
__device__ int            g_cnt[NN];
__device__ int            g_starts[NN + 1];
__device__ int            g_fill[NN];
__device__ int            g_eid[EE];
__device__ float          g_bias1[BIGW];
__device__ float          g_bias2[BIGW];
__device__ float          g_biasT[256];

__device__ __nv_bfloat16  g_xh [NN * XPAD];
__device__ __nv_bfloat16  g_xl [NN * XPAD];
__device__ __nv_bfloat16  g_xinh[NN * DIN];
__device__ __nv_bfloat16  g_xinl[NN * DIN];
__device__ __nv_bfloat16  g_hh [NN * DMID];
__device__ __nv_bfloat16  g_hl [NN * DMID];
__device__ __nv_bfloat16  g_embh[NN * EMBD];
__device__ __nv_bfloat16  g_embl[NN * EMBD];
__device__ __nv_bfloat16  g_th [NN * 256];
__device__ __nv_bfloat16  g_tl [NN * 256];

// weight arena (K-major, padded)
#define OFF_WRNA  0
#define OFF_WPROT 258048
#define OFF_C1WS  274432
#define OFF_C1WD  405504
#define OFF_L1W   536576
#define OFF_C2WS  667648
#define OFF_C2WD  929792
#define OFF_L2W   1191936
#define OFF_AGG   1454080
#define OFF_DR    1519616
#define OFF_DP    1536000
#define OFF_RR    1552384
#define OFF_RP    1808384
#define WARENA    1821184
__device__ __nv_bfloat16 g_wh[WARENA];
__device__ __nv_bfloat16 g_wl[WARENA];

// ---------------- helpers ---------------------------------------------------
__device__ __forceinline__ void bsplit(float v, __nv_bfloat16& h, __nv_bfloat16& l) {
    h = __float2bfloat16(v);
    l = __float2bfloat16(v - __bfloat162float(h));
}
__device__ __forceinline__ void cpa16(uint32_t dst, const void* src, int sz) {
    asm volatile("cp.async.ca.shared.global [%0], [%1], 16, %2;\n"
                 :: "r"(dst), "l"(src), "r"(sz));
}
__device__ __forceinline__ void mma_bf16(float* c, uint32_t a0, uint32_t a1,
                                         uint32_t a2, uint32_t a3,
                                         uint32_t b0, uint32_t b1) {
    asm volatile(
        "mma.sync.aligned.m16n8k16.row.col.f32.bf16.bf16.f32 "
        "{%0,%1,%2,%3}, {%4,%5,%6,%7}, {%8,%9}, {%0,%1,%2,%3};"
        : "+f"(c[0]), "+f"(c[1]), "+f"(c[2]), "+f"(c[3])
        : "r"(a0), "r"(a1), "r"(a2), "r"(a3), "r"(b0), "r"(b1));
}
#define LDMX4(r0, r1, r2, r3, addr) \
    asm volatile("ldmatrix.sync.aligned.m8n8.x4.shared.b16 {%0,%1,%2,%3}, [%4];" \
                 : "=r"(r0), "=r"(r1), "=r"(r2), "=r"(r3) : "r"(addr))

// ---------------- edge decode + hist (fused) --------------------------------
__global__ void detect_fmt(const unsigned* __restrict__ w) {
    if (threadIdx.x == 0 && blockIdx.x == 0) {
        unsigned acc = 0;
        for (int i = 1; i < 4096; i += 2) acc |= w[i];
        g_is64 = (acc == 0u) ? 1 : 0;
    }
}
__global__ void decode_hist(const void* __restrict__ ei,
                            int* __restrict__ src, int* __restrict__ dst,
                            int* __restrict__ cnt) {
    int i = blockIdx.x * blockDim.x + threadIdx.x;
    if (i >= 2 * EE) return;
    long long v;
    if (g_is64) v = ((const long long*)ei)[i];
    else        v = (long long)((const int*)ei)[i];
    int vi = (int)v;
    vi = vi < 0 ? 0 : (vi >= NN ? NN - 1 : vi);
    if (i < EE) src[i] = vi;
    else { dst[i - EE] = vi; atomicAdd(&cnt[vi], 1); }
}
__global__ void zero_u32(unsigned* p, int n) {
    int i = blockIdx.x * blockDim.x + threadIdx.x;
    int stride = gridDim.x * blockDim.x;
    for (; i < n; i += stride) p[i] = 0u;
}

// ---------------- CSR scan (shuffle-based) + fill ----------------------------
#define SCAN_CHUNK 10
__global__ void csr_scan(const int* __restrict__ cnt,
                         int* __restrict__ starts, int* __restrict__ fill) {
    __shared__ int wsum[32];
    int t = threadIdx.x;
    int lane = t & 31, w = t >> 5;
    int base = t * SCAN_CHUNK;
    int loc[SCAN_CHUNK];
    int s = 0;
    #pragma unroll
    for (int j = 0; j < SCAN_CHUNK; j++) {
        int idx = base + j;
        int v = (idx < NN) ? cnt[idx] : 0;
        loc[j] = s; s += v;
    }
    // inclusive warp scan of s
    int si = s;
    #pragma unroll
    for (int o = 1; o < 32; o <<= 1) {
        int v = __shfl_up_sync(0xffffffffu, si, o);
        if (lane >= o) si += v;
    }
    if (lane == 31) wsum[w] = si;
    __syncthreads();
    if (w == 0) {
        int v = wsum[lane];
        int vi = v;
        #pragma unroll
        for (int o = 1; o < 32; o <<= 1) {
            int u = __shfl_up_sync(0xffffffffu, vi, o);
            if (lane >= o) vi += u;
        }
        wsum[lane] = vi - v;    // exclusive warp offsets
    }
    __syncthreads();
    int off = wsum[w] + (si - s);   // exclusive offset for this thread
    #pragma unroll
    for (int j = 0; j < SCAN_CHUNK; j++) {
        int idx = base + j;
        if (idx < NN) {
            int st = off + loc[j];
            starts[idx] = st;
            fill[idx] = st;
        }
    }
    if (t == 1023) starts[NN] = off + s;
}
__global__ void csr_fill(const int* __restrict__ dst,
                         int* __restrict__ fill, int* __restrict__ eid) {
    int e = blockIdx.x * blockDim.x + threadIdx.x;
    if (e < EE) {
        int p = atomicAdd(&fill[dst[e]], 1);
        eid[p] = e;
    }
}

// ---------------- preprocessing ----------------------------------------------
__global__ void split_x(const float* __restrict__ x,
                        __nv_bfloat16* __restrict__ hi, __nv_bfloat16* __restrict__ lo) {
    int i = blockIdx.x * blockDim.x + threadIdx.x;
    if (i >= NN * XPAD) return;
    int r = i / XPAD, c = i % XPAD;
    float v = 0.f;
    if (c < RNAD)                            v = x[(size_t)r * (RNAD + PROTD) + c];
    else if (c >= KRNA && c < KRNA + PROTD)  v = x[(size_t)r * (RNAD + PROTD) + RNAD + (c - KRNA)];
    __nv_bfloat16 h, l; bsplit(v, h, l);
    hi[i] = h; lo[i] = l;
}

struct WP { const float* p[13]; };
__global__ void split_all(WP wp, __nv_bfloat16* __restrict__ hi,
                          __nv_bfloat16* __restrict__ lo) {
    constexpr int woff[13] = {OFF_WRNA, OFF_WPROT, OFF_C1WS, OFF_C1WD, OFF_L1W,
                              OFF_C2WS, OFF_C2WD, OFF_L2W, OFF_AGG, OFF_DR,
                              OFF_DP, OFF_RR, OFF_RP};
    constexpr int wK [13] = {RNAD, PROTD, DIN, DIN, DIN, DMID, DMID, DMID,
                             DMID, EMBD, EMBD, EMBD, EMBD};
    constexpr int wN [13] = {EMBD, EMBD, DMID, DMID, DMID, DMID, DMID, DMID,
                             EMBD, EMBD, EMBD, RNAD, PROTD};
    constexpr int wKp[13] = {KRNA, KPROT, DIN, DIN, DIN, DMID, DMID, DMID,
                             DMID, EMBD, EMBD, EMBD, EMBD};
    int i = blockIdx.x * blockDim.x + threadIdx.x;
    if (i >= WARENA) return;
    int s = 0;
    #pragma unroll
    for (int j = 1; j < 13; j++) if (i >= woff[j]) s = j;
    int local = i - woff[s];
    int Kp = wKp[s];
    int n = local / Kp, k = local % Kp;
    float v = (k < wK[s]) ? wp.p[s][(size_t)k * wN[s] + n] : 0.f;
    __nv_bfloat16 h, l; bsplit(v, h, l);
    hi[i] = h; lo[i] = l;
}

__global__ void bias3(const float* __restrict__ lb, float* __restrict__ o) {
    int i = blockIdx.x * blockDim.x + threadIdx.x;
    if (i < BIGW) o[i] = (i < 1024) ? 0.f : lb[i - 1024];
}
__global__ void bias2(const float* __restrict__ a, const float* __restrict__ b,
                      float* __restrict__ o) {
    int i = threadIdx.x;
    if (i < 256) o[i] = (i < 128) ? a[i] : b[i - 128];
}

// ============================================================================
// bf16 tensor-core GEMM, pre-split operands, ldmatrix fragment loads (R8 form).
// ============================================================================
template<int BM>
__global__ void __launch_bounds__(256, 2)
bf16_gemm(const __nv_bfloat16* __restrict__ Ah, const __nv_bfloat16* __restrict__ Al, int lda,
          const __nv_bfloat16* __restrict__ Bh, const __nv_bfloat16* __restrict__ Bl, int ldb,
          float* __restrict__ C, int ldc,
          __nv_bfloat16* __restrict__ Chi, __nv_bfloat16* __restrict__ Clo, int ldch,
          const float* __restrict__ bias,
          int M, int N, int Kp, int relu) {
    constexpr int NI  = BM / 32;
    constexpr int AT  = BM * 40;
    constexpr int BT  = 128 * 40;
    constexpr int STG = 2 * AT + 2 * BT;
    extern __shared__ uint16_t sm[];

    const int tid   = threadIdx.x;
    const int lane  = tid & 31;
    const int warp  = tid >> 5;
    const int wr    = warp >> 2;
    const int wc    = warp & 3;
    const int group = lane >> 2;
    const int tig   = lane & 3;
    const int blockRow = blockIdx.y * BM;
    const int blockCol = blockIdx.x * 128;
    const int NC = Kp >> 5;

    const uint32_t smb = (uint32_t)__cvta_generic_to_shared(sm);
    const int aRow = lane & 15,  aCol = (lane >> 4) << 3;
    const int bRow = ((lane >> 4) << 3) + (lane & 7), bCol = ((lane >> 3) & 1) << 3;

    auto loadStage = [&](int c, int s) {
        uint16_t* base = sm + s * STG;
        int k0 = c << 5;
        for (int i = tid; i < BM * 4; i += 256) {
            int r = i >> 2, ch = i & 3;
            int gr = blockRow + r;
            int sz = (gr < M) ? 16 : 0;
            const __nv_bfloat16* ph = sz ? (Ah + (size_t)gr * lda + k0 + ch * 8) : Ah;
            const __nv_bfloat16* pl = sz ? (Al + (size_t)gr * lda + k0 + ch * 8) : Al;
            cpa16((uint32_t)__cvta_generic_to_shared(base + r * 40 + ch * 8), ph, sz);
            cpa16((uint32_t)__cvta_generic_to_shared(base + AT + r * 40 + ch * 8), pl, sz);
        }
        uint16_t* bb = base + 2 * AT;
        for (int i = tid; i < 128 * 4; i += 256) {
            int r = i >> 2, ch = i & 3;
            int gn = blockCol + r;
            int sz = (gn < N) ? 16 : 0;
            const __nv_bfloat16* ph = sz ? (Bh + (size_t)gn * ldb + k0 + ch * 8) : Bh;
            const __nv_bfloat16* pl = sz ? (Bl + (size_t)gn * ldb + k0 + ch * 8) : Bl;
            cpa16((uint32_t)__cvta_generic_to_shared(bb + r * 40 + ch * 8), ph, sz);
            cpa16((uint32_t)__cvta_generic_to_shared(bb + BT + r * 40 + ch * 8), pl, sz);
        }
        asm volatile("cp.async.commit_group;\n");
    };

    float acc[NI][4][4];
    #pragma unroll
    for (int i = 0; i < NI; i++)
        #pragma unroll
        for (int j = 0; j < 4; j++) {
            acc[i][j][0] = 0.f; acc[i][j][1] = 0.f;
            acc[i][j][2] = 0.f; acc[i][j][3] = 0.f;
        }

    loadStage(0, 0);

    for (int c = 0; c < NC; c++) {
        if (c + 1 < NC) {
            loadStage(c + 1, (c + 1) & 1);
            asm volatile("cp.async.wait_group 1;\n" ::: "memory");
        } else {
            asm volatile("cp.async.wait_group 0;\n" ::: "memory");
        }
        __syncthreads();

        const uint32_t stB = smb + (uint32_t)((c & 1) * STG) * 2;
        const uint32_t uAh = stB;
        const uint32_t uAl = stB + AT * 2;
        const uint32_t uBh = stB + 2 * AT * 2;
        const uint32_t uBl = stB + (2 * AT + BT) * 2;

        #pragma unroll
        for (int ks = 0; ks < 2; ks++) {
            const int kb = ks * 16;
            uint32_t bh[4][2], bl[4][2];
            #pragma unroll
            for (int p = 0; p < 2; p++) {
                int n = wc * 32 + p * 16 + bRow;
                uint32_t off = (uint32_t)(n * 40 + kb + bCol) * 2;
                LDMX4(bh[2*p][0], bh[2*p][1], bh[2*p+1][0], bh[2*p+1][1], uBh + off);
                LDMX4(bl[2*p][0], bl[2*p][1], bl[2*p+1][0], bl[2*p+1][1], uBl + off);
            }
            #pragma unroll
            for (int i = 0; i < NI; i++) {
                int r = wr * (BM / 2) + i * 16 + aRow;
                uint32_t off = (uint32_t)(r * 40 + kb + aCol) * 2;
                uint32_t ah0, ah1, ah2, ah3, al0, al1, al2, al3;
                LDMX4(ah0, ah1, ah2, ah3, uAh + off);
                LDMX4(al0, al1, al2, al3, uAl + off);
                #pragma unroll
                for (int j = 0; j < 4; j++) {
                    mma_bf16(acc[i][j], ah0, ah1, ah2, ah3, bh[j][0], bh[j][1]);
                    mma_bf16(acc[i][j], al0, al1, al2, al3, bh[j][0], bh[j][1]);
                    mma_bf16(acc[i][j], ah0, ah1, ah2, ah3, bl[j][0], bl[j][1]);
                }
            }
        }
        __syncthreads();
    }

    #pragma unroll
    for (int i = 0; i < NI; i++) {
        int r0 = blockRow + wr * (BM / 2) + i * 16 + group;
        int r1 = r0 + 8;
        #pragma unroll
        for (int j = 0; j < 4; j++) {
            int gc = blockCol + wc * 32 + j * 8 + tig * 2;
            if (gc >= N) continue;
            float bi0 = bias ? bias[gc] : 0.f;
            float bi1 = bias ? bias[gc + 1] : 0.f;
            float v0 = acc[i][j][0] + bi0, v1 = acc[i][j][1] + bi1;
            float v2 = acc[i][j][2] + bi0, v3 = acc[i][j][3] + bi1;
            if (relu) {
                v0 = fmaxf(v0, 0.f); v1 = fmaxf(v1, 0.f);
                v2 = fmaxf(v2, 0.f); v3 = fmaxf(v3, 0.f);
            }
            if (r0 < M) {
                if (C) *(float2*)(C + (size_t)r0 * ldc + gc) = make_float2(v0, v1);
                if (Chi) {
                    __nv_bfloat16 h0, l0, h1, l1;
                    bsplit(v0, h0, l0); bsplit(v1, h1, l1);
                    Chi[(size_t)r0 * ldch + gc] = h0; Chi[(size_t)r0 * ldch + gc + 1] = h1;
                    Clo[(size_t)r0 * ldch + gc] = l0; Clo[(size_t)r0 * ldch + gc + 1] = l1;
                }
            }
            if (r1 < M) {
                if (C) *(float2*)(C + (size_t)r1 * ldc + gc) = make_float2(v2, v3);
                if (Chi) {
                    __nv_bfloat16 h2, l2, h3, l3;
                    bsplit(v2, h2, l2); bsplit(v3, h3, l3);
                    Chi[(size_t)r1 * ldch + gc] = h2; Chi[(size_t)r1 * ldch + gc + 1] = h3;
                    Clo[(size_t)r1 * ldch + gc] = l2; Clo[(size_t)r1 * ldch + gc + 1] = l3;
                }
            }
        }
    }
}

// ---------------- GAT: attention scores (strided xs/xd) --------------------
__global__ void att_scores(const float* __restrict__ xs, const float* __restrict__ xd,
                           int S,
                           const float* __restrict__ att_s, const float* __restrict__ att_d,
                           float* __restrict__ a_s, float* __restrict__ a_d) {
    int n = blockIdx.x;
    int w = threadIdx.x >> 5;
    int lane = threadIdx.x & 31;
    size_t base = (size_t)n * S + w * HIDD;
    float s = 0.f, d = 0.f;
    #pragma unroll
    for (int c = lane; c < HIDD; c += 32) {
        s += xs[base + c] * att_s[w * HIDD + c];
        d += xd[base + c] * att_d[w * HIDD + c];
    }
    #pragma unroll
    for (int o = 16; o > 0; o >>= 1) {
        s += __shfl_down_sync(0xffffffffu, s, o);
        d += __shfl_down_sync(0xffffffffu, d, o);
    }
    if (lane == 0) { a_s[n * NH + w] = s; a_d[n * NH + w] = d; }
}

// ---------------- GAT aggregation (gather, recompute alpha, 2x unroll) ------
__global__ void __launch_bounds__(128)
gat_aggregate(const int* __restrict__ starts, const int* __restrict__ eid,
              const int* __restrict__ src,
              const float* __restrict__ a_s, const float* __restrict__ a_d,
              const float* __restrict__ xs, int S,
              float* __restrict__ gat) {
    int n = blockIdx.x;
    int h = threadIdx.x >> 5;
    int lane = threadIdx.x & 31;
    int beg = starts[n], end = starts[n + 1];

    float adn = a_d[n * NH + h];

    float mx = -3.4e38f;
    for (int i = beg + lane; i < end; i += 32) {
        float a = a_s[src[eid[i]] * NH + h] + adn;
        a = a > 0.f ? a : 0.2f * a;
        mx = fmaxf(mx, a);
    }
    #pragma unroll
    for (int o = 16; o > 0; o >>= 1)
        mx = fmaxf(mx, __shfl_xor_sync(0xffffffffu, mx, o));

    float den = 0.f;
    float4 acc = make_float4(0.f, 0.f, 0.f, 0.f);
    const int chOff = h * HIDD + lane * 4;
    int i = beg;
    for (; i + 1 < end; i += 2) {
        int s0 = src[eid[i]], s1 = src[eid[i + 1]];
        float a0 = a_s[s0 * NH + h] + adn; a0 = a0 > 0.f ? a0 : 0.2f * a0;
        float a1 = a_s[s1 * NH + h] + adn; a1 = a1 > 0.f ? a1 : 0.2f * a1;
        float w0 = expf(a0 - mx), w1 = expf(a1 - mx);
        const float4 v0 = *(const float4*)(xs + (size_t)s0 * S + chOff);
        const float4 v1 = *(const float4*)(xs + (size_t)s1 * S + chOff);
        den += w0 + w1;
        acc.x += v0.x * w0 + v1.x * w1;
        acc.y += v0.y * w0 + v1.y * w1;
        acc.z += v0.z * w0 + v1.z * w1;
        acc.w += v0.w * w0 + v1.w * w1;
    }
    if (i < end) {
        int s0 = src[eid[i]];
        float a0 = a_s[s0 * NH + h] + adn; a0 = a0 > 0.f ? a0 : 0.2f * a0;
        float w0 = expf(a0 - mx);
        const float4 v0 = *(const float4*)(xs + (size_t)s0 * S + chOff);
        den += w0;
        acc.x += v0.x * w0; acc.y += v0.y * w0;
        acc.z += v0.z * w0; acc.w += v0.w * w0;
    }
    float inv = 1.f / (den + 1e-16f);
    acc.x *= inv; acc.y *= inv; acc.z *= inv; acc.w *= inv;
    *(float4*)(gat + (size_t)n * DMID + chOff) = acc;
}

// ---------------- residual (+bias) + LayerNorm + ReLU -> bf16 hi/lo --------
__global__ void resid_ln_relu(const float* __restrict__ gat, const float* __restrict__ cb,
                              const float* __restrict__ lin, int linS,
                              const float* __restrict__ g, const float* __restrict__ b,
                              __nv_bfloat16* __restrict__ hh, __nv_bfloat16* __restrict__ hl) {
    int row = blockIdx.x;
    int t = threadIdx.x;
    size_t gb = (size_t)row * DMID;
    size_t lb = (size_t)row * linS;
    float v0 = gat[gb + t]       + cb[t]       + lin[lb + t];
    float v1 = gat[gb + 256 + t] + cb[256 + t] + lin[lb + 256 + t];
    float s = v0 + v1;
    float ss = v0 * v0 + v1 * v1;
    #pragma unroll
    for (int o = 16; o > 0; o >>= 1) {
        s  += __shfl_down_sync(0xffffffffu, s, o);
        ss += __shfl_down_sync(0xffffffffu, ss, o);
    }
    __shared__ float shs[8], shss[8];
    __shared__ float mu_sh, inv_sh;
    int w = t >> 5, lane = t & 31;
    if (lane == 0) { shs[w] = s; shss[w] = ss; }
    __syncthreads();
    if (t == 0) {
        float S = 0.f, SS = 0.f;
        #pragma unroll
        for (int i = 0; i < 8; i++) { S += shs[i]; SS += shss[i]; }
        float mu = S * (1.f / DMID);
        float var = SS * (1.f / DMID) - mu * mu;
        mu_sh = mu;
        inv_sh = rsqrtf(var + 1e-5f);
    }
    __syncthreads();
    float mu = mu_sh, inv = inv_sh;
    float o0 = fmaxf((v0 - mu) * inv * g[t]       + b[t],       0.f);
    float o1 = fmaxf((v1 - mu) * inv * g[256 + t] + b[256 + t], 0.f);
    __nv_bfloat16 h0, l0, h1, l1;
    bsplit(o0, h0, l0); bsplit(o1, h1, l1);
    hh[gb + t] = h0;       hl[gb + t] = l0;
    hh[gb + 256 + t] = h1; hl[gb + 256 + t] = l1;
}

__global__ void resid_add(const float* __restrict__ gat, const float* __restrict__ cb,
                          const float* __restrict__ lin, int linS,
                          __nv_bfloat16* __restrict__ hh, __nv_bfloat16* __restrict__ hl) {
    int i = blockIdx.x * blockDim.x + threadIdx.x;
    int stride = gridDim.x * blockDim.x;
    for (; i < NN * DMID; i += stride) {
        int row = i >> 9, col = i & (DMID - 1);
        float v = gat[i] + cb[col] + lin[(size_t)row * linS + col];
        __nv_bfloat16 h, l; bsplit(v, h, l);
        hh[i] = h; hl[i] = l;
    }
}

// ---------------- host -------------------------------------------------------
static void gemm128(const __nv_bfloat16* Ah, const __nv_bfloat16* Al, int lda,
                    const __nv_bfloat16* Bh, const __nv_bfloat16* Bl, int ldb,
                    float* C, int ldc, __nv_bfloat16* Chi, __nv_bfloat16* Clo, int ldch,
                    const float* bias, int M, int N, int Kp, int relu) {
    constexpr int SM_BYTES = (2 * 128 * 40 + 2 * 128 * 40) * 2 * 2;
    cudaFuncSetAttribute(bf16_gemm<128>,
                         cudaFuncAttributeMaxDynamicSharedMemorySize, SM_BYTES);
    dim3 grid((N + 127) / 128, (M + 127) / 128);
    bf16_gemm<128><<<grid, 256, SM_BYTES>>>(Ah, Al, lda, Bh, Bl, ldb, C, ldc,
        Chi, Clo, ldch, bias, M, N, Kp, relu);
}
static void gemm64(const __nv_bfloat16* Ah, const __nv_bfloat16* Al, int lda,
                   const __nv_bfloat16* Bh, const __nv_bfloat16* Bl, int ldb,
                   float* C, int ldc, __nv_bfloat16* Chi, __nv_bfloat16* Clo, int ldch,
                   const float* bias, int M, int N, int Kp, int relu) {
    constexpr int SM_BYTES = (2 * 64 * 40 + 2 * 128 * 40) * 2 * 2;
    cudaFuncSetAttribute(bf16_gemm<64>,
                         cudaFuncAttributeMaxDynamicSharedMemorySize, SM_BYTES);
    dim3 grid((N + 127) / 128, (M + 63) / 64);
    bf16_gemm<64><<<grid, 256, SM_BYTES>>>(Ah, Al, lda, Bh, Bl, ldb, C, ldc,
        Chi, Clo, ldch, bias, M, N, Kp, relu);
}

extern "C" void kernel_launch(void* const* d_in, const int* in_sizes, int n_in,
                              void* d_out, int out_size) {
    const float* x      = (const float*)d_in[0];
    const void*  ei     = d_in[1];
    const float* W_rna  = (const float*)d_in[2];
    const float* b_rna  = (const float*)d_in[3];
    const float* W_prot = (const float*)d_in[4];
    const float* b_prot = (const float*)d_in[5];
    const float* c1_Ws  = (const float*)d_in[6];
    const float* c1_Wd  = (const float*)d_in[7];
    const float* c1_as  = (const float*)d_in[8];
    const float* c1_ad  = (const float*)d_in[9];
    const float* c1_b   = (const float*)d_in[10];
    const float* l1_W   = (const float*)d_in[11];
    const float* l1_b   = (const float*)d_in[12];
    const float* ln_g   = (const float*)d_in[13];
    const float* ln_b   = (const float*)d_in[14];
    const float* c2_Ws  = (const float*)d_in[15];
    const float* c2_Wd  = (const float*)d_in[16];
    const float* c2_as  = (const float*)d_in[17];
    const float* c2_ad  = (const float*)d_in[18];
    const float* c2_b   = (const float*)d_in[19];
    const float* l2_W   = (const float*)d_in[20];
    const float* l2_b   = (const float*)d_in[21];
    const float* agg_W  = (const float*)d_in[22];
    const float* agg_b  = (const float*)d_in[23];
    const float* dr_W   = (const float*)d_in[24];
    const float* dr_b   = (const float*)d_in[25];
    const float* dp_W   = (const float*)d_in[26];
    const float* dp_b   = (const float*)d_in[27];
    const float* rr_W   = (const float*)d_in[28];
    const float* rr_b   = (const float*)d_in[29];
    const float* rp_W   = (const float*)d_in[30];
    const float* rp_b   = (const float*)d_in[31];

    float* out = (float*)d_out;
    float* out_rna  = out;
    float* out_prot = out + (size_t)NN * RNAD;
    float* out_emb  = out + (size_t)NN * (RNAD + PROTD);

    float *big, *gat, *as_, *ad_, *bias1, *bias2b, *biasT;
    int *srcI, *dstI, *cnt, *starts, *fill, *eid;
    __nv_bfloat16 *xh, *xl, *xinh, *xinl, *hh, *hl, *embh, *embl, *th, *tl, *wh, *wl;
    cudaGetSymbolAddress((void**)&big,   g_big);
    cudaGetSymbolAddress((void**)&gat,   g_gat);
    cudaGetSymbolAddress((void**)&as_,   g_as);
    cudaGetSymbolAddress((void**)&ad_,   g_ad);
    cudaGetSymbolAddress((void**)&srcI,  g_src);
    cudaGetSymbolAddress((void**)&dstI,  g_dst);
    cudaGetSymbolAddress((void**)&cnt,   g_cnt);
    cudaGetSymbolAddress((void**)&starts,g_starts);
    cudaGetSymbolAddress((void**)&fill,  g_fill);
    cudaGetSymbolAddress((void**)&eid,   g_eid);
    cudaGetSymbolAddress((void**)&bias1, g_bias1);
    cudaGetSymbolAddress((void**)&bias2b,g_bias2);
    cudaGetSymbolAddress((void**)&biasT, g_biasT);
    cudaGetSymbolAddress((void**)&xh,    g_xh);
    cudaGetSymbolAddress((void**)&xl,    g_xl);
    cudaGetSymbolAddress((void**)&xinh,  g_xinh);
    cudaGetSymbolAddress((void**)&xinl,  g_xinl);
    cudaGetSymbolAddress((void**)&hh,    g_hh);
    cudaGetSymbolAddress((void**)&hl,    g_hl);
    cudaGetSymbolAddress((void**)&embh,  g_embh);
    cudaGetSymbolAddress((void**)&embl,  g_embl);
    cudaGetSymbolAddress((void**)&th,    g_th);
    cudaGetSymbolAddress((void**)&tl,    g_tl);
    cudaGetSymbolAddress((void**)&wh,    g_wh);
    cudaGetSymbolAddress((void**)&wl,    g_wl);

    const int EB = 256;

    // ---- decode edges (+hist) + CSR -----------------------------------------
    detect_fmt<<<1, 32>>>((const unsigned*)ei);
    zero_u32<<<40, 256>>>((unsigned*)cnt, NN);
    decode_hist<<<(2 * EE + EB - 1) / EB, EB>>>(ei, srcI, dstI, cnt);
    csr_scan<<<1, 1024>>>(cnt, starts, fill);
    csr_fill<<<(EE + EB - 1) / EB, EB>>>(dstI, fill, eid);

    // ---- preprocessing --------------------------------------------------------
    split_x<<<(NN * XPAD + 255) / 256, 256>>>(x, xh, xl);
    WP wp;
    wp.p[0] = W_rna;  wp.p[1] = W_prot; wp.p[2] = c1_Ws; wp.p[3] = c1_Wd;
    wp.p[4] = l1_W;   wp.p[5] = c2_Ws;  wp.p[6] = c2_Wd; wp.p[7] = l2_W;
    wp.p[8] = agg_W;  wp.p[9] = dr_W;   wp.p[10] = dp_W; wp.p[11] = rr_W;
    wp.p[12] = rp_W;
    split_all<<<(WARENA + 255) / 256, 256>>>(wp, wh, wl);
    bias3<<<6, 256>>>(l1_b, bias1);
    bias3<<<6, 256>>>(l2_b, bias2b);
    bias2<<<1, 256>>>(dr_b, dp_b, biasT);

    // ---- input embeddings -> xin hi/lo ----------------------------------------
    gemm64(xh, xl, XPAD, wh + OFF_WRNA, wl + OFF_WRNA, KRNA,
           nullptr, 0, xinh, xinl, DIN, b_rna, NN, EMBD, KRNA, 0);
    gemm64(xh + KRNA, xl + KRNA, XPAD, wh + OFF_WPROT, wl + OFF_WPROT, KPROT,
           nullptr, 0, xinh + EMBD, xinl + EMBD, DIN, b_prot, NN, EMBD, KPROT, 0);

    // ================= Block 1: fused xs|xd|lin ============================
    gemm128(xinh, xinl, DIN, wh + OFF_C1WS, wl + OFF_C1WS, DIN,
            big, BIGW, nullptr, nullptr, 0, bias1, NN, BIGW, DIN, 0);
    att_scores<<<NN, 128>>>(big, big + 512, BIGW, c1_as, c1_ad, as_, ad_);
    gat_aggregate<<<NN, 128>>>(starts, eid, srcI, as_, ad_, big, BIGW, gat);
    resid_ln_relu<<<NN, 256>>>(gat, c1_b, big + 1024, BIGW, ln_g, ln_b, hh, hl);

    // ================= Block 2: fused xs|xd|lin ============================
    gemm128(hh, hl, DMID, wh + OFF_C2WS, wl + OFF_C2WS, DMID,
            big, BIGW, nullptr, nullptr, 0, bias2b, NN, BIGW, DMID, 0);
    att_scores<<<NN, 128>>>(big, big + 512, BIGW, c2_as, c2_ad, as_, ad_);
    gat_aggregate<<<NN, 128>>>(starts, eid, srcI, as_, ad_, big, BIGW, gat);
    resid_add<<<512, 256>>>(gat, c2_b, big + 1024, BIGW, hh, hl);

    // ================= Heads ===============================================
    gemm64(hh, hl, DMID, wh + OFF_AGG, wl + OFF_AGG, DMID,
           out_emb, EMBD, embh, embl, EMBD, agg_b, NN, EMBD, DMID, 1);

    gemm64(embh, embl, EMBD, wh + OFF_DR, wl + OFF_DR, EMBD,
           nullptr, 0, th, tl, 256, biasT, NN, 256, EMBD, 0);

    gemm128(th, tl, 256, wh + OFF_RR, wl + OFF_RR, EMBD,
            out_rna, RNAD, nullptr, nullptr, 0, rr_b, NN, RNAD, EMBD, 0);
    gemm64(th + 128, tl + 128, 256, wh + OFF_RP, wl + OFF_RP, EMBD,
           out_prot, PROTD, nullptr, nullptr, 0, rp_b, NN, PROTD, EMBD, 0);
}

// round 11
// speedup vs baseline: 1.0619x; 1.0619x over previous
#include <cuda_runtime.h>
#include <cuda_bf16.h>
#include <cstdint>

#define NN   10000
#define EE   160000
#define RNAD 2000
#define PROTD 100
#define EMBD 128
#define HIDD 128
#define NH   4
#define DIN  256
#define DMID 512
#define BIGW 1536

#define KRNA  2016
#define KPROT 128
#define XPAD  (KRNA + KPROT)

// ---------------- scratch (static device globals) --------------------------
__device__ float          g_big[NN * BIGW];
__device__ float          g_gat[NN * DMID];
__device__ float          g_as [NN * NH];
__device__ float          g_ad [NN * NH];
__device__ float          g_alpha[EE * NH];
__device__ int            g_src[EE];
__device__ int            g_dst[EE];
__device__ int            g_is64;
__device__ int            g_cnt[NN];
__device__ int            g_starts[NN + 1];
__device__ int            g_fill[NN];
__device__ int            g_eid[EE];
__device__ float          g_bias1[BIGW];
__device__ float          g_bias2[BIGW];
__device__ float          g_biasT[256];

__device__ __nv_bfloat16  g_xh [NN * XPAD];
__device__ __nv_bfloat16  g_xl [NN * XPAD];
__device__ __nv_bfloat16  g_xinh[NN * DIN];
__device__ __nv_bfloat16  g_xinl[NN * DIN];
__device__ __nv_bfloat16  g_hh [NN * DMID];
__device__ __nv_bfloat16  g_hl [NN * DMID];
__device__ __nv_bfloat16  g_embh[NN * EMBD];
__device__ __nv_bfloat16  g_embl[NN * EMBD];
__device__ __nv_bfloat16  g_th [NN * 256];
__device__ __nv_bfloat16  g_tl [NN * 256];

// weight arena (K-major, padded)
#define OFF_WRNA  0
#define OFF_WPROT 258048
#define OFF_C1WS  274432
#define OFF_C1WD  405504
#define OFF_L1W   536576
#define OFF_C2WS  667648
#define OFF_C2WD  929792
#define OFF_L2W   1191936
#define OFF_AGG   1454080
#define OFF_DR    1519616
#define OFF_DP    1536000
#define OFF_RR    1552384
#define OFF_RP    1808384
#define WARENA    1821184
__device__ __nv_bfloat16 g_wh[WARENA];
__device__ __nv_bfloat16 g_wl[WARENA];

// ---------------- helpers ---------------------------------------------------
__device__ __forceinline__ void bsplit(float v, __nv_bfloat16& h, __nv_bfloat16& l) {
    h = __float2bfloat16(v);
    l = __float2bfloat16(v - __bfloat162float(h));
}
__device__ __forceinline__ void cpa16(uint32_t dst, const void* src, int sz) {
    asm volatile("cp.async.ca.shared.global [%0], [%1], 16, %2;\n"
                 :: "r"(dst), "l"(src), "r"(sz));
}
__device__ __forceinline__ void mma_bf16(float* c, uint32_t a0, uint32_t a1,
                                         uint32_t a2, uint32_t a3,
                                         uint32_t b0, uint32_t b1) {
    asm volatile(
        "mma.sync.aligned.m16n8k16.row.col.f32.bf16.bf16.f32 "
        "{%0,%1,%2,%3}, {%4,%5,%6,%7}, {%8,%9}, {%0,%1,%2,%3};"
        : "+f"(c[0]), "+f"(c[1]), "+f"(c[2]), "+f"(c[3])
        : "r"(a0), "r"(a1), "r"(a2), "r"(a3), "r"(b0), "r"(b1));
}
#define LDMX4(r0, r1, r2, r3, addr) \
    asm volatile("ldmatrix.sync.aligned.m8n8.x4.shared.b16 {%0,%1,%2,%3}, [%4];" \
                 : "=r"(r0), "=r"(r1), "=r"(r2), "=r"(r3) : "r"(addr))

// ---------------- edge-index dtype detect + decode -------------------------
__global__ void detect_fmt(const unsigned* __restrict__ w) {
    if (threadIdx.x == 0 && blockIdx.x == 0) {
        unsigned acc = 0;
        for (int i = 1; i < 4096; i += 2) acc |= w[i];
        g_is64 = (acc == 0u) ? 1 : 0;
    }
}
__global__ void decode_idx(const void* __restrict__ ei,
                           int* __restrict__ src, int* __restrict__ dst) {
    int i = blockIdx.x * blockDim.x + threadIdx.x;
    if (i >= 2 * EE) return;
    long long v;
    if (g_is64) v = ((const long long*)ei)[i];
    else        v = (long long)((const int*)ei)[i];
    int vi = (int)v;
    vi = vi < 0 ? 0 : (vi >= NN ? NN - 1 : vi);
    if (i < EE) src[i] = vi;
    else        dst[i - EE] = vi;
}
__global__ void zero_u32(unsigned* p, int n) {
    int i = blockIdx.x * blockDim.x + threadIdx.x;
    int stride = gridDim.x * blockDim.x;
    for (; i < n; i += stride) p[i] = 0u;
}

// ---------------- CSR build --------------------------------------------------
__global__ void csr_hist(const int* __restrict__ dst, int* __restrict__ cnt) {
    int e = blockIdx.x * blockDim.x + threadIdx.x;
    if (e < EE) atomicAdd(&cnt[dst[e]], 1);
}
// shuffle-based two-level scan: 2 barriers instead of 20
#define SCAN_CHUNK 10
__global__ void csr_scan(const int* __restrict__ cnt,
                         int* __restrict__ starts, int* __restrict__ fill) {
    __shared__ int wsum[32];
    int t = threadIdx.x;
    int lane = t & 31, w = t >> 5;
    int base = t * SCAN_CHUNK;
    int loc[SCAN_CHUNK];
    int s = 0;
    #pragma unroll
    for (int j = 0; j < SCAN_CHUNK; j++) {
        int idx = base + j;
        int v = (idx < NN) ? cnt[idx] : 0;
        loc[j] = s; s += v;
    }
    int si = s;
    #pragma unroll
    for (int o = 1; o < 32; o <<= 1) {
        int v = __shfl_up_sync(0xffffffffu, si, o);
        if (lane >= o) si += v;
    }
    if (lane == 31) wsum[w] = si;
    __syncthreads();
    if (w == 0) {
        int v = wsum[lane];
        int vi = v;
        #pragma unroll
        for (int o = 1; o < 32; o <<= 1) {
            int u = __shfl_up_sync(0xffffffffu, vi, o);
            if (lane >= o) vi += u;
        }
        wsum[lane] = vi - v;
    }
    __syncthreads();
    int off = wsum[w] + (si - s);
    #pragma unroll
    for (int j = 0; j < SCAN_CHUNK; j++) {
        int idx = base + j;
        if (idx < NN) {
            int st = off + loc[j];
            starts[idx] = st;
            fill[idx] = st;
        }
    }
    if (t == 1023) starts[NN] = off + s;
}
__global__ void csr_fill(const int* __restrict__ dst,
                         int* __restrict__ fill, int* __restrict__ eid) {
    int e = blockIdx.x * blockDim.x + threadIdx.x;
    if (e < EE) {
        int p = atomicAdd(&fill[dst[e]], 1);
        eid[p] = e;
    }
}

// ---------------- preprocessing ----------------------------------------------
__global__ void split_x(const float* __restrict__ x,
                        __nv_bfloat16* __restrict__ hi, __nv_bfloat16* __restrict__ lo) {
    int i = blockIdx.x * blockDim.x + threadIdx.x;
    if (i >= NN * XPAD) return;
    int r = i / XPAD, c = i % XPAD;
    float v = 0.f;
    if (c < RNAD)                            v = x[(size_t)r * (RNAD + PROTD) + c];
    else if (c >= KRNA && c < KRNA + PROTD)  v = x[(size_t)r * (RNAD + PROTD) + RNAD + (c - KRNA)];
    __nv_bfloat16 h, l; bsplit(v, h, l);
    hi[i] = h; lo[i] = l;
}
__global__ void split_w(const float* __restrict__ W, int K, int N, int Kp,
                        __nv_bfloat16* __restrict__ hi, __nv_bfloat16* __restrict__ lo) {
    int i = blockIdx.x * blockDim.x + threadIdx.x;
    if (i >= N * Kp) return;
    int n = i / Kp, k = i % Kp;
    float v = (k < K) ? W[(size_t)k * N + n] : 0.f;
    __nv_bfloat16 h, l; bsplit(v, h, l);
    hi[i] = h; lo[i] = l;
}
__global__ void bias3(const float* __restrict__ lb, float* __restrict__ o) {
    int i = blockIdx.x * blockDim.x + threadIdx.x;
    if (i < BIGW) o[i] = (i < 1024) ? 0.f : lb[i - 1024];
}
__global__ void bias2(const float* __restrict__ a, const float* __restrict__ b,
                      float* __restrict__ o) {
    int i = threadIdx.x;
    if (i < 256) o[i] = (i < 128) ? a[i] : b[i - 128];
}

// ============================================================================
// bf16 tensor-core GEMM, pre-split operands, ldmatrix fragment loads (R8).
// ============================================================================
template<int BM>
__global__ void __launch_bounds__(256, 2)
bf16_gemm(const __nv_bfloat16* __restrict__ Ah, const __nv_bfloat16* __restrict__ Al, int lda,
          const __nv_bfloat16* __restrict__ Bh, const __nv_bfloat16* __restrict__ Bl, int ldb,
          float* __restrict__ C, int ldc,
          __nv_bfloat16* __restrict__ Chi, __nv_bfloat16* __restrict__ Clo, int ldch,
          const float* __restrict__ bias,
          int M, int N, int Kp, int relu) {
    constexpr int NI  = BM / 32;
    constexpr int AT  = BM * 40;
    constexpr int BT  = 128 * 40;
    constexpr int STG = 2 * AT + 2 * BT;
    extern __shared__ uint16_t sm[];

    const int tid   = threadIdx.x;
    const int lane  = tid & 31;
    const int warp  = tid >> 5;
    const int wr    = warp >> 2;
    const int wc    = warp & 3;
    const int group = lane >> 2;
    const int tig   = lane & 3;
    const int blockRow = blockIdx.y * BM;
    const int blockCol = blockIdx.x * 128;
    const int NC = Kp >> 5;

    const uint32_t smb = (uint32_t)__cvta_generic_to_shared(sm);
    const int aRow = lane & 15,  aCol = (lane >> 4) << 3;
    const int bRow = ((lane >> 4) << 3) + (lane & 7), bCol = ((lane >> 3) & 1) << 3;

    auto loadStage = [&](int c, int s) {
        uint16_t* base = sm + s * STG;
        int k0 = c << 5;
        for (int i = tid; i < BM * 4; i += 256) {
            int r = i >> 2, ch = i & 3;
            int gr = blockRow + r;
            int sz = (gr < M) ? 16 : 0;
            const __nv_bfloat16* ph = sz ? (Ah + (size_t)gr * lda + k0 + ch * 8) : Ah;
            const __nv_bfloat16* pl = sz ? (Al + (size_t)gr * lda + k0 + ch * 8) : Al;
            cpa16((uint32_t)__cvta_generic_to_shared(base + r * 40 + ch * 8), ph, sz);
            cpa16((uint32_t)__cvta_generic_to_shared(base + AT + r * 40 + ch * 8), pl, sz);
        }
        uint16_t* bb = base + 2 * AT;
        for (int i = tid; i < 128 * 4; i += 256) {
            int r = i >> 2, ch = i & 3;
            int gn = blockCol + r;
            int sz = (gn < N) ? 16 : 0;
            const __nv_bfloat16* ph = sz ? (Bh + (size_t)gn * ldb + k0 + ch * 8) : Bh;
            const __nv_bfloat16* pl = sz ? (Bl + (size_t)gn * ldb + k0 + ch * 8) : Bl;
            cpa16((uint32_t)__cvta_generic_to_shared(bb + r * 40 + ch * 8), ph, sz);
            cpa16((uint32_t)__cvta_generic_to_shared(bb + BT + r * 40 + ch * 8), pl, sz);
        }
        asm volatile("cp.async.commit_group;\n");
    };

    float acc[NI][4][4];
    #pragma unroll
    for (int i = 0; i < NI; i++)
        #pragma unroll
        for (int j = 0; j < 4; j++) {
            acc[i][j][0] = 0.f; acc[i][j][1] = 0.f;
            acc[i][j][2] = 0.f; acc[i][j][3] = 0.f;
        }

    loadStage(0, 0);

    for (int c = 0; c < NC; c++) {
        if (c + 1 < NC) {
            loadStage(c + 1, (c + 1) & 1);
            asm volatile("cp.async.wait_group 1;\n" ::: "memory");
        } else {
            asm volatile("cp.async.wait_group 0;\n" ::: "memory");
        }
        __syncthreads();

        const uint32_t stB = smb + (uint32_t)((c & 1) * STG) * 2;
        const uint32_t uAh = stB;
        const uint32_t uAl = stB + AT * 2;
        const uint32_t uBh = stB + 2 * AT * 2;
        const uint32_t uBl = stB + (2 * AT + BT) * 2;

        #pragma unroll
        for (int ks = 0; ks < 2; ks++) {
            const int kb = ks * 16;
            uint32_t bh[4][2], bl[4][2];
            #pragma unroll
            for (int p = 0; p < 2; p++) {
                int n = wc * 32 + p * 16 + bRow;
                uint32_t off = (uint32_t)(n * 40 + kb + bCol) * 2;
                LDMX4(bh[2*p][0], bh[2*p][1], bh[2*p+1][0], bh[2*p+1][1], uBh + off);
                LDMX4(bl[2*p][0], bl[2*p][1], bl[2*p+1][0], bl[2*p+1][1], uBl + off);
            }
            #pragma unroll
            for (int i = 0; i < NI; i++) {
                int r = wr * (BM / 2) + i * 16 + aRow;
                uint32_t off = (uint32_t)(r * 40 + kb + aCol) * 2;
                uint32_t ah0, ah1, ah2, ah3, al0, al1, al2, al3;
                LDMX4(ah0, ah1, ah2, ah3, uAh + off);
                LDMX4(al0, al1, al2, al3, uAl + off);
                #pragma unroll
                for (int j = 0; j < 4; j++) {
                    mma_bf16(acc[i][j], ah0, ah1, ah2, ah3, bh[j][0], bh[j][1]);
                    mma_bf16(acc[i][j], al0, al1, al2, al3, bh[j][0], bh[j][1]);
                    mma_bf16(acc[i][j], ah0, ah1, ah2, ah3, bl[j][0], bl[j][1]);
                }
            }
        }
        __syncthreads();
    }

    #pragma unroll
    for (int i = 0; i < NI; i++) {
        int r0 = blockRow + wr * (BM / 2) + i * 16 + group;
        int r1 = r0 + 8;
        #pragma unroll
        for (int j = 0; j < 4; j++) {
            int gc = blockCol + wc * 32 + j * 8 + tig * 2;
            if (gc >= N) continue;
            float bi0 = bias ? bias[gc] : 0.f;
            float bi1 = bias ? bias[gc + 1] : 0.f;
            float v0 = acc[i][j][0] + bi0, v1 = acc[i][j][1] + bi1;
            float v2 = acc[i][j][2] + bi0, v3 = acc[i][j][3] + bi1;
            if (relu) {
                v0 = fmaxf(v0, 0.f); v1 = fmaxf(v1, 0.f);
                v2 = fmaxf(v2, 0.f); v3 = fmaxf(v3, 0.f);
            }
            if (r0 < M) {
                if (C) *(float2*)(C + (size_t)r0 * ldc + gc) = make_float2(v0, v1);
                if (Chi) {
                    __nv_bfloat16 h0, l0, h1, l1;
                    bsplit(v0, h0, l0); bsplit(v1, h1, l1);
                    Chi[(size_t)r0 * ldch + gc] = h0; Chi[(size_t)r0 * ldch + gc + 1] = h1;
                    Clo[(size_t)r0 * ldch + gc] = l0; Clo[(size_t)r0 * ldch + gc + 1] = l1;
                }
            }
            if (r1 < M) {
                if (C) *(float2*)(C + (size_t)r1 * ldc + gc) = make_float2(v2, v3);
                if (Chi) {
                    __nv_bfloat16 h2, l2, h3, l3;
                    bsplit(v2, h2, l2); bsplit(v3, h3, l3);
                    Chi[(size_t)r1 * ldch + gc] = h2; Chi[(size_t)r1 * ldch + gc + 1] = h3;
                    Clo[(size_t)r1 * ldch + gc] = l2; Clo[(size_t)r1 * ldch + gc + 1] = l3;
                }
            }
        }
    }
}

// ---------------- GAT: attention scores (strided xs/xd) --------------------
__global__ void att_scores(const float* __restrict__ xs, const float* __restrict__ xd,
                           int S,
                           const float* __restrict__ att_s, const float* __restrict__ att_d,
                           float* __restrict__ a_s, float* __restrict__ a_d) {
    int n = blockIdx.x;
    int w = threadIdx.x >> 5;
    int lane = threadIdx.x & 31;
    size_t base = (size_t)n * S + w * HIDD;
    float s = 0.f, d = 0.f;
    #pragma unroll
    for (int c = lane; c < HIDD; c += 32) {
        s += xs[base + c] * att_s[w * HIDD + c];
        d += xd[base + c] * att_d[w * HIDD + c];
    }
    #pragma unroll
    for (int o = 16; o > 0; o >>= 1) {
        s += __shfl_down_sync(0xffffffffu, s, o);
        d += __shfl_down_sync(0xffffffffu, d, o);
    }
    if (lane == 0) { a_s[n * NH + w] = s; a_d[n * NH + w] = d; }
}

// ---------------- GAT aggregation (gather over CSR, alpha buffer — R8) ------
__global__ void __launch_bounds__(128)
gat_aggregate(const int* __restrict__ starts, const int* __restrict__ eid,
              const int* __restrict__ src,
              const float* __restrict__ a_s, const float* __restrict__ a_d,
              const float* __restrict__ xs, int S,
              float* __restrict__ alpha, float* __restrict__ gat) {
    int n = blockIdx.x;
    int h = threadIdx.x >> 5;
    int lane = threadIdx.x & 31;
    int beg = starts[n], end = starts[n + 1];

    float adn = a_d[n * NH + h];

    float mx = -3.4e38f;
    for (int i = beg + lane; i < end; i += 32) {
        int e = eid[i];
        float a = a_s[src[e] * NH + h] + adn;
        a = a > 0.f ? a : 0.2f * a;
        alpha[(size_t)i * NH + h] = a;
        mx = fmaxf(mx, a);
    }
    #pragma unroll
    for (int o = 16; o > 0; o >>= 1)
        mx = fmaxf(mx, __shfl_xor_sync(0xffffffffu, mx, o));

    float den = 0.f;
    float4 acc = make_float4(0.f, 0.f, 0.f, 0.f);
    const int chOff = h * HIDD + lane * 4;
    for (int i = beg; i < end; i++) {
        int e = eid[i];
        float w = expf(alpha[(size_t)i * NH + h] - mx);
        den += w;
        const float4 v = *(const float4*)(xs + (size_t)src[e] * S + chOff);
        acc.x += v.x * w; acc.y += v.y * w;
        acc.z += v.z * w; acc.w += v.w * w;
    }
    float inv = 1.f / (den + 1e-16f);
    acc.x *= inv; acc.y *= inv; acc.z *= inv; acc.w *= inv;
    *(float4*)(gat + (size_t)n * DMID + chOff) = acc;
}

// ---------------- residual (+bias) + LayerNorm + ReLU -> bf16 hi/lo --------
__global__ void resid_ln_relu(const float* __restrict__ gat, const float* __restrict__ cb,
                              const float* __restrict__ lin, int linS,
                              const float* __restrict__ g, const float* __restrict__ b,
                              __nv_bfloat16* __restrict__ hh, __nv_bfloat16* __restrict__ hl) {
    int row = blockIdx.x;
    int t = threadIdx.x;
    size_t gb = (size_t)row * DMID;
    size_t lb = (size_t)row * linS;
    float v0 = gat[gb + t]       + cb[t]       + lin[lb + t];
    float v1 = gat[gb + 256 + t] + cb[256 + t] + lin[lb + 256 + t];
    float s = v0 + v1;
    float ss = v0 * v0 + v1 * v1;
    #pragma unroll
    for (int o = 16; o > 0; o >>= 1) {
        s  += __shfl_down_sync(0xffffffffu, s, o);
        ss += __shfl_down_sync(0xffffffffu, ss, o);
    }
    __shared__ float shs[8], shss[8];
    __shared__ float mu_sh, inv_sh;
    int w = t >> 5, lane = t & 31;
    if (lane == 0) { shs[w] = s; shss[w] = ss; }
    __syncthreads();
    if (t == 0) {
        float S = 0.f, SS = 0.f;
        #pragma unroll
        for (int i = 0; i < 8; i++) { S += shs[i]; SS += shss[i]; }
        float mu = S * (1.f / DMID);
        float var = SS * (1.f / DMID) - mu * mu;
        mu_sh = mu;
        inv_sh = rsqrtf(var + 1e-5f);
    }
    __syncthreads();
    float mu = mu_sh, inv = inv_sh;
    float o0 = fmaxf((v0 - mu) * inv * g[t]       + b[t],       0.f);
    float o1 = fmaxf((v1 - mu) * inv * g[256 + t] + b[256 + t], 0.f);
    __nv_bfloat16 h0, l0, h1, l1;
    bsplit(o0, h0, l0); bsplit(o1, h1, l1);
    hh[gb + t] = h0;       hl[gb + t] = l0;
    hh[gb + 256 + t] = h1; hl[gb + 256 + t] = l1;
}

__global__ void resid_add(const float* __restrict__ gat, const float* __restrict__ cb,
                          const float* __restrict__ lin, int linS,
                          __nv_bfloat16* __restrict__ hh, __nv_bfloat16* __restrict__ hl) {
    int i = blockIdx.x * blockDim.x + threadIdx.x;
    int stride = gridDim.x * blockDim.x;
    for (; i < NN * DMID; i += stride) {
        int row = i >> 9, col = i & (DMID - 1);
        float v = gat[i] + cb[col] + lin[(size_t)row * linS + col];
        __nv_bfloat16 h, l; bsplit(v, h, l);
        hh[i] = h; hl[i] = l;
    }
}

// ---------------- host -------------------------------------------------------
struct WSpec { int off, K, N, Kp; };

static void gemm128(const __nv_bfloat16* Ah, const __nv_bfloat16* Al, int lda,
                    const __nv_bfloat16* Bh, const __nv_bfloat16* Bl, int ldb,
                    float* C, int ldc, __nv_bfloat16* Chi, __nv_bfloat16* Clo, int ldch,
                    const float* bias, int M, int N, int Kp, int relu) {
    constexpr int SM_BYTES = (2 * 128 * 40 + 2 * 128 * 40) * 2 * 2;
    cudaFuncSetAttribute(bf16_gemm<128>,
                         cudaFuncAttributeMaxDynamicSharedMemorySize, SM_BYTES);
    dim3 grid((N + 127) / 128, (M + 127) / 128);
    bf16_gemm<128><<<grid, 256, SM_BYTES>>>(Ah, Al, lda, Bh, Bl, ldb, C, ldc,
        Chi, Clo, ldch, bias, M, N, Kp, relu);
}
static void gemm64(const __nv_bfloat16* Ah, const __nv_bfloat16* Al, int lda,
                   const __nv_bfloat16* Bh, const __nv_bfloat16* Bl, int ldb,
                   float* C, int ldc, __nv_bfloat16* Chi, __nv_bfloat16* Clo, int ldch,
                   const float* bias, int M, int N, int Kp, int relu) {
    constexpr int SM_BYTES = (2 * 64 * 40 + 2 * 128 * 40) * 2 * 2;
    cudaFuncSetAttribute(bf16_gemm<64>,
                         cudaFuncAttributeMaxDynamicSharedMemorySize, SM_BYTES);
    dim3 grid((N + 127) / 128, (M + 63) / 64);
    bf16_gemm<64><<<grid, 256, SM_BYTES>>>(Ah, Al, lda, Bh, Bl, ldb, C, ldc,
        Chi, Clo, ldch, bias, M, N, Kp, relu);
}

extern "C" void kernel_launch(void* const* d_in, const int* in_sizes, int n_in,
                              void* d_out, int out_size) {
    const float* x      = (const float*)d_in[0];
    const void*  ei     = d_in[1];
    const float* W_rna  = (const float*)d_in[2];
    const float* b_rna  = (const float*)d_in[3];
    const float* W_prot = (const float*)d_in[4];
    const float* b_prot = (const float*)d_in[5];
    const float* c1_Ws  = (const float*)d_in[6];
    const float* c1_Wd  = (const float*)d_in[7];
    const float* c1_as  = (const float*)d_in[8];
    const float* c1_ad  = (const float*)d_in[9];
    const float* c1_b   = (const float*)d_in[10];
    const float* l1_W   = (const float*)d_in[11];
    const float* l1_b   = (const float*)d_in[12];
    const float* ln_g   = (const float*)d_in[13];
    const float* ln_b   = (const float*)d_in[14];
    const float* c2_Ws  = (const float*)d_in[15];
    const float* c2_Wd  = (const float*)d_in[16];
    const float* c2_as  = (const float*)d_in[17];
    const float* c2_ad  = (const float*)d_in[18];
    const float* c2_b   = (const float*)d_in[19];
    const float* l2_W   = (const float*)d_in[20];
    const float* l2_b   = (const float*)d_in[21];
    const float* agg_W  = (const float*)d_in[22];
    const float* agg_b  = (const float*)d_in[23];
    const float* dr_W   = (const float*)d_in[24];
    const float* dr_b   = (const float*)d_in[25];
    const float* dp_W   = (const float*)d_in[26];
    const float* dp_b   = (const float*)d_in[27];
    const float* rr_W   = (const float*)d_in[28];
    const float* rr_b   = (const float*)d_in[29];
    const float* rp_W   = (const float*)d_in[30];
    const float* rp_b   = (const float*)d_in[31];

    float* out = (float*)d_out;
    float* out_rna  = out;
    float* out_prot = out + (size_t)NN * RNAD;
    float* out_emb  = out + (size_t)NN * (RNAD + PROTD);

    float *big, *gat, *as_, *ad_, *alpha, *bias1, *bias2b, *biasT;
    int *srcI, *dstI, *cnt, *starts, *fill, *eid;
    __nv_bfloat16 *xh, *xl, *xinh, *xinl, *hh, *hl, *embh, *embl, *th, *tl, *wh, *wl;
    cudaGetSymbolAddress((void**)&big,   g_big);
    cudaGetSymbolAddress((void**)&gat,   g_gat);
    cudaGetSymbolAddress((void**)&as_,   g_as);
    cudaGetSymbolAddress((void**)&ad_,   g_ad);
    cudaGetSymbolAddress((void**)&alpha, g_alpha);
    cudaGetSymbolAddress((void**)&srcI,  g_src);
    cudaGetSymbolAddress((void**)&dstI,  g_dst);
    cudaGetSymbolAddress((void**)&cnt,   g_cnt);
    cudaGetSymbolAddress((void**)&starts,g_starts);
    cudaGetSymbolAddress((void**)&fill,  g_fill);
    cudaGetSymbolAddress((void**)&eid,   g_eid);
    cudaGetSymbolAddress((void**)&bias1, g_bias1);
    cudaGetSymbolAddress((void**)&bias2b,g_bias2);
    cudaGetSymbolAddress((void**)&biasT, g_biasT);
    cudaGetSymbolAddress((void**)&xh,    g_xh);
    cudaGetSymbolAddress((void**)&xl,    g_xl);
    cudaGetSymbolAddress((void**)&xinh,  g_xinh);
    cudaGetSymbolAddress((void**)&xinl,  g_xinl);
    cudaGetSymbolAddress((void**)&hh,    g_hh);
    cudaGetSymbolAddress((void**)&hl,    g_hl);
    cudaGetSymbolAddress((void**)&embh,  g_embh);
    cudaGetSymbolAddress((void**)&embl,  g_embl);
    cudaGetSymbolAddress((void**)&th,    g_th);
    cudaGetSymbolAddress((void**)&tl,    g_tl);
    cudaGetSymbolAddress((void**)&wh,    g_wh);
    cudaGetSymbolAddress((void**)&wl,    g_wl);

    const int EB = 256;

    // ---- decode edges + CSR -------------------------------------------------
    detect_fmt<<<1, 32>>>((const unsigned*)ei);
    decode_idx<<<(2 * EE + EB - 1) / EB, EB>>>(ei, srcI, dstI);
    zero_u32<<<40, 256>>>((unsigned*)cnt, NN);
    csr_hist<<<(EE + EB - 1) / EB, EB>>>(dstI, cnt);
    csr_scan<<<1, 1024>>>(cnt, starts, fill);
    csr_fill<<<(EE + EB - 1) / EB, EB>>>(dstI, fill, eid);

    // ---- preprocessing -------------------------------------------------------
    split_x<<<(NN * XPAD + 255) / 256, 256>>>(x, xh, xl);
    const WSpec ws[13] = {
        {OFF_WRNA,  RNAD, EMBD, KRNA},  {OFF_WPROT, PROTD, EMBD, KPROT},
        {OFF_C1WS,  DIN,  DMID, DIN},   {OFF_C1WD,  DIN,  DMID, DIN},
        {OFF_L1W,   DIN,  DMID, DIN},
        {OFF_C2WS,  DMID, DMID, DMID},  {OFF_C2WD,  DMID, DMID, DMID},
        {OFF_L2W,   DMID, DMID, DMID},
        {OFF_AGG,   DMID, EMBD, DMID},
        {OFF_DR,    EMBD, EMBD, EMBD},  {OFF_DP,    EMBD, EMBD, EMBD},
        {OFF_RR,    EMBD, RNAD, EMBD},  {OFF_RP,    EMBD, PROTD, EMBD},
    };
    const float* wp[13] = {W_rna, W_prot, c1_Ws, c1_Wd, l1_W, c2_Ws, c2_Wd, l2_W,
                           agg_W, dr_W, dp_W, rr_W, rp_W};
    for (int i = 0; i < 13; i++) {
        int n = ws[i].N * ws[i].Kp;
        split_w<<<(n + 255) / 256, 256>>>(wp[i], ws[i].K, ws[i].N, ws[i].Kp,
                                          wh + ws[i].off, wl + ws[i].off);
    }
    bias3<<<6, 256>>>(l1_b, bias1);
    bias3<<<6, 256>>>(l2_b, bias2b);
    bias2<<<1, 256>>>(dr_b, dp_b, biasT);

    // ---- input embeddings -> xin hi/lo ---------------------------------------
    gemm64(xh, xl, XPAD, wh + OFF_WRNA, wl + OFF_WRNA, KRNA,
           nullptr, 0, xinh, xinl, DIN, b_rna, NN, EMBD, KRNA, 0);
    gemm64(xh + KRNA, xl + KRNA, XPAD, wh + OFF_WPROT, wl + OFF_WPROT, KPROT,
           nullptr, 0, xinh + EMBD, xinl + EMBD, DIN, b_prot, NN, EMBD, KPROT, 0);

    // ================= Block 1: fused xs|xd|lin ============================
    gemm128(xinh, xinl, DIN, wh + OFF_C1WS, wl + OFF_C1WS, DIN,
            big, BIGW, nullptr, nullptr, 0, bias1, NN, BIGW, DIN, 0);
    att_scores<<<NN, 128>>>(big, big + 512, BIGW, c1_as, c1_ad, as_, ad_);
    gat_aggregate<<<NN, 128>>>(starts, eid, srcI, as_, ad_, big, BIGW, alpha, gat);
    resid_ln_relu<<<NN, 256>>>(gat, c1_b, big + 1024, BIGW, ln_g, ln_b, hh, hl);

    // ================= Block 2: fused xs|xd|lin ============================
    gemm128(hh, hl, DMID, wh + OFF_C2WS, wl + OFF_C2WS, DMID,
            big, BIGW, nullptr, nullptr, 0, bias2b, NN, BIGW, DMID, 0);
    att_scores<<<NN, 128>>>(big, big + 512, BIGW, c2_as, c2_ad, as_, ad_);
    gat_aggregate<<<NN, 128>>>(starts, eid, srcI, as_, ad_, big, BIGW, alpha, gat);
    resid_add<<<512, 256>>>(gat, c2_b, big + 1024, BIGW, hh, hl);

    // ================= Heads ===============================================
    gemm64(hh, hl, DMID, wh + OFF_AGG, wl + OFF_AGG, DMID,
           out_emb, EMBD, embh, embl, EMBD, agg_b, NN, EMBD, DMID, 1);

    gemm64(embh, embl, EMBD, wh + OFF_DR, wl + OFF_DR, EMBD,
           nullptr, 0, th, tl, 256, biasT, NN, 256, EMBD, 0);

    gemm128(th, tl, 256, wh + OFF_RR, wl + OFF_RR, EMBD,
            out_rna, RNAD, nullptr, nullptr, 0, rr_b, NN, RNAD, EMBD, 0);
    gemm64(th + 128, tl + 128, 256, wh + OFF_RP, wl + OFF_RP, EMBD,
           out_prot, PROTD, nullptr, nullptr, 0, rp_b, NN, PROTD, EMBD, 0);
}

// round 12
// speedup vs baseline: 1.1236x; 1.0581x over previous
#include <cuda_runtime.h>
#include <cuda_bf16.h>
#include <cstdint>

#define NN   10000
#define EE   160000
#define RNAD 2000
#define PROTD 100
#define EMBD 128
#define HIDD 128
#define NH   4
#define DIN  256
#define DMID 512
#define BIGW 1536

#define KRNA  2016
#define KPROT 128
#define XPAD  (KRNA + KPROT)

// ---------------- scratch (static device globals) --------------------------
__device__ float          g_big[NN * BIGW];
__device__ float          g_gat[NN * DMID];
__device__ float          g_as [NN * NH];
__device__ float          g_ad [NN * NH];
__device__ float          g_alpha[EE * NH];
__device__ int            g_src[EE];
__device__ int            g_dst[EE];
__device__ int            g_is64;
__device__ int            g_cnt[NN];
__device__ int            g_starts[NN + 1];
__device__ int            g_fill[NN];
__device__ int            g_eid[EE];
__device__ float          g_bias1[BIGW];
__device__ float          g_bias2[BIGW];
__device__ float          g_biasT[256];

__device__ __nv_bfloat16  g_xh [NN * XPAD];
__device__ __nv_bfloat16  g_xl [NN * XPAD];
__device__ __nv_bfloat16  g_xinh[NN * DIN];
__device__ __nv_bfloat16  g_xinl[NN * DIN];
__device__ __nv_bfloat16  g_hh [NN * DMID];
__device__ __nv_bfloat16  g_hl [NN * DMID];
__device__ __nv_bfloat16  g_embh[NN * EMBD];
__device__ __nv_bfloat16  g_embl[NN * EMBD];
__device__ __nv_bfloat16  g_th [NN * 256];
__device__ __nv_bfloat16  g_tl [NN * 256];

// weight arena (K-major, padded)
#define OFF_WRNA  0
#define OFF_WPROT 258048
#define OFF_C1WS  274432
#define OFF_C1WD  405504
#define OFF_L1W   536576
#define OFF_C2WS  667648
#define OFF_C2WD  929792
#define OFF_L2W   1191936
#define OFF_AGG   1454080
#define OFF_DR    1519616
#define OFF_DP    1536000
#define OFF_RR    1552384
#define OFF_RP    1808384
#define WARENA    1821184
__device__ __nv_bfloat16 g_wh[WARENA];
__device__ __nv_bfloat16 g_wl[WARENA];

// ---------------- helpers ---------------------------------------------------
__device__ __forceinline__ void bsplit(float v, __nv_bfloat16& h, __nv_bfloat16& l) {
    h = __float2bfloat16(v);
    l = __float2bfloat16(v - __bfloat162float(h));
}
__device__ __forceinline__ void cpa16(uint32_t dst, const void* src, int sz) {
    asm volatile("cp.async.ca.shared.global [%0], [%1], 16, %2;\n"
                 :: "r"(dst), "l"(src), "r"(sz));
}
__device__ __forceinline__ void mma_bf16(float* c, uint32_t a0, uint32_t a1,
                                         uint32_t a2, uint32_t a3,
                                         uint32_t b0, uint32_t b1) {
    asm volatile(
        "mma.sync.aligned.m16n8k16.row.col.f32.bf16.bf16.f32 "
        "{%0,%1,%2,%3}, {%4,%5,%6,%7}, {%8,%9}, {%0,%1,%2,%3};"
        : "+f"(c[0]), "+f"(c[1]), "+f"(c[2]), "+f"(c[3])
        : "r"(a0), "r"(a1), "r"(a2), "r"(a3), "r"(b0), "r"(b1));
}
#define LDMX4(r0, r1, r2, r3, addr) \
    asm volatile("ldmatrix.sync.aligned.m8n8.x4.shared.b16 {%0,%1,%2,%3}, [%4];" \
                 : "=r"(r0), "=r"(r1), "=r"(r2), "=r"(r3) : "r"(addr))

// ---------------- edge-index dtype detect + decode -------------------------
__global__ void detect_fmt(const unsigned* __restrict__ w) {
    if (threadIdx.x == 0 && blockIdx.x == 0) {
        unsigned acc = 0;
        for (int i = 1; i < 4096; i += 2) acc |= w[i];
        g_is64 = (acc == 0u) ? 1 : 0;
    }
}
__global__ void decode_idx(const void* __restrict__ ei,
                           int* __restrict__ src, int* __restrict__ dst) {
    int i = blockIdx.x * blockDim.x + threadIdx.x;
    if (i >= 2 * EE) return;
    long long v;
    if (g_is64) v = ((const long long*)ei)[i];
    else        v = (long long)((const int*)ei)[i];
    int vi = (int)v;
    vi = vi < 0 ? 0 : (vi >= NN ? NN - 1 : vi);
    if (i < EE) src[i] = vi;
    else        dst[i - EE] = vi;
}
__global__ void zero_u32(unsigned* p, int n) {
    int i = blockIdx.x * blockDim.x + threadIdx.x;
    int stride = gridDim.x * blockDim.x;
    for (; i < n; i += stride) p[i] = 0u;
}

// ---------------- CSR build --------------------------------------------------
__global__ void csr_hist(const int* __restrict__ dst, int* __restrict__ cnt) {
    int e = blockIdx.x * blockDim.x + threadIdx.x;
    if (e < EE) atomicAdd(&cnt[dst[e]], 1);
}
#define SCAN_CHUNK 10
__global__ void csr_scan(const int* __restrict__ cnt,
                         int* __restrict__ starts, int* __restrict__ fill) {
    __shared__ int wsum[32];
    int t = threadIdx.x;
    int lane = t & 31, w = t >> 5;
    int base = t * SCAN_CHUNK;
    int loc[SCAN_CHUNK];
    int s = 0;
    #pragma unroll
    for (int j = 0; j < SCAN_CHUNK; j++) {
        int idx = base + j;
        int v = (idx < NN) ? cnt[idx] : 0;
        loc[j] = s; s += v;
    }
    int si = s;
    #pragma unroll
    for (int o = 1; o < 32; o <<= 1) {
        int v = __shfl_up_sync(0xffffffffu, si, o);
        if (lane >= o) si += v;
    }
    if (lane == 31) wsum[w] = si;
    __syncthreads();
    if (w == 0) {
        int v = wsum[lane];
        int vi = v;
        #pragma unroll
        for (int o = 1; o < 32; o <<= 1) {
            int u = __shfl_up_sync(0xffffffffu, vi, o);
            if (lane >= o) vi += u;
        }
        wsum[lane] = vi - v;
    }
    __syncthreads();
    int off = wsum[w] + (si - s);
    #pragma unroll
    for (int j = 0; j < SCAN_CHUNK; j++) {
        int idx = base + j;
        if (idx < NN) {
            int st = off + loc[j];
            starts[idx] = st;
            fill[idx] = st;
        }
    }
    if (t == 1023) starts[NN] = off + s;
}
__global__ void csr_fill(const int* __restrict__ dst,
                         int* __restrict__ fill, int* __restrict__ eid) {
    int e = blockIdx.x * blockDim.x + threadIdx.x;
    if (e < EE) {
        int p = atomicAdd(&fill[dst[e]], 1);
        eid[p] = e;
    }
}

// ---------------- preprocessing ----------------------------------------------
// float4-vectorized x split (region boundaries are all %4 == 0)
__global__ void split_x4(const float* __restrict__ x,
                         __nv_bfloat16* __restrict__ hi, __nv_bfloat16* __restrict__ lo) {
    int i4 = blockIdx.x * blockDim.x + threadIdx.x;
    if (i4 >= NN * (XPAD / 4)) return;
    int r = i4 / (XPAD / 4);
    int c = (i4 % (XPAD / 4)) * 4;
    float4 v = make_float4(0.f, 0.f, 0.f, 0.f);
    if (c < RNAD)
        v = *(const float4*)(x + (size_t)r * (RNAD + PROTD) + c);
    else if (c >= KRNA && c < KRNA + PROTD)
        v = *(const float4*)(x + (size_t)r * (RNAD + PROTD) + RNAD + (c - KRNA));
    __nv_bfloat16 h0, l0, h1, l1, h2, l2, h3, l3;
    bsplit(v.x, h0, l0); bsplit(v.y, h1, l1);
    bsplit(v.z, h2, l2); bsplit(v.w, h3, l3);
    uint2 hv, lv;
    hv.x = (uint32_t)__bfloat16_as_ushort(h0) | ((uint32_t)__bfloat16_as_ushort(h1) << 16);
    hv.y = (uint32_t)__bfloat16_as_ushort(h2) | ((uint32_t)__bfloat16_as_ushort(h3) << 16);
    lv.x = (uint32_t)__bfloat16_as_ushort(l0) | ((uint32_t)__bfloat16_as_ushort(l1) << 16);
    lv.y = (uint32_t)__bfloat16_as_ushort(l2) | ((uint32_t)__bfloat16_as_ushort(l3) << 16);
    *(uint2*)(hi + (size_t)i4 * 4) = hv;
    *(uint2*)(lo + (size_t)i4 * 4) = lv;
}

// smem-tiled transpose split: coalesced reads of W[K,N] AND coalesced arena writes
__global__ void split_w_t(const float* __restrict__ W, int K, int N, int Kp,
                          __nv_bfloat16* __restrict__ hi, __nv_bfloat16* __restrict__ lo) {
    __shared__ float tile[32][33];
    int k0 = blockIdx.x * 32;
    int n0 = blockIdx.y * 32;
    int tx = threadIdx.x, ty = threadIdx.y;      // 32 x 8
    #pragma unroll
    for (int i = 0; i < 4; i++) {
        int k = k0 + ty + i * 8;
        int n = n0 + tx;
        tile[ty + i * 8][tx] = (k < K && n < N) ? W[(size_t)k * N + n] : 0.f;
    }
    __syncthreads();
    #pragma unroll
    for (int i = 0; i < 4; i++) {
        int n = n0 + ty + i * 8;
        int k = k0 + tx;
        if (n < N && k < Kp) {
            float v = tile[tx][ty + i * 8];
            __nv_bfloat16 h, l; bsplit(v, h, l);
            hi[(size_t)n * Kp + k] = h;
            lo[(size_t)n * Kp + k] = l;
        }
    }
}

__global__ void bias3(const float* __restrict__ lb, float* __restrict__ o) {
    int i = blockIdx.x * blockDim.x + threadIdx.x;
    if (i < BIGW) o[i] = (i < 1024) ? 0.f : lb[i - 1024];
}
__global__ void bias2(const float* __restrict__ a, const float* __restrict__ b,
                      float* __restrict__ o) {
    int i = threadIdx.x;
    if (i < 256) o[i] = (i < 128) ? a[i] : b[i - 128];
}

// ============================================================================
// bf16 tensor-core GEMM, pre-split operands, ldmatrix fragment loads (R8).
// ============================================================================
template<int BM>
__global__ void __launch_bounds__(256, 2)
bf16_gemm(const __nv_bfloat16* __restrict__ Ah, const __nv_bfloat16* __restrict__ Al, int lda,
          const __nv_bfloat16* __restrict__ Bh, const __nv_bfloat16* __restrict__ Bl, int ldb,
          float* __restrict__ C, int ldc,
          __nv_bfloat16* __restrict__ Chi, __nv_bfloat16* __restrict__ Clo, int ldch,
          const float* __restrict__ bias,
          int M, int N, int Kp, int relu) {
    constexpr int NI  = BM / 32;
    constexpr int AT  = BM * 40;
    constexpr int BT  = 128 * 40;
    constexpr int STG = 2 * AT + 2 * BT;
    extern __shared__ uint16_t sm[];

    const int tid   = threadIdx.x;
    const int lane  = tid & 31;
    const int warp  = tid >> 5;
    const int wr    = warp >> 2;
    const int wc    = warp & 3;
    const int group = lane >> 2;
    const int tig   = lane & 3;
    const int blockRow = blockIdx.y * BM;
    const int blockCol = blockIdx.x * 128;
    const int NC = Kp >> 5;

    const uint32_t smb = (uint32_t)__cvta_generic_to_shared(sm);
    const int aRow = lane & 15,  aCol = (lane >> 4) << 3;
    const int bRow = ((lane >> 4) << 3) + (lane & 7), bCol = ((lane >> 3) & 1) << 3;

    auto loadStage = [&](int c, int s) {
        uint16_t* base = sm + s * STG;
        int k0 = c << 5;
        for (int i = tid; i < BM * 4; i += 256) {
            int r = i >> 2, ch = i & 3;
            int gr = blockRow + r;
            int sz = (gr < M) ? 16 : 0;
            const __nv_bfloat16* ph = sz ? (Ah + (size_t)gr * lda + k0 + ch * 8) : Ah;
            const __nv_bfloat16* pl = sz ? (Al + (size_t)gr * lda + k0 + ch * 8) : Al;
            cpa16((uint32_t)__cvta_generic_to_shared(base + r * 40 + ch * 8), ph, sz);
            cpa16((uint32_t)__cvta_generic_to_shared(base + AT + r * 40 + ch * 8), pl, sz);
        }
        uint16_t* bb = base + 2 * AT;
        for (int i = tid; i < 128 * 4; i += 256) {
            int r = i >> 2, ch = i & 3;
            int gn = blockCol + r;
            int sz = (gn < N) ? 16 : 0;
            const __nv_bfloat16* ph = sz ? (Bh + (size_t)gn * ldb + k0 + ch * 8) : Bh;
            const __nv_bfloat16* pl = sz ? (Bl + (size_t)gn * ldb + k0 + ch * 8) : Bl;
            cpa16((uint32_t)__cvta_generic_to_shared(bb + r * 40 + ch * 8), ph, sz);
            cpa16((uint32_t)__cvta_generic_to_shared(bb + BT + r * 40 + ch * 8), pl, sz);
        }
        asm volatile("cp.async.commit_group;\n");
    };

    float acc[NI][4][4];
    #pragma unroll
    for (int i = 0; i < NI; i++)
        #pragma unroll
        for (int j = 0; j < 4; j++) {
            acc[i][j][0] = 0.f; acc[i][j][1] = 0.f;
            acc[i][j][2] = 0.f; acc[i][j][3] = 0.f;
        }

    loadStage(0, 0);

    for (int c = 0; c < NC; c++) {
        if (c + 1 < NC) {
            loadStage(c + 1, (c + 1) & 1);
            asm volatile("cp.async.wait_group 1;\n" ::: "memory");
        } else {
            asm volatile("cp.async.wait_group 0;\n" ::: "memory");
        }
        __syncthreads();

        const uint32_t stB = smb + (uint32_t)((c & 1) * STG) * 2;
        const uint32_t uAh = stB;
        const uint32_t uAl = stB + AT * 2;
        const uint32_t uBh = stB + 2 * AT * 2;
        const uint32_t uBl = stB + (2 * AT + BT) * 2;

        #pragma unroll
        for (int ks = 0; ks < 2; ks++) {
            const int kb = ks * 16;
            uint32_t bh[4][2], bl[4][2];
            #pragma unroll
            for (int p = 0; p < 2; p++) {
                int n = wc * 32 + p * 16 + bRow;
                uint32_t off = (uint32_t)(n * 40 + kb + bCol) * 2;
                LDMX4(bh[2*p][0], bh[2*p][1], bh[2*p+1][0], bh[2*p+1][1], uBh + off);
                LDMX4(bl[2*p][0], bl[2*p][1], bl[2*p+1][0], bl[2*p+1][1], uBl + off);
            }
            #pragma unroll
            for (int i = 0; i < NI; i++) {
                int r = wr * (BM / 2) + i * 16 + aRow;
                uint32_t off = (uint32_t)(r * 40 + kb + aCol) * 2;
                uint32_t ah0, ah1, ah2, ah3, al0, al1, al2, al3;
                LDMX4(ah0, ah1, ah2, ah3, uAh + off);
                LDMX4(al0, al1, al2, al3, uAl + off);
                #pragma unroll
                for (int j = 0; j < 4; j++) {
                    mma_bf16(acc[i][j], ah0, ah1, ah2, ah3, bh[j][0], bh[j][1]);
                    mma_bf16(acc[i][j], al0, al1, al2, al3, bh[j][0], bh[j][1]);
                    mma_bf16(acc[i][j], ah0, ah1, ah2, ah3, bl[j][0], bl[j][1]);
                }
            }
        }
        __syncthreads();
    }

    #pragma unroll
    for (int i = 0; i < NI; i++) {
        int r0 = blockRow + wr * (BM / 2) + i * 16 + group;
        int r1 = r0 + 8;
        #pragma unroll
        for (int j = 0; j < 4; j++) {
            int gc = blockCol + wc * 32 + j * 8 + tig * 2;
            if (gc >= N) continue;
            float bi0 = bias ? bias[gc] : 0.f;
            float bi1 = bias ? bias[gc + 1] : 0.f;
            float v0 = acc[i][j][0] + bi0, v1 = acc[i][j][1] + bi1;
            float v2 = acc[i][j][2] + bi0, v3 = acc[i][j][3] + bi1;
            if (relu) {
                v0 = fmaxf(v0, 0.f); v1 = fmaxf(v1, 0.f);
                v2 = fmaxf(v2, 0.f); v3 = fmaxf(v3, 0.f);
            }
            if (r0 < M) {
                if (C) *(float2*)(C + (size_t)r0 * ldc + gc) = make_float2(v0, v1);
                if (Chi) {
                    __nv_bfloat16 h0, l0, h1, l1;
                    bsplit(v0, h0, l0); bsplit(v1, h1, l1);
                    Chi[(size_t)r0 * ldch + gc] = h0; Chi[(size_t)r0 * ldch + gc + 1] = h1;
                    Clo[(size_t)r0 * ldch + gc] = l0; Clo[(size_t)r0 * ldch + gc + 1] = l1;
                }
            }
            if (r1 < M) {
                if (C) *(float2*)(C + (size_t)r1 * ldc + gc) = make_float2(v2, v3);
                if (Chi) {
                    __nv_bfloat16 h2, l2, h3, l3;
                    bsplit(v2, h2, l2); bsplit(v3, h3, l3);
                    Chi[(size_t)r1 * ldch + gc] = h2; Chi[(size_t)r1 * ldch + gc + 1] = h3;
                    Clo[(size_t)r1 * ldch + gc] = l2; Clo[(size_t)r1 * ldch + gc + 1] = l3;
                }
            }
        }
    }
}

// ---------------- GAT: attention scores (strided xs/xd) --------------------
__global__ void att_scores(const float* __restrict__ xs, const float* __restrict__ xd,
                           int S,
                           const float* __restrict__ att_s, const float* __restrict__ att_d,
                           float* __restrict__ a_s, float* __restrict__ a_d) {
    int n = blockIdx.x;
    int w = threadIdx.x >> 5;
    int lane = threadIdx.x & 31;
    size_t base = (size_t)n * S + w * HIDD;
    float s = 0.f, d = 0.f;
    #pragma unroll
    for (int c = lane; c < HIDD; c += 32) {
        s += xs[base + c] * att_s[w * HIDD + c];
        d += xd[base + c] * att_d[w * HIDD + c];
    }
    #pragma unroll
    for (int o = 16; o > 0; o >>= 1) {
        s += __shfl_down_sync(0xffffffffu, s, o);
        d += __shfl_down_sync(0xffffffffu, d, o);
    }
    if (lane == 0) { a_s[n * NH + w] = s; a_d[n * NH + w] = d; }
}

// ---------------- GAT aggregation (gather over CSR, alpha buffer — R8) ------
__global__ void __launch_bounds__(128)
gat_aggregate(const int* __restrict__ starts, const int* __restrict__ eid,
              const int* __restrict__ src,
              const float* __restrict__ a_s, const float* __restrict__ a_d,
              const float* __restrict__ xs, int S,
              float* __restrict__ alpha, float* __restrict__ gat) {
    int n = blockIdx.x;
    int h = threadIdx.x >> 5;
    int lane = threadIdx.x & 31;
    int beg = starts[n], end = starts[n + 1];

    float adn = a_d[n * NH + h];

    float mx = -3.4e38f;
    for (int i = beg + lane; i < end; i += 32) {
        int e = eid[i];
        float a = a_s[src[e] * NH + h] + adn;
        a = a > 0.f ? a : 0.2f * a;
        alpha[(size_t)i * NH + h] = a;
        mx = fmaxf(mx, a);
    }
    #pragma unroll
    for (int o = 16; o > 0; o >>= 1)
        mx = fmaxf(mx, __shfl_xor_sync(0xffffffffu, mx, o));

    float den = 0.f;
    float4 acc = make_float4(0.f, 0.f, 0.f, 0.f);
    const int chOff = h * HIDD + lane * 4;
    for (int i = beg; i < end; i++) {
        int e = eid[i];
        float w = expf(alpha[(size_t)i * NH + h] - mx);
        den += w;
        const float4 v = *(const float4*)(xs + (size_t)src[e] * S + chOff);
        acc.x += v.x * w; acc.y += v.y * w;
        acc.z += v.z * w; acc.w += v.w * w;
    }
    float inv = 1.f / (den + 1e-16f);
    acc.x *= inv; acc.y *= inv; acc.z *= inv; acc.w *= inv;
    *(float4*)(gat + (size_t)n * DMID + chOff) = acc;
}

// ---------------- residual (+bias) + LayerNorm + ReLU -> bf16 hi/lo --------
__global__ void resid_ln_relu(const float* __restrict__ gat, const float* __restrict__ cb,
                              const float* __restrict__ lin, int linS,
                              const float* __restrict__ g, const float* __restrict__ b,
                              __nv_bfloat16* __restrict__ hh, __nv_bfloat16* __restrict__ hl) {
    int row = blockIdx.x;
    int t = threadIdx.x;
    size_t gb = (size_t)row * DMID;
    size_t lb = (size_t)row * linS;
    float v0 = gat[gb + t]       + cb[t]       + lin[lb + t];
    float v1 = gat[gb + 256 + t] + cb[256 + t] + lin[lb + 256 + t];
    float s = v0 + v1;
    float ss = v0 * v0 + v1 * v1;
    #pragma unroll
    for (int o = 16; o > 0; o >>= 1) {
        s  += __shfl_down_sync(0xffffffffu, s, o);
        ss += __shfl_down_sync(0xffffffffu, ss, o);
    }
    __shared__ float shs[8], shss[8];
    __shared__ float mu_sh, inv_sh;
    int w = t >> 5, lane = t & 31;
    if (lane == 0) { shs[w] = s; shss[w] = ss; }
    __syncthreads();
    if (t == 0) {
        float S = 0.f, SS = 0.f;
        #pragma unroll
        for (int i = 0; i < 8; i++) { S += shs[i]; SS += shss[i]; }
        float mu = S * (1.f / DMID);
        float var = SS * (1.f / DMID) - mu * mu;
        mu_sh = mu;
        inv_sh = rsqrtf(var + 1e-5f);
    }
    __syncthreads();
    float mu = mu_sh, inv = inv_sh;
    float o0 = fmaxf((v0 - mu) * inv * g[t]       + b[t],       0.f);
    float o1 = fmaxf((v1 - mu) * inv * g[256 + t] + b[256 + t], 0.f);
    __nv_bfloat16 h0, l0, h1, l1;
    bsplit(o0, h0, l0); bsplit(o1, h1, l1);
    hh[gb + t] = h0;       hl[gb + t] = l0;
    hh[gb + 256 + t] = h1; hl[gb + 256 + t] = l1;
}

__global__ void resid_add(const float* __restrict__ gat, const float* __restrict__ cb,
                          const float* __restrict__ lin, int linS,
                          __nv_bfloat16* __restrict__ hh, __nv_bfloat16* __restrict__ hl) {
    int i = blockIdx.x * blockDim.x + threadIdx.x;
    int stride = gridDim.x * blockDim.x;
    for (; i < NN * DMID; i += stride) {
        int row = i >> 9, col = i & (DMID - 1);
        float v = gat[i] + cb[col] + lin[(size_t)row * linS + col];
        __nv_bfloat16 h, l; bsplit(v, h, l);
        hh[i] = h; hl[i] = l;
    }
}

// ---------------- host -------------------------------------------------------
struct WSpec { int off, K, N, Kp; };

static void gemm128(const __nv_bfloat16* Ah, const __nv_bfloat16* Al, int lda,
                    const __nv_bfloat16* Bh, const __nv_bfloat16* Bl, int ldb,
                    float* C, int ldc, __nv_bfloat16* Chi, __nv_bfloat16* Clo, int ldch,
                    const float* bias, int M, int N, int Kp, int relu) {
    constexpr int SM_BYTES = (2 * 128 * 40 + 2 * 128 * 40) * 2 * 2;
    cudaFuncSetAttribute(bf16_gemm<128>,
                         cudaFuncAttributeMaxDynamicSharedMemorySize, SM_BYTES);
    dim3 grid((N + 127) / 128, (M + 127) / 128);
    bf16_gemm<128><<<grid, 256, SM_BYTES>>>(Ah, Al, lda, Bh, Bl, ldb, C, ldc,
        Chi, Clo, ldch, bias, M, N, Kp, relu);
}
static void gemm64(const __nv_bfloat16* Ah, const __nv_bfloat16* Al, int lda,
                   const __nv_bfloat16* Bh, const __nv_bfloat16* Bl, int ldb,
                   float* C, int ldc, __nv_bfloat16* Chi, __nv_bfloat16* Clo, int ldch,
                   const float* bias, int M, int N, int Kp, int relu) {
    constexpr int SM_BYTES = (2 * 64 * 40 + 2 * 128 * 40) * 2 * 2;
    cudaFuncSetAttribute(bf16_gemm<64>,
                         cudaFuncAttributeMaxDynamicSharedMemorySize, SM_BYTES);
    dim3 grid((N + 127) / 128, (M + 63) / 64);
    bf16_gemm<64><<<grid, 256, SM_BYTES>>>(Ah, Al, lda, Bh, Bl, ldb, C, ldc,
        Chi, Clo, ldch, bias, M, N, Kp, relu);
}

extern "C" void kernel_launch(void* const* d_in, const int* in_sizes, int n_in,
                              void* d_out, int out_size) {
    const float* x      = (const float*)d_in[0];
    const void*  ei     = d_in[1];
    const float* W_rna  = (const float*)d_in[2];
    const float* b_rna  = (const float*)d_in[3];
    const float* W_prot = (const float*)d_in[4];
    const float* b_prot = (const float*)d_in[5];
    const float* c1_Ws  = (const float*)d_in[6];
    const float* c1_Wd  = (const float*)d_in[7];
    const float* c1_as  = (const float*)d_in[8];
    const float* c1_ad  = (const float*)d_in[9];
    const float* c1_b   = (const float*)d_in[10];
    const float* l1_W   = (const float*)d_in[11];
    const float* l1_b   = (const float*)d_in[12];
    const float* ln_g   = (const float*)d_in[13];
    const float* ln_b   = (const float*)d_in[14];
    const float* c2_Ws  = (const float*)d_in[15];
    const float* c2_Wd  = (const float*)d_in[16];
    const float* c2_as  = (const float*)d_in[17];
    const float* c2_ad  = (const float*)d_in[18];
    const float* c2_b   = (const float*)d_in[19];
    const float* l2_W   = (const float*)d_in[20];
    const float* l2_b   = (const float*)d_in[21];
    const float* agg_W  = (const float*)d_in[22];
    const float* agg_b  = (const float*)d_in[23];
    const float* dr_W   = (const float*)d_in[24];
    const float* dr_b   = (const float*)d_in[25];
    const float* dp_W   = (const float*)d_in[26];
    const float* dp_b   = (const float*)d_in[27];
    const float* rr_W   = (const float*)d_in[28];
    const float* rr_b   = (const float*)d_in[29];
    const float* rp_W   = (const float*)d_in[30];
    const float* rp_b   = (const float*)d_in[31];

    float* out = (float*)d_out;
    float* out_rna  = out;
    float* out_prot = out + (size_t)NN * RNAD;
    float* out_emb  = out + (size_t)NN * (RNAD + PROTD);

    float *big, *gat, *as_, *ad_, *alpha, *bias1, *bias2b, *biasT;
    int *srcI, *dstI, *cnt, *starts, *fill, *eid;
    __nv_bfloat16 *xh, *xl, *xinh, *xinl, *hh, *hl, *embh, *embl, *th, *tl, *wh, *wl;
    cudaGetSymbolAddress((void**)&big,   g_big);
    cudaGetSymbolAddress((void**)&gat,   g_gat);
    cudaGetSymbolAddress((void**)&as_,   g_as);
    cudaGetSymbolAddress((void**)&ad_,   g_ad);
    cudaGetSymbolAddress((void**)&alpha, g_alpha);
    cudaGetSymbolAddress((void**)&srcI,  g_src);
    cudaGetSymbolAddress((void**)&dstI,  g_dst);
    cudaGetSymbolAddress((void**)&cnt,   g_cnt);
    cudaGetSymbolAddress((void**)&starts,g_starts);
    cudaGetSymbolAddress((void**)&fill,  g_fill);
    cudaGetSymbolAddress((void**)&eid,   g_eid);
    cudaGetSymbolAddress((void**)&bias1, g_bias1);
    cudaGetSymbolAddress((void**)&bias2b,g_bias2);
    cudaGetSymbolAddress((void**)&biasT, g_biasT);
    cudaGetSymbolAddress((void**)&xh,    g_xh);
    cudaGetSymbolAddress((void**)&xl,    g_xl);
    cudaGetSymbolAddress((void**)&xinh,  g_xinh);
    cudaGetSymbolAddress((void**)&xinl,  g_xinl);
    cudaGetSymbolAddress((void**)&hh,    g_hh);
    cudaGetSymbolAddress((void**)&hl,    g_hl);
    cudaGetSymbolAddress((void**)&embh,  g_embh);
    cudaGetSymbolAddress((void**)&embl,  g_embl);
    cudaGetSymbolAddress((void**)&th,    g_th);
    cudaGetSymbolAddress((void**)&tl,    g_tl);
    cudaGetSymbolAddress((void**)&wh,    g_wh);
    cudaGetSymbolAddress((void**)&wl,    g_wl);

    const int EB = 256;

    // ---- decode edges + CSR -------------------------------------------------
    detect_fmt<<<1, 32>>>((const unsigned*)ei);
    decode_idx<<<(2 * EE + EB - 1) / EB, EB>>>(ei, srcI, dstI);
    zero_u32<<<40, 256>>>((unsigned*)cnt, NN);
    csr_hist<<<(EE + EB - 1) / EB, EB>>>(dstI, cnt);
    csr_scan<<<1, 1024>>>(cnt, starts, fill);
    csr_fill<<<(EE + EB - 1) / EB, EB>>>(dstI, fill, eid);

    // ---- preprocessing -------------------------------------------------------
    split_x4<<<(NN * (XPAD / 4) + 255) / 256, 256>>>(x, xh, xl);
    const WSpec ws[13] = {
        {OFF_WRNA,  RNAD, EMBD, KRNA},  {OFF_WPROT, PROTD, EMBD, KPROT},
        {OFF_C1WS,  DIN,  DMID, DIN},   {OFF_C1WD,  DIN,  DMID, DIN},
        {OFF_L1W,   DIN,  DMID, DIN},
        {OFF_C2WS,  DMID, DMID, DMID},  {OFF_C2WD,  DMID, DMID, DMID},
        {OFF_L2W,   DMID, DMID, DMID},
        {OFF_AGG,   DMID, EMBD, DMID},
        {OFF_DR,    EMBD, EMBD, EMBD},  {OFF_DP,    EMBD, EMBD, EMBD},
        {OFF_RR,    EMBD, RNAD, EMBD},  {OFF_RP,    EMBD, PROTD, EMBD},
    };
    const float* wp[13] = {W_rna, W_prot, c1_Ws, c1_Wd, l1_W, c2_Ws, c2_Wd, l2_W,
                           agg_W, dr_W, dp_W, rr_W, rp_W};
    for (int i = 0; i < 13; i++) {
        dim3 tgrid((ws[i].Kp + 31) / 32, (ws[i].N + 31) / 32);
        split_w_t<<<tgrid, dim3(32, 8)>>>(wp[i], ws[i].K, ws[i].N, ws[i].Kp,
                                          wh + ws[i].off, wl + ws[i].off);
    }
    bias3<<<6, 256>>>(l1_b, bias1);
    bias3<<<6, 256>>>(l2_b, bias2b);
    bias2<<<1, 256>>>(dr_b, dp_b, biasT);

    // ---- input embeddings -> xin hi/lo ---------------------------------------
    gemm64(xh, xl, XPAD, wh + OFF_WRNA, wl + OFF_WRNA, KRNA,
           nullptr, 0, xinh, xinl, DIN, b_rna, NN, EMBD, KRNA, 0);
    gemm64(xh + KRNA, xl + KRNA, XPAD, wh + OFF_WPROT, wl + OFF_WPROT, KPROT,
           nullptr, 0, xinh + EMBD, xinl + EMBD, DIN, b_prot, NN, EMBD, KPROT, 0);

    // ================= Block 1: fused xs|xd|lin ============================
    gemm128(xinh, xinl, DIN, wh + OFF_C1WS, wl + OFF_C1WS, DIN,
            big, BIGW, nullptr, nullptr, 0, bias1, NN, BIGW, DIN, 0);
    att_scores<<<NN, 128>>>(big, big + 512, BIGW, c1_as, c1_ad, as_, ad_);
    gat_aggregate<<<NN, 128>>>(starts, eid, srcI, as_, ad_, big, BIGW, alpha, gat);
    resid_ln_relu<<<NN, 256>>>(gat, c1_b, big + 1024, BIGW, ln_g, ln_b, hh, hl);

    // ================= Block 2: fused xs|xd|lin ============================
    gemm128(hh, hl, DMID, wh + OFF_C2WS, wl + OFF_C2WS, DMID,
            big, BIGW, nullptr, nullptr, 0, bias2b, NN, BIGW, DMID, 0);
    att_scores<<<NN, 128>>>(big, big + 512, BIGW, c2_as, c2_ad, as_, ad_);
    gat_aggregate<<<NN, 128>>>(starts, eid, srcI, as_, ad_, big, BIGW, alpha, gat);
    resid_add<<<512, 256>>>(gat, c2_b, big + 1024, BIGW, hh, hl);

    // ================= Heads ===============================================
    gemm64(hh, hl, DMID, wh + OFF_AGG, wl + OFF_AGG, DMID,
           out_emb, EMBD, embh, embl, EMBD, agg_b, NN, EMBD, DMID, 1);

    gemm64(embh, embl, EMBD, wh + OFF_DR, wl + OFF_DR, EMBD,
           nullptr, 0, th, tl, 256, biasT, NN, 256, EMBD, 0);

    gemm128(th, tl, 256, wh + OFF_RR, wl + OFF_RR, EMBD,
            out_rna, RNAD, nullptr, nullptr, 0, rr_b, NN, RNAD, EMBD, 0);
    gemm64(th + 128, tl + 128, 256, wh + OFF_RP, wl + OFF_RP, EMBD,
           out_prot, PROTD, nullptr, nullptr, 0, rp_b, NN, PROTD, EMBD, 0);
}

// round 13
// speedup vs baseline: 1.1273x; 1.0033x over previous
#include <cuda_runtime.h>
#include <cuda_bf16.h>
#include <cstdint>

#define NN   10000
#define EE   160000
#define RNAD 2000
#define PROTD 100
#define EMBD 128
#define HIDD 128
#define NH   4
#define DIN  256
#define DMID 512
#define BIGW 1536

#define KRNA  2016
#define KPROT 128
#define XPAD  (KRNA + KPROT)

// ---------------- scratch (static device globals) --------------------------
__device__ float          g_big[NN * BIGW];
__device__ float          g_gat[NN * DMID];
__device__ float          g_as [NN * NH];
__device__ float          g_ad [NN * NH];
__device__ float          g_alpha[EE * NH];     // planar: [h][i]
__device__ int            g_src[EE];
__device__ int            g_dst[EE];
__device__ int            g_is64;
__device__ int            g_cnt[NN];
__device__ int            g_starts[NN + 1];
__device__ int            g_fill[NN];
__device__ int            g_eid[EE];
__device__ float          g_bias1[BIGW];
__device__ float          g_bias2[BIGW];
__device__ float          g_biasT[256];

__device__ __nv_bfloat16  g_xh [NN * XPAD];
__device__ __nv_bfloat16  g_xl [NN * XPAD];
__device__ __nv_bfloat16  g_xinh[NN * DIN];
__device__ __nv_bfloat16  g_xinl[NN * DIN];
__device__ __nv_bfloat16  g_hh [NN * DMID];
__device__ __nv_bfloat16  g_hl [NN * DMID];
__device__ __nv_bfloat16  g_embh[NN * EMBD];
__device__ __nv_bfloat16  g_embl[NN * EMBD];
__device__ __nv_bfloat16  g_th [NN * 256];
__device__ __nv_bfloat16  g_tl [NN * 256];

// weight arena (K-major, padded)
#define OFF_WRNA  0
#define OFF_WPROT 258048
#define OFF_C1WS  274432
#define OFF_C1WD  405504
#define OFF_L1W   536576
#define OFF_C2WS  667648
#define OFF_C2WD  929792
#define OFF_L2W   1191936
#define OFF_AGG   1454080
#define OFF_DR    1519616
#define OFF_DP    1536000
#define OFF_RR    1552384
#define OFF_RP    1808384
#define WARENA    1821184
__device__ __nv_bfloat16 g_wh[WARENA];
__device__ __nv_bfloat16 g_wl[WARENA];

// ---------------- helpers ---------------------------------------------------
__device__ __forceinline__ void bsplit(float v, __nv_bfloat16& h, __nv_bfloat16& l) {
    h = __float2bfloat16(v);
    l = __float2bfloat16(v - __bfloat162float(h));
}
__device__ __forceinline__ void cpa16(uint32_t dst, const void* src, int sz) {
    asm volatile("cp.async.ca.shared.global [%0], [%1], 16, %2;\n"
                 :: "r"(dst), "l"(src), "r"(sz));
}
__device__ __forceinline__ void mma_bf16(float* c, uint32_t a0, uint32_t a1,
                                         uint32_t a2, uint32_t a3,
                                         uint32_t b0, uint32_t b1) {
    asm volatile(
        "mma.sync.aligned.m16n8k16.row.col.f32.bf16.bf16.f32 "
        "{%0,%1,%2,%3}, {%4,%5,%6,%7}, {%8,%9}, {%0,%1,%2,%3};"
        : "+f"(c[0]), "+f"(c[1]), "+f"(c[2]), "+f"(c[3])
        : "r"(a0), "r"(a1), "r"(a2), "r"(a3), "r"(b0), "r"(b1));
}
#define LDMX4(r0, r1, r2, r3, addr) \
    asm volatile("ldmatrix.sync.aligned.m8n8.x4.shared.b16 {%0,%1,%2,%3}, [%4];" \
                 : "=r"(r0), "=r"(r1), "=r"(r2), "=r"(r3) : "r"(addr))

// ---------------- edge-index dtype detect + decode -------------------------
__global__ void detect_fmt(const unsigned* __restrict__ w) {
    if (threadIdx.x == 0 && blockIdx.x == 0) {
        unsigned acc = 0;
        for (int i = 1; i < 4096; i += 2) acc |= w[i];
        g_is64 = (acc == 0u) ? 1 : 0;
    }
}
__global__ void decode_idx(const void* __restrict__ ei,
                           int* __restrict__ src, int* __restrict__ dst) {
    int i = blockIdx.x * blockDim.x + threadIdx.x;
    if (i >= 2 * EE) return;
    long long v;
    if (g_is64) v = ((const long long*)ei)[i];
    else        v = (long long)((const int*)ei)[i];
    int vi = (int)v;
    vi = vi < 0 ? 0 : (vi >= NN ? NN - 1 : vi);
    if (i < EE) src[i] = vi;
    else        dst[i - EE] = vi;
}
__global__ void zero_u32(unsigned* p, int n) {
    int i = blockIdx.x * blockDim.x + threadIdx.x;
    int stride = gridDim.x * blockDim.x;
    for (; i < n; i += stride) p[i] = 0u;
}

// ---------------- CSR build --------------------------------------------------
__global__ void csr_hist(const int* __restrict__ dst, int* __restrict__ cnt) {
    int e = blockIdx.x * blockDim.x + threadIdx.x;
    if (e < EE) atomicAdd(&cnt[dst[e]], 1);
}
#define SCAN_CHUNK 10
__global__ void csr_scan(const int* __restrict__ cnt,
                         int* __restrict__ starts, int* __restrict__ fill) {
    __shared__ int wsum[32];
    int t = threadIdx.x;
    int lane = t & 31, w = t >> 5;
    int base = t * SCAN_CHUNK;
    int loc[SCAN_CHUNK];
    int s = 0;
    #pragma unroll
    for (int j = 0; j < SCAN_CHUNK; j++) {
        int idx = base + j;
        int v = (idx < NN) ? cnt[idx] : 0;
        loc[j] = s; s += v;
    }
    int si = s;
    #pragma unroll
    for (int o = 1; o < 32; o <<= 1) {
        int v = __shfl_up_sync(0xffffffffu, si, o);
        if (lane >= o) si += v;
    }
    if (lane == 31) wsum[w] = si;
    __syncthreads();
    if (w == 0) {
        int v = wsum[lane];
        int vi = v;
        #pragma unroll
        for (int o = 1; o < 32; o <<= 1) {
            int u = __shfl_up_sync(0xffffffffu, vi, o);
            if (lane >= o) vi += u;
        }
        wsum[lane] = vi - v;
    }
    __syncthreads();
    int off = wsum[w] + (si - s);
    #pragma unroll
    for (int j = 0; j < SCAN_CHUNK; j++) {
        int idx = base + j;
        if (idx < NN) {
            int st = off + loc[j];
            starts[idx] = st;
            fill[idx] = st;
        }
    }
    if (t == 1023) starts[NN] = off + s;
}
__global__ void csr_fill(const int* __restrict__ dst,
                         int* __restrict__ fill, int* __restrict__ eid) {
    int e = blockIdx.x * blockDim.x + threadIdx.x;
    if (e < EE) {
        int p = atomicAdd(&fill[dst[e]], 1);
        eid[p] = e;
    }
}

// ---------------- preprocessing ----------------------------------------------
__global__ void split_x4(const float* __restrict__ x,
                         __nv_bfloat16* __restrict__ hi, __nv_bfloat16* __restrict__ lo) {
    int i4 = blockIdx.x * blockDim.x + threadIdx.x;
    if (i4 >= NN * (XPAD / 4)) return;
    int r = i4 / (XPAD / 4);
    int c = (i4 % (XPAD / 4)) * 4;
    float4 v = make_float4(0.f, 0.f, 0.f, 0.f);
    if (c < RNAD)
        v = *(const float4*)(x + (size_t)r * (RNAD + PROTD) + c);
    else if (c >= KRNA && c < KRNA + PROTD)
        v = *(const float4*)(x + (size_t)r * (RNAD + PROTD) + RNAD + (c - KRNA));
    __nv_bfloat16 h0, l0, h1, l1, h2, l2, h3, l3;
    bsplit(v.x, h0, l0); bsplit(v.y, h1, l1);
    bsplit(v.z, h2, l2); bsplit(v.w, h3, l3);
    uint2 hv, lv;
    hv.x = (uint32_t)__bfloat16_as_ushort(h0) | ((uint32_t)__bfloat16_as_ushort(h1) << 16);
    hv.y = (uint32_t)__bfloat16_as_ushort(h2) | ((uint32_t)__bfloat16_as_ushort(h3) << 16);
    lv.x = (uint32_t)__bfloat16_as_ushort(l0) | ((uint32_t)__bfloat16_as_ushort(l1) << 16);
    lv.y = (uint32_t)__bfloat16_as_ushort(l2) | ((uint32_t)__bfloat16_as_ushort(l3) << 16);
    *(uint2*)(hi + (size_t)i4 * 4) = hv;
    *(uint2*)(lo + (size_t)i4 * 4) = lv;
}

__global__ void split_w_t(const float* __restrict__ W, int K, int N, int Kp,
                          __nv_bfloat16* __restrict__ hi, __nv_bfloat16* __restrict__ lo) {
    __shared__ float tile[32][33];
    int k0 = blockIdx.x * 32;
    int n0 = blockIdx.y * 32;
    int tx = threadIdx.x, ty = threadIdx.y;      // 32 x 8
    #pragma unroll
    for (int i = 0; i < 4; i++) {
        int k = k0 + ty + i * 8;
        int n = n0 + tx;
        tile[ty + i * 8][tx] = (k < K && n < N) ? W[(size_t)k * N + n] : 0.f;
    }
    __syncthreads();
    #pragma unroll
    for (int i = 0; i < 4; i++) {
        int n = n0 + ty + i * 8;
        int k = k0 + tx;
        if (n < N && k < Kp) {
            float v = tile[tx][ty + i * 8];
            __nv_bfloat16 h, l; bsplit(v, h, l);
            hi[(size_t)n * Kp + k] = h;
            lo[(size_t)n * Kp + k] = l;
        }
    }
}

__global__ void bias3(const float* __restrict__ lb, float* __restrict__ o) {
    int i = blockIdx.x * blockDim.x + threadIdx.x;
    if (i < BIGW) o[i] = (i < 1024) ? 0.f : lb[i - 1024];
}
__global__ void bias2(const float* __restrict__ a, const float* __restrict__ b,
                      float* __restrict__ o) {
    int i = threadIdx.x;
    if (i < 256) o[i] = (i < 128) ? a[i] : b[i - 128];
}

// ============================================================================
// bf16 tensor-core GEMM, pre-split operands, ldmatrix fragment loads (R8).
// ============================================================================
template<int BM>
__global__ void __launch_bounds__(256, 2)
bf16_gemm(const __nv_bfloat16* __restrict__ Ah, const __nv_bfloat16* __restrict__ Al, int lda,
          const __nv_bfloat16* __restrict__ Bh, const __nv_bfloat16* __restrict__ Bl, int ldb,
          float* __restrict__ C, int ldc,
          __nv_bfloat16* __restrict__ Chi, __nv_bfloat16* __restrict__ Clo, int ldch,
          const float* __restrict__ bias,
          int M, int N, int Kp, int relu) {
    constexpr int NI  = BM / 32;
    constexpr int AT  = BM * 40;
    constexpr int BT  = 128 * 40;
    constexpr int STG = 2 * AT + 2 * BT;
    extern __shared__ uint16_t sm[];

    const int tid   = threadIdx.x;
    const int lane  = tid & 31;
    const int warp  = tid >> 5;
    const int wr    = warp >> 2;
    const int wc    = warp & 3;
    const int group = lane >> 2;
    const int tig   = lane & 3;
    const int blockRow = blockIdx.y * BM;
    const int blockCol = blockIdx.x * 128;
    const int NC = Kp >> 5;

    const uint32_t smb = (uint32_t)__cvta_generic_to_shared(sm);
    const int aRow = lane & 15,  aCol = (lane >> 4) << 3;
    const int bRow = ((lane >> 4) << 3) + (lane & 7), bCol = ((lane >> 3) & 1) << 3;

    auto loadStage = [&](int c, int s) {
        uint16_t* base = sm + s * STG;
        int k0 = c << 5;
        for (int i = tid; i < BM * 4; i += 256) {
            int r = i >> 2, ch = i & 3;
            int gr = blockRow + r;
            int sz = (gr < M) ? 16 : 0;
            const __nv_bfloat16* ph = sz ? (Ah + (size_t)gr * lda + k0 + ch * 8) : Ah;
            const __nv_bfloat16* pl = sz ? (Al + (size_t)gr * lda + k0 + ch * 8) : Al;
            cpa16((uint32_t)__cvta_generic_to_shared(base + r * 40 + ch * 8), ph, sz);
            cpa16((uint32_t)__cvta_generic_to_shared(base + AT + r * 40 + ch * 8), pl, sz);
        }
        uint16_t* bb = base + 2 * AT;
        for (int i = tid; i < 128 * 4; i += 256) {
            int r = i >> 2, ch = i & 3;
            int gn = blockCol + r;
            int sz = (gn < N) ? 16 : 0;
            const __nv_bfloat16* ph = sz ? (Bh + (size_t)gn * ldb + k0 + ch * 8) : Bh;
            const __nv_bfloat16* pl = sz ? (Bl + (size_t)gn * ldb + k0 + ch * 8) : Bl;
            cpa16((uint32_t)__cvta_generic_to_shared(bb + r * 40 + ch * 8), ph, sz);
            cpa16((uint32_t)__cvta_generic_to_shared(bb + BT + r * 40 + ch * 8), pl, sz);
        }
        asm volatile("cp.async.commit_group;\n");
    };

    float acc[NI][4][4];
    #pragma unroll
    for (int i = 0; i < NI; i++)
        #pragma unroll
        for (int j = 0; j < 4; j++) {
            acc[i][j][0] = 0.f; acc[i][j][1] = 0.f;
            acc[i][j][2] = 0.f; acc[i][j][3] = 0.f;
        }

    loadStage(0, 0);

    for (int c = 0; c < NC; c++) {
        if (c + 1 < NC) {
            loadStage(c + 1, (c + 1) & 1);
            asm volatile("cp.async.wait_group 1;\n" ::: "memory");
        } else {
            asm volatile("cp.async.wait_group 0;\n" ::: "memory");
        }
        __syncthreads();

        const uint32_t stB = smb + (uint32_t)((c & 1) * STG) * 2;
        const uint32_t uAh = stB;
        const uint32_t uAl = stB + AT * 2;
        const uint32_t uBh = stB + 2 * AT * 2;
        const uint32_t uBl = stB + (2 * AT + BT) * 2;

        #pragma unroll
        for (int ks = 0; ks < 2; ks++) {
            const int kb = ks * 16;
            uint32_t bh[4][2], bl[4][2];
            #pragma unroll
            for (int p = 0; p < 2; p++) {
                int n = wc * 32 + p * 16 + bRow;
                uint32_t off = (uint32_t)(n * 40 + kb + bCol) * 2;
                LDMX4(bh[2*p][0], bh[2*p][1], bh[2*p+1][0], bh[2*p+1][1], uBh + off);
                LDMX4(bl[2*p][0], bl[2*p][1], bl[2*p+1][0], bl[2*p+1][1], uBl + off);
            }
            #pragma unroll
            for (int i = 0; i < NI; i++) {
                int r = wr * (BM / 2) + i * 16 + aRow;
                uint32_t off = (uint32_t)(r * 40 + kb + aCol) * 2;
                uint32_t ah0, ah1, ah2, ah3, al0, al1, al2, al3;
                LDMX4(ah0, ah1, ah2, ah3, uAh + off);
                LDMX4(al0, al1, al2, al3, uAl + off);
                #pragma unroll
                for (int j = 0; j < 4; j++) {
                    mma_bf16(acc[i][j], ah0, ah1, ah2, ah3, bh[j][0], bh[j][1]);
                    mma_bf16(acc[i][j], al0, al1, al2, al3, bh[j][0], bh[j][1]);
                    mma_bf16(acc[i][j], ah0, ah1, ah2, ah3, bl[j][0], bl[j][1]);
                }
            }
        }
        __syncthreads();
    }

    #pragma unroll
    for (int i = 0; i < NI; i++) {
        int r0 = blockRow + wr * (BM / 2) + i * 16 + group;
        int r1 = r0 + 8;
        #pragma unroll
        for (int j = 0; j < 4; j++) {
            int gc = blockCol + wc * 32 + j * 8 + tig * 2;
            if (gc >= N) continue;
            float bi0 = bias ? bias[gc] : 0.f;
            float bi1 = bias ? bias[gc + 1] : 0.f;
            float v0 = acc[i][j][0] + bi0, v1 = acc[i][j][1] + bi1;
            float v2 = acc[i][j][2] + bi0, v3 = acc[i][j][3] + bi1;
            if (relu) {
                v0 = fmaxf(v0, 0.f); v1 = fmaxf(v1, 0.f);
                v2 = fmaxf(v2, 0.f); v3 = fmaxf(v3, 0.f);
            }
            if (r0 < M) {
                if (C) *(float2*)(C + (size_t)r0 * ldc + gc) = make_float2(v0, v1);
                if (Chi) {
                    __nv_bfloat16 h0, l0, h1, l1;
                    bsplit(v0, h0, l0); bsplit(v1, h1, l1);
                    Chi[(size_t)r0 * ldch + gc] = h0; Chi[(size_t)r0 * ldch + gc + 1] = h1;
                    Clo[(size_t)r0 * ldch + gc] = l0; Clo[(size_t)r0 * ldch + gc + 1] = l1;
                }
            }
            if (r1 < M) {
                if (C) *(float2*)(C + (size_t)r1 * ldc + gc) = make_float2(v2, v3);
                if (Chi) {
                    __nv_bfloat16 h2, l2, h3, l3;
                    bsplit(v2, h2, l2); bsplit(v3, h3, l3);
                    Chi[(size_t)r1 * ldch + gc] = h2; Chi[(size_t)r1 * ldch + gc + 1] = h3;
                    Clo[(size_t)r1 * ldch + gc] = l2; Clo[(size_t)r1 * ldch + gc + 1] = l3;
                }
            }
        }
    }
}

// ---------------- GAT: attention scores (strided xs/xd) --------------------
__global__ void att_scores(const float* __restrict__ xs, const float* __restrict__ xd,
                           int S,
                           const float* __restrict__ att_s, const float* __restrict__ att_d,
                           float* __restrict__ a_s, float* __restrict__ a_d) {
    int n = blockIdx.x;
    int w = threadIdx.x >> 5;
    int lane = threadIdx.x & 31;
    size_t base = (size_t)n * S + w * HIDD;
    float s = 0.f, d = 0.f;
    #pragma unroll
    for (int c = lane; c < HIDD; c += 32) {
        s += xs[base + c] * att_s[w * HIDD + c];
        d += xd[base + c] * att_d[w * HIDD + c];
    }
    #pragma unroll
    for (int o = 16; o > 0; o >>= 1) {
        s += __shfl_down_sync(0xffffffffu, s, o);
        d += __shfl_down_sync(0xffffffffu, d, o);
    }
    if (lane == 0) { a_s[n * NH + w] = s; a_d[n * NH + w] = d; }
}

// ---------------- GAT aggregation (planar alpha, unroll x2) -----------------
__global__ void __launch_bounds__(128)
gat_aggregate(const int* __restrict__ starts, const int* __restrict__ eid,
              const int* __restrict__ src,
              const float* __restrict__ a_s, const float* __restrict__ a_d,
              const float* __restrict__ xs, int S,
              float* __restrict__ alpha, float* __restrict__ gat) {
    int n = blockIdx.x;
    int h = threadIdx.x >> 5;
    int lane = threadIdx.x & 31;
    int beg = starts[n], end = starts[n + 1];

    float adn = a_d[n * NH + h];
    float* alphaH = alpha + (size_t)h * EE;    // planar per-head slab

    // pass 1: alpha + warp max (lane-strided; coalesced planar writes)
    float mx = -3.4e38f;
    for (int i = beg + lane; i < end; i += 32) {
        int e = eid[i];
        float a = a_s[src[e] * NH + h] + adn;
        a = a > 0.f ? a : 0.2f * a;
        alphaH[i] = a;
        mx = fmaxf(mx, a);
    }
    #pragma unroll
    for (int o = 16; o > 0; o >>= 1)
        mx = fmaxf(mx, __shfl_xor_sync(0xffffffffu, mx, o));

    // pass 2: unroll x2, independent partials (MLP 2 on the 512B gathers)
    float den0 = 0.f, den1 = 0.f;
    float4 acc0 = make_float4(0.f, 0.f, 0.f, 0.f);
    float4 acc1 = make_float4(0.f, 0.f, 0.f, 0.f);
    const int chOff = h * HIDD + lane * 4;
    int i = beg;
    for (; i + 1 < end; i += 2) {
        int e0 = eid[i], e1 = eid[i + 1];
        float w0 = expf(alphaH[i] - mx);
        float w1 = expf(alphaH[i + 1] - mx);
        const float4 v0 = *(const float4*)(xs + (size_t)src[e0] * S + chOff);
        const float4 v1 = *(const float4*)(xs + (size_t)src[e1] * S + chOff);
        den0 += w0; den1 += w1;
        acc0.x += v0.x * w0; acc0.y += v0.y * w0;
        acc0.z += v0.z * w0; acc0.w += v0.w * w0;
        acc1.x += v1.x * w1; acc1.y += v1.y * w1;
        acc1.z += v1.z * w1; acc1.w += v1.w * w1;
    }
    if (i < end) {
        int e0 = eid[i];
        float w0 = expf(alphaH[i] - mx);
        const float4 v0 = *(const float4*)(xs + (size_t)src[e0] * S + chOff);
        den0 += w0;
        acc0.x += v0.x * w0; acc0.y += v0.y * w0;
        acc0.z += v0.z * w0; acc0.w += v0.w * w0;
    }
    float den = den0 + den1;
    float4 acc = make_float4(acc0.x + acc1.x, acc0.y + acc1.y,
                             acc0.z + acc1.z, acc0.w + acc1.w);
    float inv = 1.f / (den + 1e-16f);
    acc.x *= inv; acc.y *= inv; acc.z *= inv; acc.w *= inv;
    *(float4*)(gat + (size_t)n * DMID + chOff) = acc;
}

// ---------------- residual (+bias) + LayerNorm + ReLU -> bf16 hi/lo --------
__global__ void resid_ln_relu(const float* __restrict__ gat, const float* __restrict__ cb,
                              const float* __restrict__ lin, int linS,
                              const float* __restrict__ g, const float* __restrict__ b,
                              __nv_bfloat16* __restrict__ hh, __nv_bfloat16* __restrict__ hl) {
    int row = blockIdx.x;
    int t = threadIdx.x;
    size_t gb = (size_t)row * DMID;
    size_t lb = (size_t)row * linS;
    float v0 = gat[gb + t]       + cb[t]       + lin[lb + t];
    float v1 = gat[gb + 256 + t] + cb[256 + t] + lin[lb + 256 + t];
    float s = v0 + v1;
    float ss = v0 * v0 + v1 * v1;
    #pragma unroll
    for (int o = 16; o > 0; o >>= 1) {
        s  += __shfl_down_sync(0xffffffffu, s, o);
        ss += __shfl_down_sync(0xffffffffu, ss, o);
    }
    __shared__ float shs[8], shss[8];
    __shared__ float mu_sh, inv_sh;
    int w = t >> 5, lane = t & 31;
    if (lane == 0) { shs[w] = s; shss[w] = ss; }
    __syncthreads();
    if (t == 0) {
        float S = 0.f, SS = 0.f;
        #pragma unroll
        for (int i = 0; i < 8; i++) { S += shs[i]; SS += shss[i]; }
        float mu = S * (1.f / DMID);
        float var = SS * (1.f / DMID) - mu * mu;
        mu_sh = mu;
        inv_sh = rsqrtf(var + 1e-5f);
    }
    __syncthreads();
    float mu = mu_sh, inv = inv_sh;
    float o0 = fmaxf((v0 - mu) * inv * g[t]       + b[t],       0.f);
    float o1 = fmaxf((v1 - mu) * inv * g[256 + t] + b[256 + t], 0.f);
    __nv_bfloat16 h0, l0, h1, l1;
    bsplit(o0, h0, l0); bsplit(o1, h1, l1);
    hh[gb + t] = h0;       hl[gb + t] = l0;
    hh[gb + 256 + t] = h1; hl[gb + 256 + t] = l1;
}

__global__ void resid_add(const float* __restrict__ gat, const float* __restrict__ cb,
                          const float* __restrict__ lin, int linS,
                          __nv_bfloat16* __restrict__ hh, __nv_bfloat16* __restrict__ hl) {
    int i = blockIdx.x * blockDim.x + threadIdx.x;
    int stride = gridDim.x * blockDim.x;
    for (; i < NN * DMID; i += stride) {
        int row = i >> 9, col = i & (DMID - 1);
        float v = gat[i] + cb[col] + lin[(size_t)row * linS + col];
        __nv_bfloat16 h, l; bsplit(v, h, l);
        hh[i] = h; hl[i] = l;
    }
}

// ---------------- host -------------------------------------------------------
struct WSpec { int off, K, N, Kp; };

static void gemm128(const __nv_bfloat16* Ah, const __nv_bfloat16* Al, int lda,
                    const __nv_bfloat16* Bh, const __nv_bfloat16* Bl, int ldb,
                    float* C, int ldc, __nv_bfloat16* Chi, __nv_bfloat16* Clo, int ldch,
                    const float* bias, int M, int N, int Kp, int relu) {
    constexpr int SM_BYTES = (2 * 128 * 40 + 2 * 128 * 40) * 2 * 2;
    cudaFuncSetAttribute(bf16_gemm<128>,
                         cudaFuncAttributeMaxDynamicSharedMemorySize, SM_BYTES);
    dim3 grid((N + 127) / 128, (M + 127) / 128);
    bf16_gemm<128><<<grid, 256, SM_BYTES>>>(Ah, Al, lda, Bh, Bl, ldb, C, ldc,
        Chi, Clo, ldch, bias, M, N, Kp, relu);
}
static void gemm64(const __nv_bfloat16* Ah, const __nv_bfloat16* Al, int lda,
                   const __nv_bfloat16* Bh, const __nv_bfloat16* Bl, int ldb,
                   float* C, int ldc, __nv_bfloat16* Chi, __nv_bfloat16* Clo, int ldch,
                   const float* bias, int M, int N, int Kp, int relu) {
    constexpr int SM_BYTES = (2 * 64 * 40 + 2 * 128 * 40) * 2 * 2;
    cudaFuncSetAttribute(bf16_gemm<64>,
                         cudaFuncAttributeMaxDynamicSharedMemorySize, SM_BYTES);
    dim3 grid((N + 127) / 128, (M + 63) / 64);
    bf16_gemm<64><<<grid, 256, SM_BYTES>>>(Ah, Al, lda, Bh, Bl, ldb, C, ldc,
        Chi, Clo, ldch, bias, M, N, Kp, relu);
}

extern "C" void kernel_launch(void* const* d_in, const int* in_sizes, int n_in,
                              void* d_out, int out_size) {
    const float* x      = (const float*)d_in[0];
    const void*  ei     = d_in[1];
    const float* W_rna  = (const float*)d_in[2];
    const float* b_rna  = (const float*)d_in[3];
    const float* W_prot = (const float*)d_in[4];
    const float* b_prot = (const float*)d_in[5];
    const float* c1_Ws  = (const float*)d_in[6];
    const float* c1_Wd  = (const float*)d_in[7];
    const float* c1_as  = (const float*)d_in[8];
    const float* c1_ad  = (const float*)d_in[9];
    const float* c1_b   = (const float*)d_in[10];
    const float* l1_W   = (const float*)d_in[11];
    const float* l1_b   = (const float*)d_in[12];
    const float* ln_g   = (const float*)d_in[13];
    const float* ln_b   = (const float*)d_in[14];
    const float* c2_Ws  = (const float*)d_in[15];
    const float* c2_Wd  = (const float*)d_in[16];
    const float* c2_as  = (const float*)d_in[17];
    const float* c2_ad  = (const float*)d_in[18];
    const float* c2_b   = (const float*)d_in[19];
    const float* l2_W   = (const float*)d_in[20];
    const float* l2_b   = (const float*)d_in[21];
    const float* agg_W  = (const float*)d_in[22];
    const float* agg_b  = (const float*)d_in[23];
    const float* dr_W   = (const float*)d_in[24];
    const float* dr_b   = (const float*)d_in[25];
    const float* dp_W   = (const float*)d_in[26];
    const float* dp_b   = (const float*)d_in[27];
    const float* rr_W   = (const float*)d_in[28];
    const float* rr_b   = (const float*)d_in[29];
    const float* rp_W   = (const float*)d_in[30];
    const float* rp_b   = (const float*)d_in[31];

    float* out = (float*)d_out;
    float* out_rna  = out;
    float* out_prot = out + (size_t)NN * RNAD;
    float* out_emb  = out + (size_t)NN * (RNAD + PROTD);

    float *big, *gat, *as_, *ad_, *alpha, *bias1, *bias2b, *biasT;
    int *srcI, *dstI, *cnt, *starts, *fill, *eid;
    __nv_bfloat16 *xh, *xl, *xinh, *xinl, *hh, *hl, *embh, *embl, *th, *tl, *wh, *wl;
    cudaGetSymbolAddress((void**)&big,   g_big);
    cudaGetSymbolAddress((void**)&gat,   g_gat);
    cudaGetSymbolAddress((void**)&as_,   g_as);
    cudaGetSymbolAddress((void**)&ad_,   g_ad);
    cudaGetSymbolAddress((void**)&alpha, g_alpha);
    cudaGetSymbolAddress((void**)&srcI,  g_src);
    cudaGetSymbolAddress((void**)&dstI,  g_dst);
    cudaGetSymbolAddress((void**)&cnt,   g_cnt);
    cudaGetSymbolAddress((void**)&starts,g_starts);
    cudaGetSymbolAddress((void**)&fill,  g_fill);
    cudaGetSymbolAddress((void**)&eid,   g_eid);
    cudaGetSymbolAddress((void**)&bias1, g_bias1);
    cudaGetSymbolAddress((void**)&bias2b,g_bias2);
    cudaGetSymbolAddress((void**)&biasT, g_biasT);
    cudaGetSymbolAddress((void**)&xh,    g_xh);
    cudaGetSymbolAddress((void**)&xl,    g_xl);
    cudaGetSymbolAddress((void**)&xinh,  g_xinh);
    cudaGetSymbolAddress((void**)&xinl,  g_xinl);
    cudaGetSymbolAddress((void**)&hh,    g_hh);
    cudaGetSymbolAddress((void**)&hl,    g_hl);
    cudaGetSymbolAddress((void**)&embh,  g_embh);
    cudaGetSymbolAddress((void**)&embl,  g_embl);
    cudaGetSymbolAddress((void**)&th,    g_th);
    cudaGetSymbolAddress((void**)&tl,    g_tl);
    cudaGetSymbolAddress((void**)&wh,    g_wh);
    cudaGetSymbolAddress((void**)&wl,    g_wl);

    const int EB = 256;

    // ---- decode edges + CSR -------------------------------------------------
    detect_fmt<<<1, 32>>>((const unsigned*)ei);
    decode_idx<<<(2 * EE + EB - 1) / EB, EB>>>(ei, srcI, dstI);
    zero_u32<<<40, 256>>>((unsigned*)cnt, NN);
    csr_hist<<<(EE + EB - 1) / EB, EB>>>(dstI, cnt);
    csr_scan<<<1, 1024>>>(cnt, starts, fill);
    csr_fill<<<(EE + EB - 1) / EB, EB>>>(dstI, fill, eid);

    // ---- preprocessing -------------------------------------------------------
    split_x4<<<(NN * (XPAD / 4) + 255) / 256, 256>>>(x, xh, xl);
    const WSpec ws[13] = {
        {OFF_WRNA,  RNAD, EMBD, KRNA},  {OFF_WPROT, PROTD, EMBD, KPROT},
        {OFF_C1WS,  DIN,  DMID, DIN},   {OFF_C1WD,  DIN,  DMID, DIN},
        {OFF_L1W,   DIN,  DMID, DIN},
        {OFF_C2WS,  DMID, DMID, DMID},  {OFF_C2WD,  DMID, DMID, DMID},
        {OFF_L2W,   DMID, DMID, DMID},
        {OFF_AGG,   DMID, EMBD, DMID},
        {OFF_DR,    EMBD, EMBD, EMBD},  {OFF_DP,    EMBD, EMBD, EMBD},
        {OFF_RR,    EMBD, RNAD, EMBD},  {OFF_RP,    EMBD, PROTD, EMBD},
    };
    const float* wp[13] = {W_rna, W_prot, c1_Ws, c1_Wd, l1_W, c2_Ws, c2_Wd, l2_W,
                           agg_W, dr_W, dp_W, rr_W, rp_W};
    for (int i = 0; i < 13; i++) {
        dim3 tgrid((ws[i].Kp + 31) / 32, (ws[i].N + 31) / 32);
        split_w_t<<<tgrid, dim3(32, 8)>>>(wp[i], ws[i].K, ws[i].N, ws[i].Kp,
                                          wh + ws[i].off, wl + ws[i].off);
    }
    bias3<<<6, 256>>>(l1_b, bias1);
    bias3<<<6, 256>>>(l2_b, bias2b);
    bias2<<<1, 256>>>(dr_b, dp_b, biasT);

    // ---- input embeddings -> xin hi/lo ---------------------------------------
    gemm64(xh, xl, XPAD, wh + OFF_WRNA, wl + OFF_WRNA, KRNA,
           nullptr, 0, xinh, xinl, DIN, b_rna, NN, EMBD, KRNA, 0);
    gemm64(xh + KRNA, xl + KRNA, XPAD, wh + OFF_WPROT, wl + OFF_WPROT, KPROT,
           nullptr, 0, xinh + EMBD, xinl + EMBD, DIN, b_prot, NN, EMBD, KPROT, 0);

    // ================= Block 1: fused xs|xd|lin ============================
    gemm128(xinh, xinl, DIN, wh + OFF_C1WS, wl + OFF_C1WS, DIN,
            big, BIGW, nullptr, nullptr, 0, bias1, NN, BIGW, DIN, 0);
    att_scores<<<NN, 128>>>(big, big + 512, BIGW, c1_as, c1_ad, as_, ad_);
    gat_aggregate<<<NN, 128>>>(starts, eid, srcI, as_, ad_, big, BIGW, alpha, gat);
    resid_ln_relu<<<NN, 256>>>(gat, c1_b, big + 1024, BIGW, ln_g, ln_b, hh, hl);

    // ================= Block 2: fused xs|xd|lin ============================
    gemm128(hh, hl, DMID, wh + OFF_C2WS, wl + OFF_C2WS, DMID,
            big, BIGW, nullptr, nullptr, 0, bias2b, NN, BIGW, DMID, 0);
    att_scores<<<NN, 128>>>(big, big + 512, BIGW, c2_as, c2_ad, as_, ad_);
    gat_aggregate<<<NN, 128>>>(starts, eid, srcI, as_, ad_, big, BIGW, alpha, gat);
    resid_add<<<512, 256>>>(gat, c2_b, big + 1024, BIGW, hh, hl);

    // ================= Heads ===============================================
    gemm64(hh, hl, DMID, wh + OFF_AGG, wl + OFF_AGG, DMID,
           out_emb, EMBD, embh, embl, EMBD, agg_b, NN, EMBD, DMID, 1);

    gemm64(embh, embl, EMBD, wh + OFF_DR, wl + OFF_DR, EMBD,
           nullptr, 0, th, tl, 256, biasT, NN, 256, EMBD, 0);

    gemm128(th, tl, 256, wh + OFF_RR, wl + OFF_RR, EMBD,
            out_rna, RNAD, nullptr, nullptr, 0, rr_b, NN, RNAD, EMBD, 0);
    gemm64(th + 128, tl + 128, 256, wh + OFF_RP, wl + OFF_RP, EMBD,
           out_prot, PROTD, nullptr, nullptr, 0, rp_b, NN, PROTD, EMBD, 0);
}

// round 14
// speedup vs baseline: 1.1315x; 1.0037x over previous
#include <cuda_runtime.h>
#include <cuda_bf16.h>
#include <cstdint>

#define NN   10000
#define EE   160000
#define RNAD 2000
#define PROTD 100
#define EMBD 128
#define HIDD 128
#define NH   4
#define DIN  256
#define DMID 512
#define BIGW 1536

#define KRNA  2016
#define KPROT 128
#define XPAD  (KRNA + KPROT)

// ---------------- scratch (static device globals) --------------------------
__device__ float          g_big[NN * BIGW];
__device__ float          g_gat[NN * DMID];
__device__ float          g_as [NN * NH];
__device__ float          g_ad [NN * NH];
__device__ float          g_alpha[EE * NH];     // planar: [h][i]
__device__ int            g_src[EE];
__device__ int            g_dst[EE];
__device__ int            g_is64;
__device__ int            g_cnt[NN];
__device__ int            g_starts[NN + 1];
__device__ int            g_fill[NN];
__device__ int            g_eid[EE];
__device__ float          g_bias1[BIGW];
__device__ float          g_bias2[BIGW];
__device__ float          g_biasT[256];

__device__ __nv_bfloat16  g_xh [NN * XPAD];
__device__ __nv_bfloat16  g_xl [NN * XPAD];
__device__ __nv_bfloat16  g_xinh[NN * DIN];
__device__ __nv_bfloat16  g_xinl[NN * DIN];
__device__ __nv_bfloat16  g_hh [NN * DMID];
__device__ __nv_bfloat16  g_hl [NN * DMID];
__device__ __nv_bfloat16  g_embh[NN * EMBD];
__device__ __nv_bfloat16  g_embl[NN * EMBD];
__device__ __nv_bfloat16  g_th [NN * 256];
__device__ __nv_bfloat16  g_tl [NN * 256];

// weight arena (K-major, padded)
#define OFF_WRNA  0
#define OFF_WPROT 258048
#define OFF_C1WS  274432
#define OFF_C1WD  405504
#define OFF_L1W   536576
#define OFF_C2WS  667648
#define OFF_C2WD  929792
#define OFF_L2W   1191936
#define OFF_AGG   1454080
#define OFF_DR    1519616
#define OFF_DP    1536000
#define OFF_RR    1552384
#define OFF_RP    1808384
#define WARENA    1821184
__device__ __nv_bfloat16 g_wh[WARENA];
__device__ __nv_bfloat16 g_wl[WARENA];

// ---------------- helpers ---------------------------------------------------
__device__ __forceinline__ void bsplit(float v, __nv_bfloat16& h, __nv_bfloat16& l) {
    h = __float2bfloat16(v);
    l = __float2bfloat16(v - __bfloat162float(h));
}
__device__ __forceinline__ void cpa16(uint32_t dst, const void* src, int sz) {
    asm volatile("cp.async.ca.shared.global [%0], [%1], 16, %2;\n"
                 :: "r"(dst), "l"(src), "r"(sz));
}
__device__ __forceinline__ void mma_bf16(float* c, uint32_t a0, uint32_t a1,
                                         uint32_t a2, uint32_t a3,
                                         uint32_t b0, uint32_t b1) {
    asm volatile(
        "mma.sync.aligned.m16n8k16.row.col.f32.bf16.bf16.f32 "
        "{%0,%1,%2,%3}, {%4,%5,%6,%7}, {%8,%9}, {%0,%1,%2,%3};"
        : "+f"(c[0]), "+f"(c[1]), "+f"(c[2]), "+f"(c[3])
        : "r"(a0), "r"(a1), "r"(a2), "r"(a3), "r"(b0), "r"(b1));
}
#define LDMX4(r0, r1, r2, r3, addr) \
    asm volatile("ldmatrix.sync.aligned.m8n8.x4.shared.b16 {%0,%1,%2,%3}, [%4];" \
                 : "=r"(r0), "=r"(r1), "=r"(r2), "=r"(r3) : "r"(addr))

// ---------------- edge-index dtype detect + decode -------------------------
__global__ void detect_fmt(const unsigned* __restrict__ w) {
    if (threadIdx.x == 0 && blockIdx.x == 0) {
        unsigned acc = 0;
        for (int i = 1; i < 4096; i += 2) acc |= w[i];
        g_is64 = (acc == 0u) ? 1 : 0;
    }
}
__global__ void decode_idx(const void* __restrict__ ei,
                           int* __restrict__ src, int* __restrict__ dst) {
    int i = blockIdx.x * blockDim.x + threadIdx.x;
    if (i >= 2 * EE) return;
    long long v;
    if (g_is64) v = ((const long long*)ei)[i];
    else        v = (long long)((const int*)ei)[i];
    int vi = (int)v;
    vi = vi < 0 ? 0 : (vi >= NN ? NN - 1 : vi);
    if (i < EE) src[i] = vi;
    else        dst[i - EE] = vi;
}
__global__ void zero_u32(unsigned* p, int n) {
    int i = blockIdx.x * blockDim.x + threadIdx.x;
    int stride = gridDim.x * blockDim.x;
    for (; i < n; i += stride) p[i] = 0u;
}

// ---------------- CSR build --------------------------------------------------
__global__ void csr_hist(const int* __restrict__ dst, int* __restrict__ cnt) {
    int e = blockIdx.x * blockDim.x + threadIdx.x;
    if (e < EE) atomicAdd(&cnt[dst[e]], 1);
}
#define SCAN_CHUNK 10
__global__ void csr_scan(const int* __restrict__ cnt,
                         int* __restrict__ starts, int* __restrict__ fill) {
    __shared__ int wsum[32];
    int t = threadIdx.x;
    int lane = t & 31, w = t >> 5;
    int base = t * SCAN_CHUNK;
    int loc[SCAN_CHUNK];
    int s = 0;
    #pragma unroll
    for (int j = 0; j < SCAN_CHUNK; j++) {
        int idx = base + j;
        int v = (idx < NN) ? cnt[idx] : 0;
        loc[j] = s; s += v;
    }
    int si = s;
    #pragma unroll
    for (int o = 1; o < 32; o <<= 1) {
        int v = __shfl_up_sync(0xffffffffu, si, o);
        if (lane >= o) si += v;
    }
    if (lane == 31) wsum[w] = si;
    __syncthreads();
    if (w == 0) {
        int v = wsum[lane];
        int vi = v;
        #pragma unroll
        for (int o = 1; o < 32; o <<= 1) {
            int u = __shfl_up_sync(0xffffffffu, vi, o);
            if (lane >= o) vi += u;
        }
        wsum[lane] = vi - v;
    }
    __syncthreads();
    int off = wsum[w] + (si - s);
    #pragma unroll
    for (int j = 0; j < SCAN_CHUNK; j++) {
        int idx = base + j;
        if (idx < NN) {
            int st = off + loc[j];
            starts[idx] = st;
            fill[idx] = st;
        }
    }
    if (t == 1023) starts[NN] = off + s;
}
__global__ void csr_fill(const int* __restrict__ dst,
                         int* __restrict__ fill, int* __restrict__ eid) {
    int e = blockIdx.x * blockDim.x + threadIdx.x;
    if (e < EE) {
        int p = atomicAdd(&fill[dst[e]], 1);
        eid[p] = e;
    }
}

// ---------------- preprocessing ----------------------------------------------
__global__ void split_x4(const float* __restrict__ x,
                         __nv_bfloat16* __restrict__ hi, __nv_bfloat16* __restrict__ lo) {
    int i4 = blockIdx.x * blockDim.x + threadIdx.x;
    if (i4 >= NN * (XPAD / 4)) return;
    int r = i4 / (XPAD / 4);
    int c = (i4 % (XPAD / 4)) * 4;
    float4 v = make_float4(0.f, 0.f, 0.f, 0.f);
    if (c < RNAD)
        v = *(const float4*)(x + (size_t)r * (RNAD + PROTD) + c);
    else if (c >= KRNA && c < KRNA + PROTD)
        v = *(const float4*)(x + (size_t)r * (RNAD + PROTD) + RNAD + (c - KRNA));
    __nv_bfloat16 h0, l0, h1, l1, h2, l2, h3, l3;
    bsplit(v.x, h0, l0); bsplit(v.y, h1, l1);
    bsplit(v.z, h2, l2); bsplit(v.w, h3, l3);
    uint2 hv, lv;
    hv.x = (uint32_t)__bfloat16_as_ushort(h0) | ((uint32_t)__bfloat16_as_ushort(h1) << 16);
    hv.y = (uint32_t)__bfloat16_as_ushort(h2) | ((uint32_t)__bfloat16_as_ushort(h3) << 16);
    lv.x = (uint32_t)__bfloat16_as_ushort(l0) | ((uint32_t)__bfloat16_as_ushort(l1) << 16);
    lv.y = (uint32_t)__bfloat16_as_ushort(l2) | ((uint32_t)__bfloat16_as_ushort(l3) << 16);
    *(uint2*)(hi + (size_t)i4 * 4) = hv;
    *(uint2*)(lo + (size_t)i4 * 4) = lv;
}

__global__ void split_w_t(const float* __restrict__ W, int K, int N, int Kp,
                          __nv_bfloat16* __restrict__ hi, __nv_bfloat16* __restrict__ lo) {
    __shared__ float tile[32][33];
    int k0 = blockIdx.x * 32;
    int n0 = blockIdx.y * 32;
    int tx = threadIdx.x, ty = threadIdx.y;      // 32 x 8
    #pragma unroll
    for (int i = 0; i < 4; i++) {
        int k = k0 + ty + i * 8;
        int n = n0 + tx;
        tile[ty + i * 8][tx] = (k < K && n < N) ? W[(size_t)k * N + n] : 0.f;
    }
    __syncthreads();
    #pragma unroll
    for (int i = 0; i < 4; i++) {
        int n = n0 + ty + i * 8;
        int k = k0 + tx;
        if (n < N && k < Kp) {
            float v = tile[tx][ty + i * 8];
            __nv_bfloat16 h, l; bsplit(v, h, l);
            hi[(size_t)n * Kp + k] = h;
            lo[(size_t)n * Kp + k] = l;
        }
    }
}

// fused bias prep: bias1, bias2, biasT in one launch
__global__ void bias_all(const float* __restrict__ l1b, const float* __restrict__ l2b,
                         const float* __restrict__ drb, const float* __restrict__ dpb,
                         float* __restrict__ b1, float* __restrict__ b2,
                         float* __restrict__ bT) {
    int i = blockIdx.x * blockDim.x + threadIdx.x;
    if (i < BIGW) {
        float v1 = (i < 1024) ? 0.f : l1b[i - 1024];
        float v2 = (i < 1024) ? 0.f : l2b[i - 1024];
        b1[i] = v1; b2[i] = v2;
    }
    if (i < 256) bT[i] = (i < 128) ? drb[i] : dpb[i - 128];
}

// ============================================================================
// bf16 tensor-core GEMM, pre-split operands, ldmatrix fragment loads,
// term-major MMA ordering (4 independent accumulator chains per term).
// ============================================================================
template<int BM>
__global__ void __launch_bounds__(256, 2)
bf16_gemm(const __nv_bfloat16* __restrict__ Ah, const __nv_bfloat16* __restrict__ Al, int lda,
          const __nv_bfloat16* __restrict__ Bh, const __nv_bfloat16* __restrict__ Bl, int ldb,
          float* __restrict__ C, int ldc,
          __nv_bfloat16* __restrict__ Chi, __nv_bfloat16* __restrict__ Clo, int ldch,
          const float* __restrict__ bias,
          int M, int N, int Kp, int relu) {
    constexpr int NI  = BM / 32;
    constexpr int AT  = BM * 40;
    constexpr int BT  = 128 * 40;
    constexpr int STG = 2 * AT + 2 * BT;
    extern __shared__ uint16_t sm[];

    const int tid   = threadIdx.x;
    const int lane  = tid & 31;
    const int warp  = tid >> 5;
    const int wr    = warp >> 2;
    const int wc    = warp & 3;
    const int group = lane >> 2;
    const int tig   = lane & 3;
    const int blockRow = blockIdx.y * BM;
    const int blockCol = blockIdx.x * 128;
    const int NC = Kp >> 5;

    const uint32_t smb = (uint32_t)__cvta_generic_to_shared(sm);
    const int aRow = lane & 15,  aCol = (lane >> 4) << 3;
    const int bRow = ((lane >> 4) << 3) + (lane & 7), bCol = ((lane >> 3) & 1) << 3;

    auto loadStage = [&](int c, int s) {
        uint16_t* base = sm + s * STG;
        int k0 = c << 5;
        for (int i = tid; i < BM * 4; i += 256) {
            int r = i >> 2, ch = i & 3;
            int gr = blockRow + r;
            int sz = (gr < M) ? 16 : 0;
            const __nv_bfloat16* ph = sz ? (Ah + (size_t)gr * lda + k0 + ch * 8) : Ah;
            const __nv_bfloat16* pl = sz ? (Al + (size_t)gr * lda + k0 + ch * 8) : Al;
            cpa16((uint32_t)__cvta_generic_to_shared(base + r * 40 + ch * 8), ph, sz);
            cpa16((uint32_t)__cvta_generic_to_shared(base + AT + r * 40 + ch * 8), pl, sz);
        }
        uint16_t* bb = base + 2 * AT;
        for (int i = tid; i < 128 * 4; i += 256) {
            int r = i >> 2, ch = i & 3;
            int gn = blockCol + r;
            int sz = (gn < N) ? 16 : 0;
            const __nv_bfloat16* ph = sz ? (Bh + (size_t)gn * ldb + k0 + ch * 8) : Bh;
            const __nv_bfloat16* pl = sz ? (Bl + (size_t)gn * ldb + k0 + ch * 8) : Bl;
            cpa16((uint32_t)__cvta_generic_to_shared(bb + r * 40 + ch * 8), ph, sz);
            cpa16((uint32_t)__cvta_generic_to_shared(bb + BT + r * 40 + ch * 8), pl, sz);
        }
        asm volatile("cp.async.commit_group;\n");
    };

    float acc[NI][4][4];
    #pragma unroll
    for (int i = 0; i < NI; i++)
        #pragma unroll
        for (int j = 0; j < 4; j++) {
            acc[i][j][0] = 0.f; acc[i][j][1] = 0.f;
            acc[i][j][2] = 0.f; acc[i][j][3] = 0.f;
        }

    loadStage(0, 0);

    for (int c = 0; c < NC; c++) {
        if (c + 1 < NC) {
            loadStage(c + 1, (c + 1) & 1);
            asm volatile("cp.async.wait_group 1;\n" ::: "memory");
        } else {
            asm volatile("cp.async.wait_group 0;\n" ::: "memory");
        }
        __syncthreads();

        const uint32_t stB = smb + (uint32_t)((c & 1) * STG) * 2;
        const uint32_t uAh = stB;
        const uint32_t uAl = stB + AT * 2;
        const uint32_t uBh = stB + 2 * AT * 2;
        const uint32_t uBl = stB + (2 * AT + BT) * 2;

        #pragma unroll
        for (int ks = 0; ks < 2; ks++) {
            const int kb = ks * 16;
            uint32_t bh[4][2], bl[4][2];
            #pragma unroll
            for (int p = 0; p < 2; p++) {
                int n = wc * 32 + p * 16 + bRow;
                uint32_t off = (uint32_t)(n * 40 + kb + bCol) * 2;
                LDMX4(bh[2*p][0], bh[2*p][1], bh[2*p+1][0], bh[2*p+1][1], uBh + off);
                LDMX4(bl[2*p][0], bl[2*p][1], bl[2*p+1][0], bl[2*p+1][1], uBl + off);
            }
            #pragma unroll
            for (int i = 0; i < NI; i++) {
                int r = wr * (BM / 2) + i * 16 + aRow;
                uint32_t off = (uint32_t)(r * 40 + kb + aCol) * 2;
                uint32_t ah0, ah1, ah2, ah3, al0, al1, al2, al3;
                LDMX4(ah0, ah1, ah2, ah3, uAh + off);
                LDMX4(al0, al1, al2, al3, uAl + off);
                // term-major: 4 independent chains per term, same per-acc order
                #pragma unroll
                for (int j = 0; j < 4; j++)
                    mma_bf16(acc[i][j], ah0, ah1, ah2, ah3, bh[j][0], bh[j][1]);
                #pragma unroll
                for (int j = 0; j < 4; j++)
                    mma_bf16(acc[i][j], al0, al1, al2, al3, bh[j][0], bh[j][1]);
                #pragma unroll
                for (int j = 0; j < 4; j++)
                    mma_bf16(acc[i][j], ah0, ah1, ah2, ah3, bl[j][0], bl[j][1]);
            }
        }
        __syncthreads();
    }

    #pragma unroll
    for (int i = 0; i < NI; i++) {
        int r0 = blockRow + wr * (BM / 2) + i * 16 + group;
        int r1 = r0 + 8;
        #pragma unroll
        for (int j = 0; j < 4; j++) {
            int gc = blockCol + wc * 32 + j * 8 + tig * 2;
            if (gc >= N) continue;
            float bi0 = bias ? bias[gc] : 0.f;
            float bi1 = bias ? bias[gc + 1] : 0.f;
            float v0 = acc[i][j][0] + bi0, v1 = acc[i][j][1] + bi1;
            float v2 = acc[i][j][2] + bi0, v3 = acc[i][j][3] + bi1;
            if (relu) {
                v0 = fmaxf(v0, 0.f); v1 = fmaxf(v1, 0.f);
                v2 = fmaxf(v2, 0.f); v3 = fmaxf(v3, 0.f);
            }
            if (r0 < M) {
                if (C) *(float2*)(C + (size_t)r0 * ldc + gc) = make_float2(v0, v1);
                if (Chi) {
                    __nv_bfloat16 h0, l0, h1, l1;
                    bsplit(v0, h0, l0); bsplit(v1, h1, l1);
                    Chi[(size_t)r0 * ldch + gc] = h0; Chi[(size_t)r0 * ldch + gc + 1] = h1;
                    Clo[(size_t)r0 * ldch + gc] = l0; Clo[(size_t)r0 * ldch + gc + 1] = l1;
                }
            }
            if (r1 < M) {
                if (C) *(float2*)(C + (size_t)r1 * ldc + gc) = make_float2(v2, v3);
                if (Chi) {
                    __nv_bfloat16 h2, l2, h3, l3;
                    bsplit(v2, h2, l2); bsplit(v3, h3, l3);
                    Chi[(size_t)r1 * ldch + gc] = h2; Chi[(size_t)r1 * ldch + gc + 1] = h3;
                    Clo[(size_t)r1 * ldch + gc] = l2; Clo[(size_t)r1 * ldch + gc + 1] = l3;
                }
            }
        }
    }
}

// ---------------- GAT: attention scores (float4 loads) ----------------------
__global__ void att_scores(const float* __restrict__ xs, const float* __restrict__ xd,
                           int S,
                           const float* __restrict__ att_s, const float* __restrict__ att_d,
                           float* __restrict__ a_s, float* __restrict__ a_d) {
    int n = blockIdx.x;
    int w = threadIdx.x >> 5;
    int lane = threadIdx.x & 31;
    size_t base = (size_t)n * S + w * HIDD + lane * 4;
    const float4 vs = *(const float4*)(xs + base);
    const float4 vd = *(const float4*)(xd + base);
    const float4 as4 = *(const float4*)(att_s + w * HIDD + lane * 4);
    const float4 ad4 = *(const float4*)(att_d + w * HIDD + lane * 4);
    float s = vs.x * as4.x + vs.y * as4.y + vs.z * as4.z + vs.w * as4.w;
    float d = vd.x * ad4.x + vd.y * ad4.y + vd.z * ad4.z + vd.w * ad4.w;
    #pragma unroll
    for (int o = 16; o > 0; o >>= 1) {
        s += __shfl_down_sync(0xffffffffu, s, o);
        d += __shfl_down_sync(0xffffffffu, d, o);
    }
    if (lane == 0) { a_s[n * NH + w] = s; a_d[n * NH + w] = d; }
}

// ---------------- GAT aggregation (planar alpha, unroll x2) -----------------
__global__ void __launch_bounds__(128)
gat_aggregate(const int* __restrict__ starts, const int* __restrict__ eid,
              const int* __restrict__ src,
              const float* __restrict__ a_s, const float* __restrict__ a_d,
              const float* __restrict__ xs, int S,
              float* __restrict__ alpha, float* __restrict__ gat) {
    int n = blockIdx.x;
    int h = threadIdx.x >> 5;
    int lane = threadIdx.x & 31;
    int beg = starts[n], end = starts[n + 1];

    float adn = a_d[n * NH + h];
    float* alphaH = alpha + (size_t)h * EE;

    float mx = -3.4e38f;
    for (int i = beg + lane; i < end; i += 32) {
        int e = eid[i];
        float a = a_s[src[e] * NH + h] + adn;
        a = a > 0.f ? a : 0.2f * a;
        alphaH[i] = a;
        mx = fmaxf(mx, a);
    }
    #pragma unroll
    for (int o = 16; o > 0; o >>= 1)
        mx = fmaxf(mx, __shfl_xor_sync(0xffffffffu, mx, o));

    float den0 = 0.f, den1 = 0.f;
    float4 acc0 = make_float4(0.f, 0.f, 0.f, 0.f);
    float4 acc1 = make_float4(0.f, 0.f, 0.f, 0.f);
    const int chOff = h * HIDD + lane * 4;
    int i = beg;
    for (; i + 1 < end; i += 2) {
        int e0 = eid[i], e1 = eid[i + 1];
        float w0 = expf(alphaH[i] - mx);
        float w1 = expf(alphaH[i + 1] - mx);
        const float4 v0 = *(const float4*)(xs + (size_t)src[e0] * S + chOff);
        const float4 v1 = *(const float4*)(xs + (size_t)src[e1] * S + chOff);
        den0 += w0; den1 += w1;
        acc0.x += v0.x * w0; acc0.y += v0.y * w0;
        acc0.z += v0.z * w0; acc0.w += v0.w * w0;
        acc1.x += v1.x * w1; acc1.y += v1.y * w1;
        acc1.z += v1.z * w1; acc1.w += v1.w * w1;
    }
    if (i < end) {
        int e0 = eid[i];
        float w0 = expf(alphaH[i] - mx);
        const float4 v0 = *(const float4*)(xs + (size_t)src[e0] * S + chOff);
        den0 += w0;
        acc0.x += v0.x * w0; acc0.y += v0.y * w0;
        acc0.z += v0.z * w0; acc0.w += v0.w * w0;
    }
    float den = den0 + den1;
    float4 acc = make_float4(acc0.x + acc1.x, acc0.y + acc1.y,
                             acc0.z + acc1.z, acc0.w + acc1.w);
    float inv = 1.f / (den + 1e-16f);
    acc.x *= inv; acc.y *= inv; acc.z *= inv; acc.w *= inv;
    *(float4*)(gat + (size_t)n * DMID + chOff) = acc;
}

// ---------------- residual (+bias) + LayerNorm + ReLU -> bf16 hi/lo --------
__global__ void resid_ln_relu(const float* __restrict__ gat, const float* __restrict__ cb,
                              const float* __restrict__ lin, int linS,
                              const float* __restrict__ g, const float* __restrict__ b,
                              __nv_bfloat16* __restrict__ hh, __nv_bfloat16* __restrict__ hl) {
    int row = blockIdx.x;
    int t = threadIdx.x;
    size_t gb = (size_t)row * DMID;
    size_t lb = (size_t)row * linS;
    float v0 = gat[gb + t]       + cb[t]       + lin[lb + t];
    float v1 = gat[gb + 256 + t] + cb[256 + t] + lin[lb + 256 + t];
    float s = v0 + v1;
    float ss = v0 * v0 + v1 * v1;
    #pragma unroll
    for (int o = 16; o > 0; o >>= 1) {
        s  += __shfl_down_sync(0xffffffffu, s, o);
        ss += __shfl_down_sync(0xffffffffu, ss, o);
    }
    __shared__ float shs[8], shss[8];
    __shared__ float mu_sh, inv_sh;
    int w = t >> 5, lane = t & 31;
    if (lane == 0) { shs[w] = s; shss[w] = ss; }
    __syncthreads();
    if (t == 0) {
        float S = 0.f, SS = 0.f;
        #pragma unroll
        for (int i = 0; i < 8; i++) { S += shs[i]; SS += shss[i]; }
        float mu = S * (1.f / DMID);
        float var = SS * (1.f / DMID) - mu * mu;
        mu_sh = mu;
        inv_sh = rsqrtf(var + 1e-5f);
    }
    __syncthreads();
    float mu = mu_sh, inv = inv_sh;
    float o0 = fmaxf((v0 - mu) * inv * g[t]       + b[t],       0.f);
    float o1 = fmaxf((v1 - mu) * inv * g[256 + t] + b[256 + t], 0.f);
    __nv_bfloat16 h0, l0, h1, l1;
    bsplit(o0, h0, l0); bsplit(o1, h1, l1);
    hh[gb + t] = h0;       hl[gb + t] = l0;
    hh[gb + 256 + t] = h1; hl[gb + 256 + t] = l1;
}

__global__ void resid_add(const float* __restrict__ gat, const float* __restrict__ cb,
                          const float* __restrict__ lin, int linS,
                          __nv_bfloat16* __restrict__ hh, __nv_bfloat16* __restrict__ hl) {
    int i = blockIdx.x * blockDim.x + threadIdx.x;
    int stride = gridDim.x * blockDim.x;
    for (; i < NN * DMID; i += stride) {
        int row = i >> 9, col = i & (DMID - 1);
        float v = gat[i] + cb[col] + lin[(size_t)row * linS + col];
        __nv_bfloat16 h, l; bsplit(v, h, l);
        hh[i] = h; hl[i] = l;
    }
}

// ---------------- host -------------------------------------------------------
struct WSpec { int off, K, N, Kp; };

static void gemm128(const __nv_bfloat16* Ah, const __nv_bfloat16* Al, int lda,
                    const __nv_bfloat16* Bh, const __nv_bfloat16* Bl, int ldb,
                    float* C, int ldc, __nv_bfloat16* Chi, __nv_bfloat16* Clo, int ldch,
                    const float* bias, int M, int N, int Kp, int relu) {
    constexpr int SM_BYTES = (2 * 128 * 40 + 2 * 128 * 40) * 2 * 2;
    cudaFuncSetAttribute(bf16_gemm<128>,
                         cudaFuncAttributeMaxDynamicSharedMemorySize, SM_BYTES);
    dim3 grid((N + 127) / 128, (M + 127) / 128);
    bf16_gemm<128><<<grid, 256, SM_BYTES>>>(Ah, Al, lda, Bh, Bl, ldb, C, ldc,
        Chi, Clo, ldch, bias, M, N, Kp, relu);
}
static void gemm64(const __nv_bfloat16* Ah, const __nv_bfloat16* Al, int lda,
                   const __nv_bfloat16* Bh, const __nv_bfloat16* Bl, int ldb,
                   float* C, int ldc, __nv_bfloat16* Chi, __nv_bfloat16* Clo, int ldch,
                   const float* bias, int M, int N, int Kp, int relu) {
    constexpr int SM_BYTES = (2 * 64 * 40 + 2 * 128 * 40) * 2 * 2;
    cudaFuncSetAttribute(bf16_gemm<64>,
                         cudaFuncAttributeMaxDynamicSharedMemorySize, SM_BYTES);
    dim3 grid((N + 127) / 128, (M + 63) / 64);
    bf16_gemm<64><<<grid, 256, SM_BYTES>>>(Ah, Al, lda, Bh, Bl, ldb, C, ldc,
        Chi, Clo, ldch, bias, M, N, Kp, relu);
}

extern "C" void kernel_launch(void* const* d_in, const int* in_sizes, int n_in,
                              void* d_out, int out_size) {
    const float* x      = (const float*)d_in[0];
    const void*  ei     = d_in[1];
    const float* W_rna  = (const float*)d_in[2];
    const float* b_rna  = (const float*)d_in[3];
    const float* W_prot = (const float*)d_in[4];
    const float* b_prot = (const float*)d_in[5];
    const float* c1_Ws  = (const float*)d_in[6];
    const float* c1_Wd  = (const float*)d_in[7];
    const float* c1_as  = (const float*)d_in[8];
    const float* c1_ad  = (const float*)d_in[9];
    const float* c1_b   = (const float*)d_in[10];
    const float* l1_W   = (const float*)d_in[11];
    const float* l1_b   = (const float*)d_in[12];
    const float* ln_g   = (const float*)d_in[13];
    const float* ln_b   = (const float*)d_in[14];
    const float* c2_Ws  = (const float*)d_in[15];
    const float* c2_Wd  = (const float*)d_in[16];
    const float* c2_as  = (const float*)d_in[17];
    const float* c2_ad  = (const float*)d_in[18];
    const float* c2_b   = (const float*)d_in[19];
    const float* l2_W   = (const float*)d_in[20];
    const float* l2_b   = (const float*)d_in[21];
    const float* agg_W  = (const float*)d_in[22];
    const float* agg_b  = (const float*)d_in[23];
    const float* dr_W   = (const float*)d_in[24];
    const float* dr_b   = (const float*)d_in[25];
    const float* dp_W   = (const float*)d_in[26];
    const float* dp_b   = (const float*)d_in[27];
    const float* rr_W   = (const float*)d_in[28];
    const float* rr_b   = (const float*)d_in[29];
    const float* rp_W   = (const float*)d_in[30];
    const float* rp_b   = (const float*)d_in[31];

    float* out = (float*)d_out;
    float* out_rna  = out;
    float* out_prot = out + (size_t)NN * RNAD;
    float* out_emb  = out + (size_t)NN * (RNAD + PROTD);

    float *big, *gat, *as_, *ad_, *alpha, *bias1, *bias2b, *biasT;
    int *srcI, *dstI, *cnt, *starts, *fill, *eid;
    __nv_bfloat16 *xh, *xl, *xinh, *xinl, *hh, *hl, *embh, *embl, *th, *tl, *wh, *wl;
    cudaGetSymbolAddress((void**)&big,   g_big);
    cudaGetSymbolAddress((void**)&gat,   g_gat);
    cudaGetSymbolAddress((void**)&as_,   g_as);
    cudaGetSymbolAddress((void**)&ad_,   g_ad);
    cudaGetSymbolAddress((void**)&alpha, g_alpha);
    cudaGetSymbolAddress((void**)&srcI,  g_src);
    cudaGetSymbolAddress((void**)&dstI,  g_dst);
    cudaGetSymbolAddress((void**)&cnt,   g_cnt);
    cudaGetSymbolAddress((void**)&starts,g_starts);
    cudaGetSymbolAddress((void**)&fill,  g_fill);
    cudaGetSymbolAddress((void**)&eid,   g_eid);
    cudaGetSymbolAddress((void**)&bias1, g_bias1);
    cudaGetSymbolAddress((void**)&bias2b,g_bias2);
    cudaGetSymbolAddress((void**)&biasT, g_biasT);
    cudaGetSymbolAddress((void**)&xh,    g_xh);
    cudaGetSymbolAddress((void**)&xl,    g_xl);
    cudaGetSymbolAddress((void**)&xinh,  g_xinh);
    cudaGetSymbolAddress((void**)&xinl,  g_xinl);
    cudaGetSymbolAddress((void**)&hh,    g_hh);
    cudaGetSymbolAddress((void**)&hl,    g_hl);
    cudaGetSymbolAddress((void**)&embh,  g_embh);
    cudaGetSymbolAddress((void**)&embl,  g_embl);
    cudaGetSymbolAddress((void**)&th,    g_th);
    cudaGetSymbolAddress((void**)&tl,    g_tl);
    cudaGetSymbolAddress((void**)&wh,    g_wh);
    cudaGetSymbolAddress((void**)&wl,    g_wl);

    const int EB = 256;

    // ---- decode edges + CSR -------------------------------------------------
    detect_fmt<<<1, 32>>>((const unsigned*)ei);
    decode_idx<<<(2 * EE + EB - 1) / EB, EB>>>(ei, srcI, dstI);
    zero_u32<<<40, 256>>>((unsigned*)cnt, NN);
    csr_hist<<<(EE + EB - 1) / EB, EB>>>(dstI, cnt);
    csr_scan<<<1, 1024>>>(cnt, starts, fill);
    csr_fill<<<(EE + EB - 1) / EB, EB>>>(dstI, fill, eid);

    // ---- preprocessing -------------------------------------------------------
    split_x4<<<(NN * (XPAD / 4) + 255) / 256, 256>>>(x, xh, xl);
    const WSpec ws[13] = {
        {OFF_WRNA,  RNAD, EMBD, KRNA},  {OFF_WPROT, PROTD, EMBD, KPROT},
        {OFF_C1WS,  DIN,  DMID, DIN},   {OFF_C1WD,  DIN,  DMID, DIN},
        {OFF_L1W,   DIN,  DMID, DIN},
        {OFF_C2WS,  DMID, DMID, DMID},  {OFF_C2WD,  DMID, DMID, DMID},
        {OFF_L2W,   DMID, DMID, DMID},
        {OFF_AGG,   DMID, EMBD, DMID},
        {OFF_DR,    EMBD, EMBD, EMBD},  {OFF_DP,    EMBD, EMBD, EMBD},
        {OFF_RR,    EMBD, RNAD, EMBD},  {OFF_RP,    EMBD, PROTD, EMBD},
    };
    const float* wp[13] = {W_rna, W_prot, c1_Ws, c1_Wd, l1_W, c2_Ws, c2_Wd, l2_W,
                           agg_W, dr_W, dp_W, rr_W, rp_W};
    for (int i = 0; i < 13; i++) {
        dim3 tgrid((ws[i].Kp + 31) / 32, (ws[i].N + 31) / 32);
        split_w_t<<<tgrid, dim3(32, 8)>>>(wp[i], ws[i].K, ws[i].N, ws[i].Kp,
                                          wh + ws[i].off, wl + ws[i].off);
    }
    bias_all<<<6, 256>>>(l1_b, l2_b, dr_b, dp_b, bias1, bias2b, biasT);

    // ---- input embeddings -> xin hi/lo ---------------------------------------
    gemm64(xh, xl, XPAD, wh + OFF_WRNA, wl + OFF_WRNA, KRNA,
           nullptr, 0, xinh, xinl, DIN, b_rna, NN, EMBD, KRNA, 0);
    gemm64(xh + KRNA, xl + KRNA, XPAD, wh + OFF_WPROT, wl + OFF_WPROT, KPROT,
           nullptr, 0, xinh + EMBD, xinl + EMBD, DIN, b_prot, NN, EMBD, KPROT, 0);

    // ================= Block 1: fused xs|xd|lin ============================
    gemm128(xinh, xinl, DIN, wh + OFF_C1WS, wl + OFF_C1WS, DIN,
            big, BIGW, nullptr, nullptr, 0, bias1, NN, BIGW, DIN, 0);
    att_scores<<<NN, 128>>>(big, big + 512, BIGW, c1_as, c1_ad, as_, ad_);
    gat_aggregate<<<NN, 128>>>(starts, eid, srcI, as_, ad_, big, BIGW, alpha, gat);
    resid_ln_relu<<<NN, 256>>>(gat, c1_b, big + 1024, BIGW, ln_g, ln_b, hh, hl);

    // ================= Block 2: fused xs|xd|lin ============================
    gemm128(hh, hl, DMID, wh + OFF_C2WS, wl + OFF_C2WS, DMID,
            big, BIGW, nullptr, nullptr, 0, bias2b, NN, BIGW, DMID, 0);
    att_scores<<<NN, 128>>>(big, big + 512, BIGW, c2_as, c2_ad, as_, ad_);
    gat_aggregate<<<NN, 128>>>(starts, eid, srcI, as_, ad_, big, BIGW, alpha, gat);
    resid_add<<<512, 256>>>(gat, c2_b, big + 1024, BIGW, hh, hl);

    // ================= Heads ===============================================
    gemm64(hh, hl, DMID, wh + OFF_AGG, wl + OFF_AGG, DMID,
           out_emb, EMBD, embh, embl, EMBD, agg_b, NN, EMBD, DMID, 1);

    gemm64(embh, embl, EMBD, wh + OFF_DR, wl + OFF_DR, EMBD,
           nullptr, 0, th, tl, 256, biasT, NN, 256, EMBD, 0);

    gemm128(th, tl, 256, wh + OFF_RR, wl + OFF_RR, EMBD,
            out_rna, RNAD, nullptr, nullptr, 0, rr_b, NN, RNAD, EMBD, 0);
    gemm64(th + 128, tl + 128, 256, wh + OFF_RP, wl + OFF_RP, EMBD,
           out_prot, PROTD, nullptr, nullptr, 0, rp_b, NN, PROTD, EMBD, 0);
}

// round 15
// speedup vs baseline: 1.2455x; 1.1008x over previous
#include <cuda_runtime.h>
#include <cuda_bf16.h>
#include <cstdint>

#define NN   10000
#define EE   160000
#define RNAD 2000
#define PROTD 100
#define EMBD 128
#define HIDD 128
#define NH   4
#define DIN  256
#define DMID 512
#define BIGW 1536

#define KRNA  2016
#define KPROT 128
#define XPAD  (KRNA + KPROT)

// ---------------- scratch (static device globals) --------------------------
__device__ float          g_big[NN * BIGW];
__device__ float          g_gat[NN * DMID];
__device__ float          g_as [NN * NH];
__device__ float          g_ad [NN * NH];
__device__ float          g_alpha[EE * NH];     // planar: [h][i]
__device__ int            g_src[EE];
__device__ int            g_dst[EE];
__device__ int            g_is64;
__device__ int            g_cnt[NN];
__device__ int            g_starts[NN + 1];
__device__ int            g_fill[NN];
__device__ int            g_eid[EE];
__device__ float          g_bias1[BIGW];
__device__ float          g_bias2[BIGW];
__device__ float          g_biasT[256];

__device__ __nv_bfloat16  g_xh [NN * XPAD];
__device__ __nv_bfloat16  g_xl [NN * XPAD];
__device__ __nv_bfloat16  g_xinh[NN * DIN];
__device__ __nv_bfloat16  g_xinl[NN * DIN];
__device__ __nv_bfloat16  g_hh [NN * DMID];
__device__ __nv_bfloat16  g_hl [NN * DMID];
__device__ __nv_bfloat16  g_embh[NN * EMBD];
__device__ __nv_bfloat16  g_embl[NN * EMBD];
__device__ __nv_bfloat16  g_th [NN * 256];
__device__ __nv_bfloat16  g_tl [NN * 256];

// weight arena (K-major, padded)
#define OFF_WRNA  0
#define OFF_WPROT 258048
#define OFF_C1WS  274432
#define OFF_C1WD  405504
#define OFF_L1W   536576
#define OFF_C2WS  667648
#define OFF_C2WD  929792
#define OFF_L2W   1191936
#define OFF_AGG   1454080
#define OFF_DR    1519616
#define OFF_DP    1536000
#define OFF_RR    1552384
#define OFF_RP    1808384
#define WARENA    1821184
__device__ __nv_bfloat16 g_wh[WARENA];
__device__ __nv_bfloat16 g_wl[WARENA];

// ---------------- helpers ---------------------------------------------------
__device__ __forceinline__ void bsplit(float v, __nv_bfloat16& h, __nv_bfloat16& l) {
    h = __float2bfloat16(v);
    l = __float2bfloat16(v - __bfloat162float(h));
}
__device__ __forceinline__ void cpa16(uint32_t dst, const void* src, int sz) {
    asm volatile("cp.async.ca.shared.global [%0], [%1], 16, %2;\n"
                 :: "r"(dst), "l"(src), "r"(sz));
}
__device__ __forceinline__ void mma_bf16(float* c, uint32_t a0, uint32_t a1,
                                         uint32_t a2, uint32_t a3,
                                         uint32_t b0, uint32_t b1) {
    asm volatile(
        "mma.sync.aligned.m16n8k16.row.col.f32.bf16.bf16.f32 "
        "{%0,%1,%2,%3}, {%4,%5,%6,%7}, {%8,%9}, {%0,%1,%2,%3};"
        : "+f"(c[0]), "+f"(c[1]), "+f"(c[2]), "+f"(c[3])
        : "r"(a0), "r"(a1), "r"(a2), "r"(a3), "r"(b0), "r"(b1));
}
#define LDMX4(r0, r1, r2, r3, addr) \
    asm volatile("ldmatrix.sync.aligned.m8n8.x4.shared.b16 {%0,%1,%2,%3}, [%4];" \
                 : "=r"(r0), "=r"(r1), "=r"(r2), "=r"(r3) : "r"(addr))

// ---------------- edge-index dtype detect + decode -------------------------
__global__ void detect_fmt(const unsigned* __restrict__ w) {
    if (threadIdx.x == 0 && blockIdx.x == 0) {
        unsigned acc = 0;
        for (int i = 1; i < 4096; i += 2) acc |= w[i];
        g_is64 = (acc == 0u) ? 1 : 0;
    }
}
__global__ void decode_idx(const void* __restrict__ ei,
                           int* __restrict__ src, int* __restrict__ dst) {
    int i = blockIdx.x * blockDim.x + threadIdx.x;
    if (i >= 2 * EE) return;
    long long v;
    if (g_is64) v = ((const long long*)ei)[i];
    else        v = (long long)((const int*)ei)[i];
    int vi = (int)v;
    vi = vi < 0 ? 0 : (vi >= NN ? NN - 1 : vi);
    if (i < EE) src[i] = vi;
    else        dst[i - EE] = vi;
}
__global__ void zero_u32(unsigned* p, int n) {
    int i = blockIdx.x * blockDim.x + threadIdx.x;
    int stride = gridDim.x * blockDim.x;
    for (; i < n; i += stride) p[i] = 0u;
}

// ---------------- CSR build --------------------------------------------------
__global__ void csr_hist(const int* __restrict__ dst, int* __restrict__ cnt) {
    int e = blockIdx.x * blockDim.x + threadIdx.x;
    if (e < EE) atomicAdd(&cnt[dst[e]], 1);
}
#define SCAN_CHUNK 10
__global__ void csr_scan(const int* __restrict__ cnt,
                         int* __restrict__ starts, int* __restrict__ fill) {
    __shared__ int wsum[32];
    int t = threadIdx.x;
    int lane = t & 31, w = t >> 5;
    int base = t * SCAN_CHUNK;
    int loc[SCAN_CHUNK];
    int s = 0;
    #pragma unroll
    for (int j = 0; j < SCAN_CHUNK; j++) {
        int idx = base + j;
        int v = (idx < NN) ? cnt[idx] : 0;
        loc[j] = s; s += v;
    }
    int si = s;
    #pragma unroll
    for (int o = 1; o < 32; o <<= 1) {
        int v = __shfl_up_sync(0xffffffffu, si, o);
        if (lane >= o) si += v;
    }
    if (lane == 31) wsum[w] = si;
    __syncthreads();
    if (w == 0) {
        int v = wsum[lane];
        int vi = v;
        #pragma unroll
        for (int o = 1; o < 32; o <<= 1) {
            int u = __shfl_up_sync(0xffffffffu, vi, o);
            if (lane >= o) vi += u;
        }
        wsum[lane] = vi - v;
    }
    __syncthreads();
    int off = wsum[w] + (si - s);
    #pragma unroll
    for (int j = 0; j < SCAN_CHUNK; j++) {
        int idx = base + j;
        if (idx < NN) {
            int st = off + loc[j];
            starts[idx] = st;
            fill[idx] = st;
        }
    }
    if (t == 1023) starts[NN] = off + s;
}
__global__ void csr_fill(const int* __restrict__ dst,
                         int* __restrict__ fill, int* __restrict__ eid) {
    int e = blockIdx.x * blockDim.x + threadIdx.x;
    if (e < EE) {
        int p = atomicAdd(&fill[dst[e]], 1);
        eid[p] = e;
    }
}

// ---------------- preprocessing ----------------------------------------------
__global__ void split_x4(const float* __restrict__ x,
                         __nv_bfloat16* __restrict__ hi, __nv_bfloat16* __restrict__ lo) {
    int i4 = blockIdx.x * blockDim.x + threadIdx.x;
    if (i4 >= NN * (XPAD / 4)) return;
    int r = i4 / (XPAD / 4);
    int c = (i4 % (XPAD / 4)) * 4;
    float4 v = make_float4(0.f, 0.f, 0.f, 0.f);
    if (c < RNAD)
        v = *(const float4*)(x + (size_t)r * (RNAD + PROTD) + c);
    else if (c >= KRNA && c < KRNA + PROTD)
        v = *(const float4*)(x + (size_t)r * (RNAD + PROTD) + RNAD + (c - KRNA));
    __nv_bfloat16 h0, l0, h1, l1, h2, l2, h3, l3;
    bsplit(v.x, h0, l0); bsplit(v.y, h1, l1);
    bsplit(v.z, h2, l2); bsplit(v.w, h3, l3);
    uint2 hv, lv;
    hv.x = (uint32_t)__bfloat16_as_ushort(h0) | ((uint32_t)__bfloat16_as_ushort(h1) << 16);
    hv.y = (uint32_t)__bfloat16_as_ushort(h2) | ((uint32_t)__bfloat16_as_ushort(h3) << 16);
    lv.x = (uint32_t)__bfloat16_as_ushort(l0) | ((uint32_t)__bfloat16_as_ushort(l1) << 16);
    lv.y = (uint32_t)__bfloat16_as_ushort(l2) | ((uint32_t)__bfloat16_as_ushort(l3) << 16);
    *(uint2*)(hi + (size_t)i4 * 4) = hv;
    *(uint2*)(lo + (size_t)i4 * 4) = lv;
}

__global__ void split_w_t(const float* __restrict__ W, int K, int N, int Kp,
                          __nv_bfloat16* __restrict__ hi, __nv_bfloat16* __restrict__ lo) {
    __shared__ float tile[32][33];
    int k0 = blockIdx.x * 32;
    int n0 = blockIdx.y * 32;
    int tx = threadIdx.x, ty = threadIdx.y;      // 32 x 8
    #pragma unroll
    for (int i = 0; i < 4; i++) {
        int k = k0 + ty + i * 8;
        int n = n0 + tx;
        tile[ty + i * 8][tx] = (k < K && n < N) ? W[(size_t)k * N + n] : 0.f;
    }
    __syncthreads();
    #pragma unroll
    for (int i = 0; i < 4; i++) {
        int n = n0 + ty + i * 8;
        int k = k0 + tx;
        if (n < N && k < Kp) {
            float v = tile[tx][ty + i * 8];
            __nv_bfloat16 h, l; bsplit(v, h, l);
            hi[(size_t)n * Kp + k] = h;
            lo[(size_t)n * Kp + k] = l;
        }
    }
}

__global__ void bias_all(const float* __restrict__ l1b, const float* __restrict__ l2b,
                         const float* __restrict__ drb, const float* __restrict__ dpb,
                         float* __restrict__ b1, float* __restrict__ b2,
                         float* __restrict__ bT) {
    int i = blockIdx.x * blockDim.x + threadIdx.x;
    if (i < BIGW) {
        float v1 = (i < 1024) ? 0.f : l1b[i - 1024];
        float v2 = (i < 1024) ? 0.f : l2b[i - 1024];
        b1[i] = v1; b2[i] = v2;
    }
    if (i < 256) bT[i] = (i < 128) ? drb[i] : dpb[i - 128];
}

// ============================================================================
// bf16 tensor-core GEMM (identical to R14)
// ============================================================================
template<int BM>
__global__ void __launch_bounds__(256, 2)
bf16_gemm(const __nv_bfloat16* __restrict__ Ah, const __nv_bfloat16* __restrict__ Al, int lda,
          const __nv_bfloat16* __restrict__ Bh, const __nv_bfloat16* __restrict__ Bl, int ldb,
          float* __restrict__ C, int ldc,
          __nv_bfloat16* __restrict__ Chi, __nv_bfloat16* __restrict__ Clo, int ldch,
          const float* __restrict__ bias,
          int M, int N, int Kp, int relu) {
    constexpr int NI  = BM / 32;
    constexpr int AT  = BM * 40;
    constexpr int BT  = 128 * 40;
    constexpr int STG = 2 * AT + 2 * BT;
    extern __shared__ uint16_t sm[];

    const int tid   = threadIdx.x;
    const int lane  = tid & 31;
    const int warp  = tid >> 5;
    const int wr    = warp >> 2;
    const int wc    = warp & 3;
    const int group = lane >> 2;
    const int tig   = lane & 3;
    const int blockRow = blockIdx.y * BM;
    const int blockCol = blockIdx.x * 128;
    const int NC = Kp >> 5;

    const uint32_t smb = (uint32_t)__cvta_generic_to_shared(sm);
    const int aRow = lane & 15,  aCol = (lane >> 4) << 3;
    const int bRow = ((lane >> 4) << 3) + (lane & 7), bCol = ((lane >> 3) & 1) << 3;

    auto loadStage = [&](int c, int s) {
        uint16_t* base = sm + s * STG;
        int k0 = c << 5;
        for (int i = tid; i < BM * 4; i += 256) {
            int r = i >> 2, ch = i & 3;
            int gr = blockRow + r;
            int sz = (gr < M) ? 16 : 0;
            const __nv_bfloat16* ph = sz ? (Ah + (size_t)gr * lda + k0 + ch * 8) : Ah;
            const __nv_bfloat16* pl = sz ? (Al + (size_t)gr * lda + k0 + ch * 8) : Al;
            cpa16((uint32_t)__cvta_generic_to_shared(base + r * 40 + ch * 8), ph, sz);
            cpa16((uint32_t)__cvta_generic_to_shared(base + AT + r * 40 + ch * 8), pl, sz);
        }
        uint16_t* bb = base + 2 * AT;
        for (int i = tid; i < 128 * 4; i += 256) {
            int r = i >> 2, ch = i & 3;
            int gn = blockCol + r;
            int sz = (gn < N) ? 16 : 0;
            const __nv_bfloat16* ph = sz ? (Bh + (size_t)gn * ldb + k0 + ch * 8) : Bh;
            const __nv_bfloat16* pl = sz ? (Bl + (size_t)gn * ldb + k0 + ch * 8) : Bl;
            cpa16((uint32_t)__cvta_generic_to_shared(bb + r * 40 + ch * 8), ph, sz);
            cpa16((uint32_t)__cvta_generic_to_shared(bb + BT + r * 40 + ch * 8), pl, sz);
        }
        asm volatile("cp.async.commit_group;\n");
    };

    float acc[NI][4][4];
    #pragma unroll
    for (int i = 0; i < NI; i++)
        #pragma unroll
        for (int j = 0; j < 4; j++) {
            acc[i][j][0] = 0.f; acc[i][j][1] = 0.f;
            acc[i][j][2] = 0.f; acc[i][j][3] = 0.f;
        }

    loadStage(0, 0);

    for (int c = 0; c < NC; c++) {
        if (c + 1 < NC) {
            loadStage(c + 1, (c + 1) & 1);
            asm volatile("cp.async.wait_group 1;\n" ::: "memory");
        } else {
            asm volatile("cp.async.wait_group 0;\n" ::: "memory");
        }
        __syncthreads();

        const uint32_t stB = smb + (uint32_t)((c & 1) * STG) * 2;
        const uint32_t uAh = stB;
        const uint32_t uAl = stB + AT * 2;
        const uint32_t uBh = stB + 2 * AT * 2;
        const uint32_t uBl = stB + (2 * AT + BT) * 2;

        #pragma unroll
        for (int ks = 0; ks < 2; ks++) {
            const int kb = ks * 16;
            uint32_t bh[4][2], bl[4][2];
            #pragma unroll
            for (int p = 0; p < 2; p++) {
                int n = wc * 32 + p * 16 + bRow;
                uint32_t off = (uint32_t)(n * 40 + kb + bCol) * 2;
                LDMX4(bh[2*p][0], bh[2*p][1], bh[2*p+1][0], bh[2*p+1][1], uBh + off);
                LDMX4(bl[2*p][0], bl[2*p][1], bl[2*p+1][0], bl[2*p+1][1], uBl + off);
            }
            #pragma unroll
            for (int i = 0; i < NI; i++) {
                int r = wr * (BM / 2) + i * 16 + aRow;
                uint32_t off = (uint32_t)(r * 40 + kb + aCol) * 2;
                uint32_t ah0, ah1, ah2, ah3, al0, al1, al2, al3;
                LDMX4(ah0, ah1, ah2, ah3, uAh + off);
                LDMX4(al0, al1, al2, al3, uAl + off);
                #pragma unroll
                for (int j = 0; j < 4; j++)
                    mma_bf16(acc[i][j], ah0, ah1, ah2, ah3, bh[j][0], bh[j][1]);
                #pragma unroll
                for (int j = 0; j < 4; j++)
                    mma_bf16(acc[i][j], al0, al1, al2, al3, bh[j][0], bh[j][1]);
                #pragma unroll
                for (int j = 0; j < 4; j++)
                    mma_bf16(acc[i][j], ah0, ah1, ah2, ah3, bl[j][0], bl[j][1]);
            }
        }
        __syncthreads();
    }

    #pragma unroll
    for (int i = 0; i < NI; i++) {
        int r0 = blockRow + wr * (BM / 2) + i * 16 + group;
        int r1 = r0 + 8;
        #pragma unroll
        for (int j = 0; j < 4; j++) {
            int gc = blockCol + wc * 32 + j * 8 + tig * 2;
            if (gc >= N) continue;
            float bi0 = bias ? bias[gc] : 0.f;
            float bi1 = bias ? bias[gc + 1] : 0.f;
            float v0 = acc[i][j][0] + bi0, v1 = acc[i][j][1] + bi1;
            float v2 = acc[i][j][2] + bi0, v3 = acc[i][j][3] + bi1;
            if (relu) {
                v0 = fmaxf(v0, 0.f); v1 = fmaxf(v1, 0.f);
                v2 = fmaxf(v2, 0.f); v3 = fmaxf(v3, 0.f);
            }
            if (r0 < M) {
                if (C) *(float2*)(C + (size_t)r0 * ldc + gc) = make_float2(v0, v1);
                if (Chi) {
                    __nv_bfloat16 h0, l0, h1, l1;
                    bsplit(v0, h0, l0); bsplit(v1, h1, l1);
                    Chi[(size_t)r0 * ldch + gc] = h0; Chi[(size_t)r0 * ldch + gc + 1] = h1;
                    Clo[(size_t)r0 * ldch + gc] = l0; Clo[(size_t)r0 * ldch + gc + 1] = l1;
                }
            }
            if (r1 < M) {
                if (C) *(float2*)(C + (size_t)r1 * ldc + gc) = make_float2(v2, v3);
                if (Chi) {
                    __nv_bfloat16 h2, l2, h3, l3;
                    bsplit(v2, h2, l2); bsplit(v3, h3, l3);
                    Chi[(size_t)r1 * ldch + gc] = h2; Chi[(size_t)r1 * ldch + gc + 1] = h3;
                    Clo[(size_t)r1 * ldch + gc] = l2; Clo[(size_t)r1 * ldch + gc + 1] = l3;
                }
            }
        }
    }
}

// ---------------- GAT: attention scores (float4 loads) ----------------------
__global__ void att_scores(const float* __restrict__ xs, const float* __restrict__ xd,
                           int S,
                           const float* __restrict__ att_s, const float* __restrict__ att_d,
                           float* __restrict__ a_s, float* __restrict__ a_d) {
    int n = blockIdx.x;
    int w = threadIdx.x >> 5;
    int lane = threadIdx.x & 31;
    size_t base = (size_t)n * S + w * HIDD + lane * 4;
    const float4 vs = *(const float4*)(xs + base);
    const float4 vd = *(const float4*)(xd + base);
    const float4 as4 = *(const float4*)(att_s + w * HIDD + lane * 4);
    const float4 ad4 = *(const float4*)(att_d + w * HIDD + lane * 4);
    float s = vs.x * as4.x + vs.y * as4.y + vs.z * as4.z + vs.w * as4.w;
    float d = vd.x * ad4.x + vd.y * ad4.y + vd.z * ad4.z + vd.w * ad4.w;
    #pragma unroll
    for (int o = 16; o > 0; o >>= 1) {
        s += __shfl_down_sync(0xffffffffu, s, o);
        d += __shfl_down_sync(0xffffffffu, d, o);
    }
    if (lane == 0) { a_s[n * NH + w] = s; a_d[n * NH + w] = d; }
}

// ---------------- GAT aggregation (planar alpha, unroll x2) -----------------
__global__ void __launch_bounds__(128)
gat_aggregate(const int* __restrict__ starts, const int* __restrict__ eid,
              const int* __restrict__ src,
              const float* __restrict__ a_s, const float* __restrict__ a_d,
              const float* __restrict__ xs, int S,
              float* __restrict__ alpha, float* __restrict__ gat) {
    int n = blockIdx.x;
    int h = threadIdx.x >> 5;
    int lane = threadIdx.x & 31;
    int beg = starts[n], end = starts[n + 1];

    float adn = a_d[n * NH + h];
    float* alphaH = alpha + (size_t)h * EE;

    float mx = -3.4e38f;
    for (int i = beg + lane; i < end; i += 32) {
        int e = eid[i];
        float a = a_s[src[e] * NH + h] + adn;
        a = a > 0.f ? a : 0.2f * a;
        alphaH[i] = a;
        mx = fmaxf(mx, a);
    }
    #pragma unroll
    for (int o = 16; o > 0; o >>= 1)
        mx = fmaxf(mx, __shfl_xor_sync(0xffffffffu, mx, o));

    float den0 = 0.f, den1 = 0.f;
    float4 acc0 = make_float4(0.f, 0.f, 0.f, 0.f);
    float4 acc1 = make_float4(0.f, 0.f, 0.f, 0.f);
    const int chOff = h * HIDD + lane * 4;
    int i = beg;
    for (; i + 1 < end; i += 2) {
        int e0 = eid[i], e1 = eid[i + 1];
        float w0 = expf(alphaH[i] - mx);
        float w1 = expf(alphaH[i + 1] - mx);
        const float4 v0 = *(const float4*)(xs + (size_t)src[e0] * S + chOff);
        const float4 v1 = *(const float4*)(xs + (size_t)src[e1] * S + chOff);
        den0 += w0; den1 += w1;
        acc0.x += v0.x * w0; acc0.y += v0.y * w0;
        acc0.z += v0.z * w0; acc0.w += v0.w * w0;
        acc1.x += v1.x * w1; acc1.y += v1.y * w1;
        acc1.z += v1.z * w1; acc1.w += v1.w * w1;
    }
    if (i < end) {
        int e0 = eid[i];
        float w0 = expf(alphaH[i] - mx);
        const float4 v0 = *(const float4*)(xs + (size_t)src[e0] * S + chOff);
        den0 += w0;
        acc0.x += v0.x * w0; acc0.y += v0.y * w0;
        acc0.z += v0.z * w0; acc0.w += v0.w * w0;
    }
    float den = den0 + den1;
    float4 acc = make_float4(acc0.x + acc1.x, acc0.y + acc1.y,
                             acc0.z + acc1.z, acc0.w + acc1.w);
    float inv = 1.f / (den + 1e-16f);
    acc.x *= inv; acc.y *= inv; acc.z *= inv; acc.w *= inv;
    *(float4*)(gat + (size_t)n * DMID + chOff) = acc;
}

// ---------------- residual (+bias) + LayerNorm + ReLU -> bf16 hi/lo --------
__global__ void resid_ln_relu(const float* __restrict__ gat, const float* __restrict__ cb,
                              const float* __restrict__ lin, int linS,
                              const float* __restrict__ g, const float* __restrict__ b,
                              __nv_bfloat16* __restrict__ hh, __nv_bfloat16* __restrict__ hl) {
    int row = blockIdx.x;
    int t = threadIdx.x;
    size_t gb = (size_t)row * DMID;
    size_t lb = (size_t)row * linS;
    float v0 = gat[gb + t]       + cb[t]       + lin[lb + t];
    float v1 = gat[gb + 256 + t] + cb[256 + t] + lin[lb + 256 + t];
    float s = v0 + v1;
    float ss = v0 * v0 + v1 * v1;
    #pragma unroll
    for (int o = 16; o > 0; o >>= 1) {
        s  += __shfl_down_sync(0xffffffffu, s, o);
        ss += __shfl_down_sync(0xffffffffu, ss, o);
    }
    __shared__ float shs[8], shss[8];
    __shared__ float mu_sh, inv_sh;
    int w = t >> 5, lane = t & 31;
    if (lane == 0) { shs[w] = s; shss[w] = ss; }
    __syncthreads();
    if (t == 0) {
        float S = 0.f, SS = 0.f;
        #pragma unroll
        for (int i = 0; i < 8; i++) { S += shs[i]; SS += shss[i]; }
        float mu = S * (1.f / DMID);
        float var = SS * (1.f / DMID) - mu * mu;
        mu_sh = mu;
        inv_sh = rsqrtf(var + 1e-5f);
    }
    __syncthreads();
    float mu = mu_sh, inv = inv_sh;
    float o0 = fmaxf((v0 - mu) * inv * g[t]       + b[t],       0.f);
    float o1 = fmaxf((v1 - mu) * inv * g[256 + t] + b[256 + t], 0.f);
    __nv_bfloat16 h0, l0, h1, l1;
    bsplit(o0, h0, l0); bsplit(o1, h1, l1);
    hh[gb + t] = h0;       hl[gb + t] = l0;
    hh[gb + 256 + t] = h1; hl[gb + 256 + t] = l1;
}

__global__ void resid_add(const float* __restrict__ gat, const float* __restrict__ cb,
                          const float* __restrict__ lin, int linS,
                          __nv_bfloat16* __restrict__ hh, __nv_bfloat16* __restrict__ hl) {
    int i = blockIdx.x * blockDim.x + threadIdx.x;
    int stride = gridDim.x * blockDim.x;
    for (; i < NN * DMID; i += stride) {
        int row = i >> 9, col = i & (DMID - 1);
        float v = gat[i] + cb[col] + lin[(size_t)row * linS + col];
        __nv_bfloat16 h, l; bsplit(v, h, l);
        hh[i] = h; hl[i] = l;
    }
}

// ---------------- host -------------------------------------------------------
struct WSpec { int off, K, N, Kp; };

static void gemm128(cudaStream_t st,
                    const __nv_bfloat16* Ah, const __nv_bfloat16* Al, int lda,
                    const __nv_bfloat16* Bh, const __nv_bfloat16* Bl, int ldb,
                    float* C, int ldc, __nv_bfloat16* Chi, __nv_bfloat16* Clo, int ldch,
                    const float* bias, int M, int N, int Kp, int relu) {
    constexpr int SM_BYTES = (2 * 128 * 40 + 2 * 128 * 40) * 2 * 2;
    cudaFuncSetAttribute(bf16_gemm<128>,
                         cudaFuncAttributeMaxDynamicSharedMemorySize, SM_BYTES);
    dim3 grid((N + 127) / 128, (M + 127) / 128);
    bf16_gemm<128><<<grid, 256, SM_BYTES, st>>>(Ah, Al, lda, Bh, Bl, ldb, C, ldc,
        Chi, Clo, ldch, bias, M, N, Kp, relu);
}
static void gemm64(cudaStream_t st,
                   const __nv_bfloat16* Ah, const __nv_bfloat16* Al, int lda,
                   const __nv_bfloat16* Bh, const __nv_bfloat16* Bl, int ldb,
                   float* C, int ldc, __nv_bfloat16* Chi, __nv_bfloat16* Clo, int ldch,
                   const float* bias, int M, int N, int Kp, int relu) {
    constexpr int SM_BYTES = (2 * 64 * 40 + 2 * 128 * 40) * 2 * 2;
    cudaFuncSetAttribute(bf16_gemm<64>,
                         cudaFuncAttributeMaxDynamicSharedMemorySize, SM_BYTES);
    dim3 grid((N + 127) / 128, (M + 63) / 64);
    bf16_gemm<64><<<grid, 256, SM_BYTES, st>>>(Ah, Al, lda, Bh, Bl, ldb, C, ldc,
        Chi, Clo, ldch, bias, M, N, Kp, relu);
}

extern "C" void kernel_launch(void* const* d_in, const int* in_sizes, int n_in,
                              void* d_out, int out_size) {
    const float* x      = (const float*)d_in[0];
    const void*  ei     = d_in[1];
    const float* W_rna  = (const float*)d_in[2];
    const float* b_rna  = (const float*)d_in[3];
    const float* W_prot = (const float*)d_in[4];
    const float* b_prot = (const float*)d_in[5];
    const float* c1_Ws  = (const float*)d_in[6];
    const float* c1_Wd  = (const float*)d_in[7];
    const float* c1_as  = (const float*)d_in[8];
    const float* c1_ad  = (const float*)d_in[9];
    const float* c1_b   = (const float*)d_in[10];
    const float* l1_W   = (const float*)d_in[11];
    const float* l1_b   = (const float*)d_in[12];
    const float* ln_g   = (const float*)d_in[13];
    const float* ln_b   = (const float*)d_in[14];
    const float* c2_Ws  = (const float*)d_in[15];
    const float* c2_Wd  = (const float*)d_in[16];
    const float* c2_as  = (const float*)d_in[17];
    const float* c2_ad  = (const float*)d_in[18];
    const float* c2_b   = (const float*)d_in[19];
    const float* l2_W   = (const float*)d_in[20];
    const float* l2_b   = (const float*)d_in[21];
    const float* agg_W  = (const float*)d_in[22];
    const float* agg_b  = (const float*)d_in[23];
    const float* dr_W   = (const float*)d_in[24];
    const float* dr_b   = (const float*)d_in[25];
    const float* dp_W   = (const float*)d_in[26];
    const float* dp_b   = (const float*)d_in[27];
    const float* rr_W   = (const float*)d_in[28];
    const float* rr_b   = (const float*)d_in[29];
    const float* rp_W   = (const float*)d_in[30];
    const float* rp_b   = (const float*)d_in[31];

    float* out = (float*)d_out;
    float* out_rna  = out;
    float* out_prot = out + (size_t)NN * RNAD;
    float* out_emb  = out + (size_t)NN * (RNAD + PROTD);

    float *big, *gat, *as_, *ad_, *alpha, *bias1, *bias2b, *biasT;
    int *srcI, *dstI, *cnt, *starts, *fill, *eid;
    __nv_bfloat16 *xh, *xl, *xinh, *xinl, *hh, *hl, *embh, *embl, *th, *tl, *wh, *wl;
    cudaGetSymbolAddress((void**)&big,   g_big);
    cudaGetSymbolAddress((void**)&gat,   g_gat);
    cudaGetSymbolAddress((void**)&as_,   g_as);
    cudaGetSymbolAddress((void**)&ad_,   g_ad);
    cudaGetSymbolAddress((void**)&alpha, g_alpha);
    cudaGetSymbolAddress((void**)&srcI,  g_src);
    cudaGetSymbolAddress((void**)&dstI,  g_dst);
    cudaGetSymbolAddress((void**)&cnt,   g_cnt);
    cudaGetSymbolAddress((void**)&starts,g_starts);
    cudaGetSymbolAddress((void**)&fill,  g_fill);
    cudaGetSymbolAddress((void**)&eid,   g_eid);
    cudaGetSymbolAddress((void**)&bias1, g_bias1);
    cudaGetSymbolAddress((void**)&bias2b,g_bias2);
    cudaGetSymbolAddress((void**)&biasT, g_biasT);
    cudaGetSymbolAddress((void**)&xh,    g_xh);
    cudaGetSymbolAddress((void**)&xl,    g_xl);
    cudaGetSymbolAddress((void**)&xinh,  g_xinh);
    cudaGetSymbolAddress((void**)&xinl,  g_xinl);
    cudaGetSymbolAddress((void**)&hh,    g_hh);
    cudaGetSymbolAddress((void**)&hl,    g_hl);
    cudaGetSymbolAddress((void**)&embh,  g_embh);
    cudaGetSymbolAddress((void**)&embl,  g_embl);
    cudaGetSymbolAddress((void**)&th,    g_th);
    cudaGetSymbolAddress((void**)&tl,    g_tl);
    cudaGetSymbolAddress((void**)&wh,    g_wh);
    cudaGetSymbolAddress((void**)&wl,    g_wl);

    const int EB = 256;
    cudaStream_t s0 = 0;

    cudaStream_t s1;
    cudaStreamCreateWithFlags(&s1, cudaStreamNonBlocking);
    cudaEvent_t eFork, eCsr, eJoin;
    cudaEventCreateWithFlags(&eFork, cudaEventDisableTiming);
    cudaEventCreateWithFlags(&eCsr,  cudaEventDisableTiming);
    cudaEventCreateWithFlags(&eJoin, cudaEventDisableTiming);

    // ---- fork: CSR chain on s1, overlapping splits + embeds + block1 GEMM ---
    cudaEventRecord(eFork, s0);
    cudaStreamWaitEvent(s1, eFork, 0);
    detect_fmt<<<1, 32, 0, s1>>>((const unsigned*)ei);
    decode_idx<<<(2 * EE + EB - 1) / EB, EB, 0, s1>>>(ei, srcI, dstI);
    zero_u32<<<40, 256, 0, s1>>>((unsigned*)cnt, NN);
    csr_hist<<<(EE + EB - 1) / EB, EB, 0, s1>>>(dstI, cnt);
    csr_scan<<<1, 1024, 0, s1>>>(cnt, starts, fill);
    csr_fill<<<(EE + EB - 1) / EB, EB, 0, s1>>>(dstI, fill, eid);
    cudaEventRecord(eCsr, s1);

    // ---- preprocessing (main stream) ----------------------------------------
    split_x4<<<(NN * (XPAD / 4) + 255) / 256, 256, 0, s0>>>(x, xh, xl);
    const WSpec ws[13] = {
        {OFF_WRNA,  RNAD, EMBD, KRNA},  {OFF_WPROT, PROTD, EMBD, KPROT},
        {OFF_C1WS,  DIN,  DMID, DIN},   {OFF_C1WD,  DIN,  DMID, DIN},
        {OFF_L1W,   DIN,  DMID, DIN},
        {OFF_C2WS,  DMID, DMID, DMID},  {OFF_C2WD,  DMID, DMID, DMID},
        {OFF_L2W,   DMID, DMID, DMID},
        {OFF_AGG,   DMID, EMBD, DMID},
        {OFF_DR,    EMBD, EMBD, EMBD},  {OFF_DP,    EMBD, EMBD, EMBD},
        {OFF_RR,    EMBD, RNAD, EMBD},  {OFF_RP,    EMBD, PROTD, EMBD},
    };
    const float* wp[13] = {W_rna, W_prot, c1_Ws, c1_Wd, l1_W, c2_Ws, c2_Wd, l2_W,
                           agg_W, dr_W, dp_W, rr_W, rp_W};
    for (int i = 0; i < 13; i++) {
        dim3 tgrid((ws[i].Kp + 31) / 32, (ws[i].N + 31) / 32);
        split_w_t<<<tgrid, dim3(32, 8), 0, s0>>>(wp[i], ws[i].K, ws[i].N, ws[i].Kp,
                                                 wh + ws[i].off, wl + ws[i].off);
    }
    bias_all<<<6, 256, 0, s0>>>(l1_b, l2_b, dr_b, dp_b, bias1, bias2b, biasT);

    // ---- input embeddings: rna (big) on s0, prot (small) overlapped ----------
    gemm64(s0, xh, xl, XPAD, wh + OFF_WRNA, wl + OFF_WRNA, KRNA,
           nullptr, 0, xinh, xinl, DIN, b_rna, NN, EMBD, KRNA, 0);
    gemm64(s0, xh + KRNA, xl + KRNA, XPAD, wh + OFF_WPROT, wl + OFF_WPROT, KPROT,
           nullptr, 0, xinh + EMBD, xinl + EMBD, DIN, b_prot, NN, EMBD, KPROT, 0);

    // ================= Block 1: fused xs|xd|lin ============================
    gemm128(s0, xinh, xinl, DIN, wh + OFF_C1WS, wl + OFF_C1WS, DIN,
            big, BIGW, nullptr, nullptr, 0, bias1, NN, BIGW, DIN, 0);
    att_scores<<<NN, 128, 0, s0>>>(big, big + 512, BIGW, c1_as, c1_ad, as_, ad_);
    cudaStreamWaitEvent(s0, eCsr, 0);   // CSR must be ready before gather
    gat_aggregate<<<NN, 128, 0, s0>>>(starts, eid, srcI, as_, ad_, big, BIGW, alpha, gat);
    resid_ln_relu<<<NN, 256, 0, s0>>>(gat, c1_b, big + 1024, BIGW, ln_g, ln_b, hh, hl);

    // ================= Block 2: fused xs|xd|lin ============================
    gemm128(s0, hh, hl, DMID, wh + OFF_C2WS, wl + OFF_C2WS, DMID,
            big, BIGW, nullptr, nullptr, 0, bias2b, NN, BIGW, DMID, 0);
    att_scores<<<NN, 128, 0, s0>>>(big, big + 512, BIGW, c2_as, c2_ad, as_, ad_);
    gat_aggregate<<<NN, 128, 0, s0>>>(starts, eid, srcI, as_, ad_, big, BIGW, alpha, gat);
    resid_add<<<512, 256, 0, s0>>>(gat, c2_b, big + 1024, BIGW, hh, hl);

    // ================= Heads ===============================================
    gemm64(s0, hh, hl, DMID, wh + OFF_AGG, wl + OFF_AGG, DMID,
           out_emb, EMBD, embh, embl, EMBD, agg_b, NN, EMBD, DMID, 1);

    gemm64(s0, embh, embl, EMBD, wh + OFF_DR, wl + OFF_DR, EMBD,
           nullptr, 0, th, tl, 256, biasT, NN, 256, EMBD, 0);

    // rr (big) on s0; rp (small) overlapped on s1
    cudaEventRecord(eFork, s0);
    cudaStreamWaitEvent(s1, eFork, 0);
    gemm64(s1, th + 128, tl + 128, 256, wh + OFF_RP, wl + OFF_RP, EMBD,
           out_prot, PROTD, nullptr, nullptr, 0, rp_b, NN, PROTD, EMBD, 0);
    cudaEventRecord(eJoin, s1);

    gemm128(s0, th, tl, 256, wh + OFF_RR, wl + OFF_RR, EMBD,
            out_rna, RNAD, nullptr, nullptr, 0, rr_b, NN, RNAD, EMBD, 0);
    cudaStreamWaitEvent(s0, eJoin, 0);

    cudaEventDestroy(eFork);
    cudaEventDestroy(eCsr);
    cudaEventDestroy(eJoin);
    cudaStreamDestroy(s1);
}